// round 1
// baseline (speedup 1.0000x reference)
#include <cuda_runtime.h>
#include <cuda_bf16.h>
#include <math.h>

// ---------------- problem constants ----------------
#define BATCH 8
#define SEQ 2048
#define TOK (BATCH*SEQ)          // 16384
#define DMODEL 512
#define DINNER 1024
#define DSTATE 128
#define NHEADS 16
#define HEADDIM 64
#define CONVDIM 1280             // DINNER + 2*DSTATE
#define DINPROJ 2320             // 2*DINNER + 2*DSTATE + NHEADS
#define FF 2048
#define CHUNK 128
#define NCHUNK (SEQ/CHUNK)       // 16
#define NBLK (BATCH*NCHUNK*NHEADS) // 2048
#define EPSF 1e-5f

// ---------------- scratch (device globals; no runtime alloc) ----------------
__device__ float g_zx[TOK*DINPROJ];       // in_proj output
__device__ float g_xbc[TOK*CONVDIM];      // conv+silu output
__device__ float g_dt[NBLK*CHUNK];        // softplus dt, layout (blk,l)
__device__ float g_acs[NBLK*CHUNK];       // cumsum(dt*A), layout (blk,l)
__device__ float g_states[(size_t)NBLK*DSTATE*HEADDIM]; // (blk,n,p)
__device__ float g_prev[(size_t)NBLK*DSTATE*HEADDIM];   // (blk,n,p) state at chunk start
__device__ float g_y[(size_t)TOK*DINNER];   // ssd out
__device__ float g_gate[(size_t)TOK*DINNER];// gated+rmsnorm
__device__ float g_mo[(size_t)TOK*DMODEL];  // mamba out (after out_proj)
__device__ float g_t[(size_t)TOK*DMODEL];   // after norm1
__device__ float g_f1[(size_t)TOK*FF];      // ffn hidden
__device__ float g_f2[(size_t)TOK*DMODEL];  // ffn out

// ---------------- helpers ----------------
__device__ __forceinline__ void blockReduce2(float& a, float& b, float* sh) {
    int lane = threadIdx.x & 31, w = threadIdx.x >> 5;
    #pragma unroll
    for (int o = 16; o; o >>= 1) {
        a += __shfl_xor_sync(0xffffffffu, a, o);
        b += __shfl_xor_sync(0xffffffffu, b, o);
    }
    if (lane == 0) { sh[w] = a; sh[32 + w] = b; }
    __syncthreads();
    int nw = blockDim.x >> 5;
    if (w == 0) {
        a = (lane < nw) ? sh[lane] : 0.f;
        b = (lane < nw) ? sh[32 + lane] : 0.f;
        #pragma unroll
        for (int o = 16; o; o >>= 1) {
            a += __shfl_xor_sync(0xffffffffu, a, o);
            b += __shfl_xor_sync(0xffffffffu, b, o);
        }
        if (lane == 0) { sh[0] = a; sh[32] = b; }
    }
    __syncthreads();
    a = sh[0]; b = sh[32];
}

// ---------------- GEMM: C[M,N] = A[M,K] @ W[N,K]^T (+bias, +act) ----------------
// 128x128 tile, 256 threads, 8x8 per thread, TK=8. M multiple of 128, K multiple of 8.
template<int ACT>
__global__ void __launch_bounds__(256) k_gemm(const float* __restrict__ A,
                                              const float* __restrict__ W,
                                              const float* __restrict__ bias,
                                              float* __restrict__ C,
                                              int N, int K) {
    __shared__ float As[8][128];
    __shared__ float Ws[8][128];
    int tid = threadIdx.x;
    int bm = blockIdx.y * 128, bn = blockIdx.x * 128;
    int lr = tid >> 1;
    int lc = (tid & 1) * 4;
    int tx = tid & 15, ty = tid >> 4;
    float acc[8][8];
    #pragma unroll
    for (int i = 0; i < 8; i++)
        #pragma unroll
        for (int j = 0; j < 8; j++) acc[i][j] = 0.f;

    const float* Aptr = A + (size_t)(bm + lr) * K + lc;
    int wr = bn + lr;
    const float* Wptr = (wr < N) ? (W + (size_t)wr * K + lc) : nullptr;

    for (int k0 = 0; k0 < K; k0 += 8) {
        float4 av = *(const float4*)(Aptr + k0);
        float4 wv = Wptr ? *(const float4*)(Wptr + k0) : make_float4(0.f, 0.f, 0.f, 0.f);
        __syncthreads();
        As[lc + 0][lr] = av.x; As[lc + 1][lr] = av.y; As[lc + 2][lr] = av.z; As[lc + 3][lr] = av.w;
        Ws[lc + 0][lr] = wv.x; Ws[lc + 1][lr] = wv.y; Ws[lc + 2][lr] = wv.z; Ws[lc + 3][lr] = wv.w;
        __syncthreads();
        #pragma unroll
        for (int k = 0; k < 8; k++) {
            float a[8], bv[8];
            *(float4*)&a[0]  = *(const float4*)&As[k][ty * 8];
            *(float4*)&a[4]  = *(const float4*)&As[k][ty * 8 + 4];
            *(float4*)&bv[0] = *(const float4*)&Ws[k][tx * 8];
            *(float4*)&bv[4] = *(const float4*)&Ws[k][tx * 8 + 4];
            #pragma unroll
            for (int i = 0; i < 8; i++)
                #pragma unroll
                for (int j = 0; j < 8; j++) acc[i][j] += a[i] * bv[j];
        }
    }
    #pragma unroll
    for (int i = 0; i < 8; i++) {
        int m = bm + ty * 8 + i;
        #pragma unroll
        for (int j = 0; j < 8; j++) {
            int n = bn + tx * 8 + j;
            if (n < N) {
                float v = acc[i][j];
                if (bias) v += bias[n];
                if (ACT == 1) v = 0.5f * v * (1.f + erff(v * 0.70710678118654752f));
                C[(size_t)m * N + n] = v;
            }
        }
    }
}

// ---------------- causal depthwise conv1d + silu ----------------
__global__ void k_conv(const float* __restrict__ conv_w, const float* __restrict__ conv_b) {
    int idx = blockIdx.x * 256 + threadIdx.x;   // (b, s, ch) linear, total TOK*CONVDIM
    int ch = idx % CONVDIM;
    int s  = (idx / CONVDIM) % SEQ;
    int b  = idx / (CONVDIM * SEQ);
    float acc = conv_b[ch];
    #pragma unroll
    for (int k = 0; k < 4; k++) {
        int sp = s + k - 3;
        if (sp >= 0)
            acc += g_zx[(size_t)(b * SEQ + sp) * DINPROJ + DINNER + ch] * conv_w[ch * 4 + k];
    }
    acc = acc / (1.f + expf(-acc));   // silu
    g_xbc[idx] = acc;
}

// ---------------- dt softplus + per-chunk cumulative log-decay ----------------
__global__ void k_dtscan(const float* __restrict__ dt_bias, const float* __restrict__ A_log) {
    __shared__ float s[128];
    int blk = blockIdx.x, l = threadIdx.x;
    int h = blk & 15, c = (blk >> 4) & 15, b = blk >> 8;
    int tok = b * SEQ + c * CHUNK + l;
    float raw = g_zx[(size_t)tok * DINPROJ + 2 * DINNER + CONVDIM - DINNER + h]; // see note below
    // offset: z(1024) + xBC(1280) = 2304, dt at 2304+h
    raw = g_zx[(size_t)tok * DINPROJ + 2304 + h] + dt_bias[h];
    float dtv = (raw > 20.f) ? raw : log1pf(expf(raw));
    float A = -expf(A_log[h]);
    g_dt[blk * 128 + l] = dtv;
    s[l] = dtv * A;
    __syncthreads();
    #pragma unroll
    for (int off = 1; off < 128; off <<= 1) {
        float t = (l >= off) ? s[l - off] : 0.f;
        __syncthreads();
        s[l] += t;
        __syncthreads();
    }
    g_acs[blk * 128 + l] = s[l];
}

// ---------------- per-chunk end states: states[n,p] = sum_l B[l,n]*exp(acsL-acs[l])*dt[l]*x[l,p]
__global__ void k_states() {
    extern __shared__ float sh[];
    float* Bs = sh;              // 128*128
    float* xs = Bs + 16384;      // 128*64
    float* ws = xs + 8192;       // 128
    int blk = blockIdx.x, tid = threadIdx.x;
    int h = blk & 15, c = (blk >> 4) & 15, b = blk >> 8;
    int base = b * SEQ + c * CHUNK;
    for (int q = tid; q < 16384; q += 128) {
        int l = q >> 7, n = q & 127;
        Bs[q] = g_xbc[(size_t)(base + l) * CONVDIM + DINNER + n];
    }
    for (int q = tid; q < 8192; q += 128) {
        int l = q >> 6, p = q & 63;
        xs[q] = g_xbc[(size_t)(base + l) * CONVDIM + h * 64 + p];
    }
    float acsL = g_acs[blk * 128 + 127];
    ws[tid] = expf(acsL - g_acs[blk * 128 + tid]) * g_dt[blk * 128 + tid];
    __syncthreads();
    float acc[64];
    #pragma unroll
    for (int p = 0; p < 64; p++) acc[p] = 0.f;
    for (int l = 0; l < 128; l++) {
        float bw = Bs[l * 128 + tid] * ws[l];
        const float* xl = &xs[l * 64];
        #pragma unroll
        for (int p = 0; p < 64; p++) acc[p] += bw * xl[p];
    }
    float* dst = &g_states[(size_t)blk * 8192 + tid * 64];
    #pragma unroll
    for (int p = 0; p < 64; p++) dst[p] = acc[p];
}

// ---------------- sequential chunk scan: prev[c] = state at chunk start ----------------
__global__ void k_scan() {
    int bx = blockIdx.x;              // 128 blocks: (b,h)
    int b = bx >> 4, h = bx & 15;
    int tid = threadIdx.x;            // 256
    for (int e = tid; e < 8192; e += 256) {
        float acc = 0.f;
        #pragma unroll
        for (int c = 0; c < NCHUNK; c++) {
            int blk = ((b * NCHUNK + c) << 4) + h;
            g_prev[(size_t)blk * 8192 + e] = acc;
            float cd = expf(g_acs[blk * 128 + 127]);
            acc = cd * acc + g_states[(size_t)blk * 8192 + e];
        }
    }
}

// ---------------- fused SSD output: Y_diag + Y_off + D*x ----------------
__global__ void k_y(const float* __restrict__ D_head) {
    extern __shared__ float sh[];
    float* CsT  = sh;              // 128*129 (transposed, padded)
    float* Bs   = CsT + 128 * 129; // 128*128
    float* xs   = Bs + 16384;      // 128*64
    float* ps   = xs + 8192;       // 128*64  prev [n][p]
    float* acs_s = ps + 8192;      // 128
    float* dt_s  = acs_s + 128;    // 128
    int blk = blockIdx.x, i = threadIdx.x;
    int h = blk & 15, c = (blk >> 4) & 15, b = blk >> 8;
    int base = b * SEQ + c * CHUNK;

    for (int q = i; q < 16384; q += 128) {
        int l = q >> 7, n = q & 127;
        const float* row = &g_xbc[(size_t)(base + l) * CONVDIM];
        CsT[n * 129 + l] = row[DINNER + DSTATE + n];
        Bs[q]            = row[DINNER + n];
    }
    for (int q = i; q < 8192; q += 128) {
        int l = q >> 6, p = q & 63;
        xs[q] = g_xbc[(size_t)(base + l) * CONVDIM + h * 64 + p];
    }
    {
        const float4* src = (const float4*)&g_prev[(size_t)blk * 8192];
        float4* d = (float4*)ps;
        for (int q = i; q < 2048; q += 128) d[q] = src[q];
    }
    acs_s[i] = g_acs[blk * 128 + i];
    dt_s[i]  = g_dt[blk * 128 + i];
    __syncthreads();

    float y[64];
    #pragma unroll
    for (int p = 0; p < 64; p++) y[p] = 0.f;
    float ai = acs_s[i];

    for (int j = 0; j <= i; ++j) {
        float d = 0.f;
        const float* Bj = &Bs[j * 128];
        #pragma unroll 8
        for (int n = 0; n < 128; ++n) d += CsT[n * 129 + i] * Bj[n];
        float g = expf(ai - acs_s[j]) * dt_s[j] * d;
        const float* xj = &xs[j * 64];
        #pragma unroll
        for (int p = 0; p < 64; p++) y[p] += g * xj[p];
    }
    float e = expf(ai);
    for (int n = 0; n < 128; ++n) {
        float cv = e * CsT[n * 129 + i];
        const float* pn = &ps[n * 64];
        #pragma unroll
        for (int p = 0; p < 64; p++) y[p] += cv * pn[p];
    }
    float dh = D_head[h];
    const float* xi = &xs[i * 64];
    #pragma unroll
    for (int p = 0; p < 64; p++) y[p] += dh * xi[p];

    float* dst = &g_y[(size_t)(base + i) * DINNER + h * 64];
    #pragma unroll
    for (int p = 0; p < 64; p += 4) {
        float4 v = make_float4(y[p], y[p + 1], y[p + 2], y[p + 3]);
        *(float4*)&dst[p] = v;
    }
}

// ---------------- gate with silu(z) + RMSNorm * norm_w ----------------
__global__ void k_gate(const float* __restrict__ norm_w) {
    __shared__ float red[64];
    int t = blockIdx.x, tid = threadIdx.x;   // 256 threads, 4 elems each
    float v[4]; float ss = 0.f, dummy = 0.f;
    #pragma unroll
    for (int k = 0; k < 4; k++) {
        int d = tid + k * 256;
        float yv = g_y[(size_t)t * DINNER + d];
        float zv = g_zx[(size_t)t * DINPROJ + d];
        float sv = yv * (zv / (1.f + expf(-zv)));
        v[k] = sv; ss += sv * sv;
    }
    blockReduce2(ss, dummy, red);
    float sc = rsqrtf(ss * (1.f / 1024.f) + EPSF);
    #pragma unroll
    for (int k = 0; k < 4; k++) {
        int d = tid + k * 256;
        g_gate[(size_t)t * DINNER + d] = v[k] * sc * norm_w[d];
    }
}

// ---------------- out = LayerNorm(a + b) * w + beta (D=512) ----------------
__global__ void k_addln(const float* __restrict__ a, const float* __restrict__ bsrc,
                        const float* __restrict__ w, const float* __restrict__ beta,
                        float* __restrict__ o) {
    __shared__ float red[64];
    int t = blockIdx.x, tid = threadIdx.x;   // 128 threads, 4 elems each
    float v[4]; float s = 0.f, ssq = 0.f;
    #pragma unroll
    for (int k = 0; k < 4; k++) {
        int d = tid + k * 128;
        float x = a[(size_t)t * DMODEL + d] + bsrc[(size_t)t * DMODEL + d];
        v[k] = x; s += x; ssq += x * x;
    }
    blockReduce2(s, ssq, red);
    float mean = s * (1.f / 512.f);
    float var = ssq * (1.f / 512.f) - mean * mean;
    float inv = rsqrtf(var + EPSF);
    #pragma unroll
    for (int k = 0; k < 4; k++) {
        int d = tid + k * 128;
        o[(size_t)t * DMODEL + d] = (v[k] - mean) * inv * w[d] + beta[d];
    }
}

// ---------------- launch ----------------
extern "C" void kernel_launch(void* const* d_in, const int* in_sizes, int n_in,
                              void* d_out, int out_size) {
    const float* tgt        = (const float*)d_in[0];
    const float* in_proj_w  = (const float*)d_in[5];
    const float* conv_w     = (const float*)d_in[6];
    const float* conv_b     = (const float*)d_in[7];
    const float* dt_bias    = (const float*)d_in[8];
    const float* A_log      = (const float*)d_in[9];
    const float* D_head     = (const float*)d_in[10];
    const float* norm_w     = (const float*)d_in[11];
    const float* out_proj_w = (const float*)d_in[12];
    const float* n1w = (const float*)d_in[13];
    const float* n1b = (const float*)d_in[14];
    const float* w1  = (const float*)d_in[15];
    const float* b1  = (const float*)d_in[16];
    const float* w2  = (const float*)d_in[17];
    const float* b2  = (const float*)d_in[18];
    const float* n3w = (const float*)d_in[19];
    const float* n3b = (const float*)d_in[20];
    float* out = (float*)d_out;

    float *zx, *gate, *mo, *tb, *f1, *f2;
    cudaGetSymbolAddress((void**)&zx,   g_zx);
    cudaGetSymbolAddress((void**)&gate, g_gate);
    cudaGetSymbolAddress((void**)&mo,   g_mo);
    cudaGetSymbolAddress((void**)&tb,   g_t);
    cudaGetSymbolAddress((void**)&f1,   g_f1);
    cudaGetSymbolAddress((void**)&f2,   g_f2);

    const int smem_states = (16384 + 8192 + 128) * 4;                 // 98816
    const int smem_y = (128 * 129 + 16384 + 8192 + 8192 + 256) * 4;   // 198144
    cudaFuncSetAttribute(k_states, cudaFuncAttributeMaxDynamicSharedMemorySize, smem_states);
    cudaFuncSetAttribute(k_y,      cudaFuncAttributeMaxDynamicSharedMemorySize, smem_y);

    // 1. in_proj: zx = tgt @ in_proj_w^T  (16384x512 @ 512x2320)
    k_gemm<0><<<dim3((DINPROJ + 127) / 128, TOK / 128), 256>>>(tgt, in_proj_w, nullptr, zx, DINPROJ, DMODEL);
    // 2. conv + silu
    k_conv<<<(TOK * CONVDIM) / 256, 256>>>(conv_w, conv_b);
    // 3. dt softplus + cumsum
    k_dtscan<<<NBLK, 128>>>(dt_bias, A_log);
    // 4. chunk end-states
    k_states<<<NBLK, 128, smem_states>>>();
    // 5. chunk scan -> prev
    k_scan<<<BATCH * NHEADS, 256>>>();
    // 6. fused SSD output
    k_y<<<NBLK, 128, smem_y>>>(D_head);
    // 7. gate + rmsnorm
    k_gate<<<TOK, 256>>>(norm_w);
    // 8. out_proj: mo = gate @ out_proj_w^T  (K=1024, N=512)
    k_gemm<0><<<dim3(DMODEL / 128, TOK / 128), 256>>>(gate, out_proj_w, nullptr, mo, DMODEL, DINNER);
    // 9. t = LN(tgt + mo)
    k_addln<<<TOK, 128>>>(tgt, mo, n1w, n1b, tb);
    // 10. f1 = gelu(t @ w1^T + b1)  (K=512, N=2048)
    k_gemm<1><<<dim3(FF / 128, TOK / 128), 256>>>(tb, w1, b1, f1, FF, DMODEL);
    // 11. f2 = f1 @ w2^T + b2  (K=2048, N=512)
    k_gemm<0><<<dim3(DMODEL / 128, TOK / 128), 256>>>(f1, w2, b2, f2, DMODEL, FF);
    // 12. out = LN(t + f2)
    k_addln<<<TOK, 128>>>(tb, f2, n3w, n3b, out);
}

// round 3
// speedup vs baseline: 1.2357x; 1.2357x over previous
#include <cuda_runtime.h>
#include <cuda_bf16.h>
#include <math.h>

// ---------------- problem constants ----------------
#define BATCH 8
#define SEQ 2048
#define TOK (BATCH*SEQ)          // 16384
#define DMODEL 512
#define DINNER 1024
#define DSTATE 128
#define NHEADS 16
#define HEADDIM 64
#define CONVDIM 1280             // DINNER + 2*DSTATE
#define DINPROJ 2320             // 2*DINNER + 2*DSTATE + NHEADS
#define FF 2048
#define CHUNK 128
#define NCHUNK (SEQ/CHUNK)       // 16
#define NBLK (BATCH*NCHUNK*NHEADS) // 2048
#define EPSF 1e-5f

typedef unsigned long long ull;

// ---------------- packed f32x2 helpers ----------------
__device__ __forceinline__ ull pk(float x) {
    ull r; asm("mov.b64 %0,{%1,%2};" : "=l"(r) : "f"(x), "f"(x)); return r;
}
__device__ __forceinline__ ull ffma2(ull a, ull b, ull c) {
    ull d; asm("fma.rn.f32x2 %0,%1,%2,%3;" : "=l"(d) : "l"(a), "l"(b), "l"(c)); return d;
}
__device__ __forceinline__ float2 upk(ull v) {
    float2 f; asm("mov.b64 {%0,%1},%2;" : "=f"(f.x), "=f"(f.y) : "l"(v)); return f;
}

// ---------------- scratch (device globals; no runtime alloc) ----------------
__device__ __align__(16) float g_zx[TOK*DINPROJ];
__device__ __align__(16) float g_xbc[TOK*CONVDIM];
__device__ __align__(16) float g_dt[NBLK*CHUNK];
__device__ __align__(16) float g_acs[NBLK*CHUNK];
__device__ __align__(16) float g_states[(size_t)NBLK*DSTATE*HEADDIM];
__device__ __align__(16) float g_prev[(size_t)NBLK*DSTATE*HEADDIM];
__device__ __align__(16) float g_y[(size_t)TOK*DINNER];
__device__ __align__(16) float g_gate[(size_t)TOK*DINNER];
__device__ __align__(16) float g_mo[(size_t)TOK*DMODEL];
__device__ __align__(16) float g_t[(size_t)TOK*DMODEL];
__device__ __align__(16) float g_f1[(size_t)TOK*FF];
__device__ __align__(16) float g_f2[(size_t)TOK*DMODEL];

// ---------------- helpers ----------------
__device__ __forceinline__ void blockReduce2(float& a, float& b, float* sh) {
    int lane = threadIdx.x & 31, w = threadIdx.x >> 5;
    #pragma unroll
    for (int o = 16; o; o >>= 1) {
        a += __shfl_xor_sync(0xffffffffu, a, o);
        b += __shfl_xor_sync(0xffffffffu, b, o);
    }
    if (lane == 0) { sh[w] = a; sh[32 + w] = b; }
    __syncthreads();
    int nw = blockDim.x >> 5;
    if (w == 0) {
        a = (lane < nw) ? sh[lane] : 0.f;
        b = (lane < nw) ? sh[32 + lane] : 0.f;
        #pragma unroll
        for (int o = 16; o; o >>= 1) {
            a += __shfl_xor_sync(0xffffffffu, a, o);
            b += __shfl_xor_sync(0xffffffffu, b, o);
        }
        if (lane == 0) { sh[0] = a; sh[32] = b; }
    }
    __syncthreads();
    a = sh[0]; b = sh[32];
}

// ---------------- GEMM: C[M,N] = A[M,K] @ W[N,K]^T (+bias, +act), packed f32x2 ----------------
template<int ACT>
__global__ void __launch_bounds__(256) k_gemm(const float* __restrict__ A,
                                              const float* __restrict__ W,
                                              const float* __restrict__ bias,
                                              float* __restrict__ C,
                                              int N, int K) {
    __shared__ __align__(16) float As[8][128];
    __shared__ __align__(16) float Ws[8][128];
    int tid = threadIdx.x;
    int bm = blockIdx.y * 128, bn = blockIdx.x * 128;
    int lr = tid >> 1;
    int lc = (tid & 1) * 4;
    int tx = tid & 15, ty = tid >> 4;
    ull acc2[8][4];
    #pragma unroll
    for (int i = 0; i < 8; i++)
        #pragma unroll
        for (int j = 0; j < 4; j++) acc2[i][j] = 0ull;

    const float* Aptr = A + (size_t)(bm + lr) * K + lc;
    int wr = bn + lr;
    const float* Wptr = (wr < N) ? (W + (size_t)wr * K + lc) : nullptr;

    float4 av = *(const float4*)(Aptr);
    float4 wv = Wptr ? *(const float4*)(Wptr) : make_float4(0.f, 0.f, 0.f, 0.f);

    for (int k0 = 0; k0 < K; k0 += 8) {
        __syncthreads();
        As[lc + 0][lr] = av.x; As[lc + 1][lr] = av.y; As[lc + 2][lr] = av.z; As[lc + 3][lr] = av.w;
        Ws[lc + 0][lr] = wv.x; Ws[lc + 1][lr] = wv.y; Ws[lc + 2][lr] = wv.z; Ws[lc + 3][lr] = wv.w;
        __syncthreads();
        if (k0 + 8 < K) {
            av = *(const float4*)(Aptr + k0 + 8);
            wv = Wptr ? *(const float4*)(Wptr + k0 + 8) : make_float4(0.f, 0.f, 0.f, 0.f);
        }
        #pragma unroll
        for (int k = 0; k < 8; k++) {
            float4 a0 = *(const float4*)&As[k][ty * 8];
            float4 a1 = *(const float4*)&As[k][ty * 8 + 4];
            ulonglong2 b01 = *(const ulonglong2*)&Ws[k][tx * 8];
            ulonglong2 b23 = *(const ulonglong2*)&Ws[k][tx * 8 + 4];
            ull bb0 = b01.x, bb1 = b01.y, bb2 = b23.x, bb3 = b23.y;
            float aa[8] = {a0.x, a0.y, a0.z, a0.w, a1.x, a1.y, a1.z, a1.w};
            #pragma unroll
            for (int i = 0; i < 8; i++) {
                ull ad = pk(aa[i]);
                acc2[i][0] = ffma2(ad, bb0, acc2[i][0]);
                acc2[i][1] = ffma2(ad, bb1, acc2[i][1]);
                acc2[i][2] = ffma2(ad, bb2, acc2[i][2]);
                acc2[i][3] = ffma2(ad, bb3, acc2[i][3]);
            }
        }
    }
    #pragma unroll
    for (int i = 0; i < 8; i++) {
        int m = bm + ty * 8 + i;
        #pragma unroll
        for (int j = 0; j < 4; j++) {
            float2 v2 = upk(acc2[i][j]);
            int n0 = bn + tx * 8 + 2 * j;
            float vv[2] = {v2.x, v2.y};
            #pragma unroll
            for (int u = 0; u < 2; u++) {
                int n = n0 + u;
                if (n < N) {
                    float v = vv[u];
                    if (bias) v += bias[n];
                    if (ACT == 1) v = 0.5f * v * (1.f + erff(v * 0.70710678118654752f));
                    C[(size_t)m * N + n] = v;
                }
            }
        }
    }
}

// ---------------- causal depthwise conv1d + silu ----------------
__global__ void k_conv(const float* __restrict__ conv_w, const float* __restrict__ conv_b) {
    int idx = blockIdx.x * 256 + threadIdx.x;
    int ch = idx % CONVDIM;
    int s  = (idx / CONVDIM) % SEQ;
    int b  = idx / (CONVDIM * SEQ);
    float acc = conv_b[ch];
    #pragma unroll
    for (int k = 0; k < 4; k++) {
        int sp = s + k - 3;
        if (sp >= 0)
            acc += g_zx[(size_t)(b * SEQ + sp) * DINPROJ + DINNER + ch] * conv_w[ch * 4 + k];
    }
    acc = acc / (1.f + expf(-acc));
    g_xbc[idx] = acc;
}

// ---------------- dt softplus + per-chunk cumulative log-decay ----------------
__global__ void k_dtscan(const float* __restrict__ dt_bias, const float* __restrict__ A_log) {
    __shared__ float s[128];
    int blk = blockIdx.x, l = threadIdx.x;
    int h = blk & 15, c = (blk >> 4) & 15, b = blk >> 8;
    int tok = b * SEQ + c * CHUNK + l;
    float raw = g_zx[(size_t)tok * DINPROJ + 2304 + h] + dt_bias[h];
    float dtv = (raw > 20.f) ? raw : log1pf(expf(raw));
    float A = -expf(A_log[h]);
    g_dt[blk * 128 + l] = dtv;
    s[l] = dtv * A;
    __syncthreads();
    #pragma unroll
    for (int off = 1; off < 128; off <<= 1) {
        float t = (l >= off) ? s[l - off] : 0.f;
        __syncthreads();
        s[l] += t;
        __syncthreads();
    }
    g_acs[blk * 128 + l] = s[l];
}

// ---------------- per-chunk end states (packed) ----------------
__global__ void __launch_bounds__(128) k_states() {
    extern __shared__ __align__(16) float sh[];
    float* Bs = sh;              // 128*128
    float* xs = Bs + 16384;      // 128*64
    float* ws = xs + 8192;       // 128
    int blk = blockIdx.x, tid = threadIdx.x;
    int h = blk & 15, c = (blk >> 4) & 15, b = blk >> 8;
    int base = b * SEQ + c * CHUNK;
    for (int q = tid; q < 16384; q += 128) {
        int l = q >> 7, n = q & 127;
        Bs[q] = g_xbc[(size_t)(base + l) * CONVDIM + DINNER + n];
    }
    for (int q = tid; q < 8192; q += 128) {
        int l = q >> 6, p = q & 63;
        xs[q] = g_xbc[(size_t)(base + l) * CONVDIM + h * 64 + p];
    }
    float acsL = g_acs[blk * 128 + 127];
    ws[tid] = expf(acsL - g_acs[blk * 128 + tid]) * g_dt[blk * 128 + tid];
    __syncthreads();
    ull acc2[32];
    #pragma unroll
    for (int q = 0; q < 32; q++) acc2[q] = 0ull;
    for (int l = 0; l < 128; l++) {
        float bw = Bs[l * 128 + tid] * ws[l];
        ull bwp = pk(bw);
        const ulonglong2* xl = (const ulonglong2*)&xs[l * 64];
        #pragma unroll
        for (int q = 0; q < 16; q++) {
            ulonglong2 v = xl[q];
            acc2[2 * q]     = ffma2(bwp, v.x, acc2[2 * q]);
            acc2[2 * q + 1] = ffma2(bwp, v.y, acc2[2 * q + 1]);
        }
    }
    ulonglong2* dst = (ulonglong2*)&g_states[(size_t)blk * 8192 + tid * 64];
    #pragma unroll
    for (int q = 0; q < 16; q++) {
        ulonglong2 v; v.x = acc2[2 * q]; v.y = acc2[2 * q + 1];
        dst[q] = v;
    }
}

// ---------------- sequential chunk scan ----------------
__global__ void k_scan() {
    int bx = blockIdx.x;              // 128 blocks: (b,h)
    int b = bx >> 4, h = bx & 15;
    int tid = threadIdx.x;            // 256
    for (int e = tid; e < 8192; e += 256) {
        float acc = 0.f;
        #pragma unroll
        for (int c = 0; c < NCHUNK; c++) {
            int blk = ((b * NCHUNK + c) << 4) + h;
            g_prev[(size_t)blk * 8192 + e] = acc;
            float cd = expf(g_acs[blk * 128 + 127]);
            acc = cd * acc + g_states[(size_t)blk * 8192 + e];
        }
    }
}

// ---------------- fused SSD output: Y_diag + Y_off + D*x (packed) ----------------
#define CPAD 132   // row pitch for C tile: 132 floats = 528B, 16B multiple
__global__ void __launch_bounds__(128, 1) k_y(const float* __restrict__ D_head) {
    extern __shared__ __align__(16) float sh[];
    float* Cs   = sh;                 // 128*CPAD
    float* Bs   = Cs + 128 * CPAD;    // 128*128
    float* xs   = Bs + 16384;         // 128*64
    float* ps   = xs + 8192;          // 128*64  prev [n][p]
    float* acs_s = ps + 8192;         // 128
    float* dt_s  = acs_s + 128;       // 128
    int blk = blockIdx.x, i = threadIdx.x;
    int h = blk & 15, c = (blk >> 4) & 15, b = blk >> 8;
    int base = b * SEQ + c * CHUNK;

    for (int q = i; q < 16384; q += 128) {
        int l = q >> 7, n = q & 127;
        const float* row = &g_xbc[(size_t)(base + l) * CONVDIM];
        Cs[l * CPAD + n] = row[DINNER + DSTATE + n];
        Bs[q]            = row[DINNER + n];
    }
    for (int q = i; q < 8192; q += 128) {
        int l = q >> 6, p = q & 63;
        xs[q] = g_xbc[(size_t)(base + l) * CONVDIM + h * 64 + p];
    }
    {
        const float4* src = (const float4*)&g_prev[(size_t)blk * 8192];
        float4* d = (float4*)ps;
        for (int q = i; q < 2048; q += 128) d[q] = src[q];
    }
    acs_s[i] = g_acs[blk * 128 + i];
    dt_s[i]  = g_dt[blk * 128 + i];
    __syncthreads();

    // C row of this thread -> registers (64 packed pairs)
    ull Ci[64];
    {
        const ulonglong2* cp = (const ulonglong2*)&Cs[i * CPAD];
        #pragma unroll
        for (int q = 0; q < 32; q++) { ulonglong2 v = cp[q]; Ci[2 * q] = v.x; Ci[2 * q + 1] = v.y; }
    }
    ull y2[32];
    #pragma unroll
    for (int q = 0; q < 32; q++) y2[q] = 0ull;
    float ai = acs_s[i];

    // Y_diag: causal
    for (int j = 0; j <= i; ++j) {
        const ulonglong2* Bj = (const ulonglong2*)&Bs[j * 128];
        ull da = 0ull, db = 0ull, dc = 0ull, dd = 0ull;
        #pragma unroll
        for (int q = 0; q < 16; q++) {
            ulonglong2 v0 = Bj[2 * q];
            ulonglong2 v1 = Bj[2 * q + 1];
            da = ffma2(Ci[4 * q + 0], v0.x, da);
            db = ffma2(Ci[4 * q + 1], v0.y, db);
            dc = ffma2(Ci[4 * q + 2], v1.x, dc);
            dd = ffma2(Ci[4 * q + 3], v1.y, dd);
        }
        float2 fa = upk(da), fb = upk(db), fc = upk(dc), fd = upk(dd);
        float d = (fa.x + fa.y) + (fb.x + fb.y) + (fc.x + fc.y) + (fd.x + fd.y);
        float g = expf(ai - acs_s[j]) * dt_s[j] * d;
        ull gp = pk(g);
        const ulonglong2* xj = (const ulonglong2*)&xs[j * 64];
        #pragma unroll
        for (int q = 0; q < 16; q++) {
            ulonglong2 v = xj[q];
            y2[2 * q]     = ffma2(gp, v.x, y2[2 * q]);
            y2[2 * q + 1] = ffma2(gp, v.y, y2[2 * q + 1]);
        }
    }

    // Y_off: e^acs[i] * sum_n C[i][n] * prev[n][p]
    float e = expf(ai);
    #pragma unroll 4
    for (int q = 0; q < 64; q++) {
        float2 cf = upk(Ci[q]);
        ull c0 = pk(e * cf.x);
        ull c1 = pk(e * cf.y);
        const ulonglong2* p0 = (const ulonglong2*)&ps[(2 * q) * 64];
        const ulonglong2* p1 = (const ulonglong2*)&ps[(2 * q + 1) * 64];
        #pragma unroll
        for (int r = 0; r < 16; r++) {
            ulonglong2 v0 = p0[r];
            ulonglong2 v1 = p1[r];
            y2[2 * r]     = ffma2(c0, v0.x, y2[2 * r]);
            y2[2 * r + 1] = ffma2(c0, v0.y, y2[2 * r + 1]);
            y2[2 * r]     = ffma2(c1, v1.x, y2[2 * r]);
            y2[2 * r + 1] = ffma2(c1, v1.y, y2[2 * r + 1]);
        }
    }

    // + D*x
    float dh = D_head[h];
    ull dhp = pk(dh);
    const ulonglong2* xi = (const ulonglong2*)&xs[i * 64];
    #pragma unroll
    for (int q = 0; q < 16; q++) {
        ulonglong2 v = xi[q];
        y2[2 * q]     = ffma2(dhp, v.x, y2[2 * q]);
        y2[2 * q + 1] = ffma2(dhp, v.y, y2[2 * q + 1]);
    }

    ulonglong2* dst = (ulonglong2*)&g_y[(size_t)(base + i) * DINNER + h * 64];
    #pragma unroll
    for (int q = 0; q < 16; q++) {
        ulonglong2 v; v.x = y2[2 * q]; v.y = y2[2 * q + 1];
        dst[q] = v;
    }
}

// ---------------- gate with silu(z) + RMSNorm * norm_w ----------------
__global__ void k_gate(const float* __restrict__ norm_w) {
    __shared__ float red[64];
    int t = blockIdx.x, tid = threadIdx.x;
    float v[4]; float ss = 0.f, dummy = 0.f;
    #pragma unroll
    for (int k = 0; k < 4; k++) {
        int d = tid + k * 256;
        float yv = g_y[(size_t)t * DINNER + d];
        float zv = g_zx[(size_t)t * DINPROJ + d];
        float sv = yv * (zv / (1.f + expf(-zv)));
        v[k] = sv; ss += sv * sv;
    }
    blockReduce2(ss, dummy, red);
    float sc = rsqrtf(ss * (1.f / 1024.f) + EPSF);
    #pragma unroll
    for (int k = 0; k < 4; k++) {
        int d = tid + k * 256;
        g_gate[(size_t)t * DINNER + d] = v[k] * sc * norm_w[d];
    }
}

// ---------------- out = LayerNorm(a + b) * w + beta (D=512) ----------------
__global__ void k_addln(const float* __restrict__ a, const float* __restrict__ bsrc,
                        const float* __restrict__ w, const float* __restrict__ beta,
                        float* __restrict__ o) {
    __shared__ float red[64];
    int t = blockIdx.x, tid = threadIdx.x;
    float v[4]; float s = 0.f, ssq = 0.f;
    #pragma unroll
    for (int k = 0; k < 4; k++) {
        int d = tid + k * 128;
        float x = a[(size_t)t * DMODEL + d] + bsrc[(size_t)t * DMODEL + d];
        v[k] = x; s += x; ssq += x * x;
    }
    blockReduce2(s, ssq, red);
    float mean = s * (1.f / 512.f);
    float var = ssq * (1.f / 512.f) - mean * mean;
    float inv = rsqrtf(var + EPSF);
    #pragma unroll
    for (int k = 0; k < 4; k++) {
        int d = tid + k * 128;
        o[(size_t)t * DMODEL + d] = (v[k] - mean) * inv * w[d] + beta[d];
    }
}

// ---------------- launch ----------------
extern "C" void kernel_launch(void* const* d_in, const int* in_sizes, int n_in,
                              void* d_out, int out_size) {
    const float* tgt        = (const float*)d_in[0];
    const float* in_proj_w  = (const float*)d_in[5];
    const float* conv_w     = (const float*)d_in[6];
    const float* conv_b     = (const float*)d_in[7];
    const float* dt_bias    = (const float*)d_in[8];
    const float* A_log      = (const float*)d_in[9];
    const float* D_head     = (const float*)d_in[10];
    const float* norm_w     = (const float*)d_in[11];
    const float* out_proj_w = (const float*)d_in[12];
    const float* n1w = (const float*)d_in[13];
    const float* n1b = (const float*)d_in[14];
    const float* w1  = (const float*)d_in[15];
    const float* b1  = (const float*)d_in[16];
    const float* w2  = (const float*)d_in[17];
    const float* b2  = (const float*)d_in[18];
    const float* n3w = (const float*)d_in[19];
    const float* n3b = (const float*)d_in[20];
    float* out = (float*)d_out;

    float *zx, *gate, *mo, *tb, *f1, *f2;
    cudaGetSymbolAddress((void**)&zx,   g_zx);
    cudaGetSymbolAddress((void**)&gate, g_gate);
    cudaGetSymbolAddress((void**)&mo,   g_mo);
    cudaGetSymbolAddress((void**)&tb,   g_t);
    cudaGetSymbolAddress((void**)&f1,   g_f1);
    cudaGetSymbolAddress((void**)&f2,   g_f2);

    const int smem_states = (16384 + 8192 + 128) * 4;                     // 98816
    const int smem_y = (128 * CPAD + 16384 + 8192 + 8192 + 256) * 4;      // 199680
    cudaFuncSetAttribute(k_states, cudaFuncAttributeMaxDynamicSharedMemorySize, smem_states);
    cudaFuncSetAttribute(k_y,      cudaFuncAttributeMaxDynamicSharedMemorySize, smem_y);

    // 1. in_proj
    k_gemm<0><<<dim3((DINPROJ + 127) / 128, TOK / 128), 256>>>(tgt, in_proj_w, nullptr, zx, DINPROJ, DMODEL);
    // 2. conv + silu
    k_conv<<<(TOK * CONVDIM) / 256, 256>>>(conv_w, conv_b);
    // 3. dt softplus + cumsum
    k_dtscan<<<NBLK, 128>>>(dt_bias, A_log);
    // 4. chunk end-states
    k_states<<<NBLK, 128, smem_states>>>();
    // 5. chunk scan -> prev
    k_scan<<<BATCH * NHEADS, 256>>>();
    // 6. fused SSD output
    k_y<<<NBLK, 128, smem_y>>>(D_head);
    // 7. gate + rmsnorm
    k_gate<<<TOK, 256>>>(norm_w);
    // 8. out_proj
    k_gemm<0><<<dim3(DMODEL / 128, TOK / 128), 256>>>(gate, out_proj_w, nullptr, mo, DMODEL, DINNER);
    // 9. t = LN(tgt + mo)
    k_addln<<<TOK, 128>>>(tgt, mo, n1w, n1b, tb);
    // 10. f1 = gelu(t @ w1^T + b1)
    k_gemm<1><<<dim3(FF / 128, TOK / 128), 256>>>(tb, w1, b1, f1, FF, DMODEL);
    // 11. f2 = f1 @ w2^T + b2
    k_gemm<0><<<dim3(DMODEL / 128, TOK / 128), 256>>>(f1, w2, b2, f2, DMODEL, FF);
    // 12. out = LN(t + f2)
    k_addln<<<TOK, 128>>>(tb, f2, n3w, n3b, out);
}

// round 5
// speedup vs baseline: 1.4184x; 1.1478x over previous
#include <cuda_runtime.h>
#include <cuda_bf16.h>
#include <math.h>
#include <cstdint>

// ---------------- problem constants ----------------
#define BATCH 8
#define SEQ 2048
#define TOK (BATCH*SEQ)          // 16384
#define DMODEL 512
#define DINNER 1024
#define DSTATE 128
#define NHEADS 16
#define HEADDIM 64
#define CONVDIM 1280
#define DINPROJ 2320
#define FF 2048
#define CHUNK 128
#define NCHUNK (SEQ/CHUNK)       // 16
#define NBLK (BATCH*NCHUNK*NHEADS) // 2048
#define EPSF 1e-5f

typedef unsigned long long ull;

// ---------------- packed f32x2 helpers ----------------
__device__ __forceinline__ ull pk(float x) {
    ull r; asm("mov.b64 %0,{%1,%2};" : "=l"(r) : "f"(x), "f"(x)); return r;
}
__device__ __forceinline__ ull ffma2(ull a, ull b, ull c) {
    ull d; asm("fma.rn.f32x2 %0,%1,%2,%3;" : "=l"(d) : "l"(a), "l"(b), "l"(c)); return d;
}
__device__ __forceinline__ float2 upk(ull v) {
    float2 f; asm("mov.b64 {%0,%1},%2;" : "=f"(f.x), "=f"(f.y) : "l"(v)); return f;
}

// ---------------- tf32 helpers ----------------
__device__ __forceinline__ float tf32r(float x) {
    uint32_t r; asm("cvt.rna.tf32.f32 %0,%1;" : "=r"(r) : "f"(x));
    return __uint_as_float(r);
}
__device__ __forceinline__ uint32_t f2b(float x) { return __float_as_uint(x); }

#define MMA_TF32(cc, aa, b0, b1) \
    asm volatile("mma.sync.aligned.m16n8k8.row.col.f32.tf32.tf32.f32 " \
        "{%0,%1,%2,%3},{%4,%5,%6,%7},{%8,%9},{%0,%1,%2,%3};" \
        : "+f"(cc[0]), "+f"(cc[1]), "+f"(cc[2]), "+f"(cc[3]) \
        : "r"(aa[0]), "r"(aa[1]), "r"(aa[2]), "r"(aa[3]), "r"(b0), "r"(b1))

// ---------------- scratch ----------------
__device__ __align__(16) float g_zx[TOK*DINPROJ];
__device__ __align__(16) float g_xbc[TOK*CONVDIM];
__device__ __align__(16) float g_dt[NBLK*CHUNK];
__device__ __align__(16) float g_acs[NBLK*CHUNK];
__device__ __align__(16) float g_states[(size_t)NBLK*DSTATE*HEADDIM];
__device__ __align__(16) float g_prev[(size_t)NBLK*DSTATE*HEADDIM];
__device__ __align__(16) float g_y[(size_t)TOK*DINNER];
__device__ __align__(16) float g_gate[(size_t)TOK*DINNER];
__device__ __align__(16) float g_mo[(size_t)TOK*DMODEL];
__device__ __align__(16) float g_t[(size_t)TOK*DMODEL];
__device__ __align__(16) float g_f1[(size_t)TOK*FF];
__device__ __align__(16) float g_f2[(size_t)TOK*DMODEL];

// ---------------- helpers ----------------
__device__ __forceinline__ void blockReduce2(float& a, float& b, float* sh) {
    int lane = threadIdx.x & 31, w = threadIdx.x >> 5;
    #pragma unroll
    for (int o = 16; o; o >>= 1) {
        a += __shfl_xor_sync(0xffffffffu, a, o);
        b += __shfl_xor_sync(0xffffffffu, b, o);
    }
    if (lane == 0) { sh[w] = a; sh[32 + w] = b; }
    __syncthreads();
    int nw = blockDim.x >> 5;
    if (w == 0) {
        a = (lane < nw) ? sh[lane] : 0.f;
        b = (lane < nw) ? sh[32 + lane] : 0.f;
        #pragma unroll
        for (int o = 16; o; o >>= 1) {
            a += __shfl_xor_sync(0xffffffffu, a, o);
            b += __shfl_xor_sync(0xffffffffu, b, o);
        }
        if (lane == 0) { sh[0] = a; sh[32] = b; }
    }
    __syncthreads();
    a = sh[0]; b = sh[32];
}

// ---------------- tensor-core GEMM (3xTF32): C[M,N] = A[M,K] @ W[N,K]^T ----------------
// 128x128 tile, 256 threads (4x2 warps, each 32m x 64n), BK=16.
template<int ACT>
__global__ void __launch_bounds__(256) k_gemm_tc(const float* __restrict__ A,
                                                 const float* __restrict__ W,
                                                 const float* __restrict__ bias,
                                                 float* __restrict__ C,
                                                 int N, int K) {
    __shared__ __align__(16) float Ah[16][136];
    __shared__ __align__(16) float Al[16][136];
    __shared__ __align__(16) float Wh[16][136];
    __shared__ __align__(16) float Wl[16][136];
    int tid = threadIdx.x;
    int bm = blockIdx.y * 128, bn = blockIdx.x * 128;
    int lr = tid >> 1;
    int lc8 = (tid & 1) * 8;
    int lane = tid & 31, wid = tid >> 5;
    int wm = (wid & 3) * 32;      // warp m offset
    int wn = (wid >> 2) * 64;     // warp n offset
    int g = lane >> 2, t4 = lane & 3;

    float c[2][8][4];
    #pragma unroll
    for (int mi = 0; mi < 2; mi++)
        #pragma unroll
        for (int ni = 0; ni < 8; ni++)
            #pragma unroll
            for (int q = 0; q < 4; q++) c[mi][ni][q] = 0.f;

    const float* Aptr = A + (size_t)(bm + lr) * K + lc8;
    int wr = bn + lr;
    const float* Wptr = (wr < N) ? (W + (size_t)wr * K + lc8) : nullptr;

    float av[8], wv[8];
    *(float4*)&av[0] = *(const float4*)(Aptr);
    *(float4*)&av[4] = *(const float4*)(Aptr + 4);
    if (Wptr) {
        *(float4*)&wv[0] = *(const float4*)(Wptr);
        *(float4*)&wv[4] = *(const float4*)(Wptr + 4);
    } else {
        #pragma unroll
        for (int j = 0; j < 8; j++) wv[j] = 0.f;
    }

    for (int k0 = 0; k0 < K; k0 += 16) {
        __syncthreads();
        #pragma unroll
        for (int j = 0; j < 8; j++) {
            float hf = tf32r(av[j]);
            Ah[lc8 + j][lr] = hf;
            Al[lc8 + j][lr] = tf32r(av[j] - hf);
            float wh = tf32r(wv[j]);
            Wh[lc8 + j][lr] = wh;
            Wl[lc8 + j][lr] = tf32r(wv[j] - wh);
        }
        __syncthreads();
        if (k0 + 16 < K) {
            *(float4*)&av[0] = *(const float4*)(Aptr + k0 + 16);
            *(float4*)&av[4] = *(const float4*)(Aptr + k0 + 20);
            if (Wptr) {
                *(float4*)&wv[0] = *(const float4*)(Wptr + k0 + 16);
                *(float4*)&wv[4] = *(const float4*)(Wptr + k0 + 20);
            }
        }
        #pragma unroll
        for (int kk = 0; kk < 16; kk += 8) {
            uint32_t ah[2][4], al2[2][4];
            #pragma unroll
            for (int mi = 0; mi < 2; mi++) {
                int rm = wm + mi * 16 + g;
                ah[mi][0] = f2b(Ah[kk + t4][rm]);
                ah[mi][1] = f2b(Ah[kk + t4][rm + 8]);
                ah[mi][2] = f2b(Ah[kk + t4 + 4][rm]);
                ah[mi][3] = f2b(Ah[kk + t4 + 4][rm + 8]);
                al2[mi][0] = f2b(Al[kk + t4][rm]);
                al2[mi][1] = f2b(Al[kk + t4][rm + 8]);
                al2[mi][2] = f2b(Al[kk + t4 + 4][rm]);
                al2[mi][3] = f2b(Al[kk + t4 + 4][rm + 8]);
            }
            #pragma unroll
            for (int ni = 0; ni < 8; ni++) {
                int cn = wn + ni * 8 + g;
                uint32_t bh0 = f2b(Wh[kk + t4][cn]);
                uint32_t bh1 = f2b(Wh[kk + t4 + 4][cn]);
                uint32_t bl0 = f2b(Wl[kk + t4][cn]);
                uint32_t bl1 = f2b(Wl[kk + t4 + 4][cn]);
                #pragma unroll
                for (int mi = 0; mi < 2; mi++) {
                    MMA_TF32(c[mi][ni], ah[mi], bh0, bh1);
                    MMA_TF32(c[mi][ni], al2[mi], bh0, bh1);
                    MMA_TF32(c[mi][ni], ah[mi], bl0, bl1);
                }
            }
        }
    }

    // epilogue
    #pragma unroll
    for (int mi = 0; mi < 2; mi++) {
        int r0 = bm + wm + mi * 16 + g;
        #pragma unroll
        for (int ni = 0; ni < 8; ni++) {
            int col = bn + wn + ni * 8 + 2 * t4;
            #pragma unroll
            for (int half = 0; half < 2; half++) {
                int r = r0 + half * 8;
                #pragma unroll
                for (int u = 0; u < 2; u++) {
                    int n = col + u;
                    if (n < N) {
                        float v = c[mi][ni][half * 2 + u];
                        if (bias) v += bias[n];
                        if (ACT == 1) v = 0.5f * v * (1.f + erff(v * 0.70710678118654752f));
                        C[(size_t)r * N + n] = v;
                    }
                }
            }
        }
    }
}

// ---------------- causal depthwise conv1d + silu ----------------
__global__ void k_conv(const float* __restrict__ conv_w, const float* __restrict__ conv_b) {
    int idx = blockIdx.x * 256 + threadIdx.x;
    int ch = idx % CONVDIM;
    int s  = (idx / CONVDIM) % SEQ;
    int b  = idx / (CONVDIM * SEQ);
    float acc = conv_b[ch];
    #pragma unroll
    for (int k = 0; k < 4; k++) {
        int sp = s + k - 3;
        if (sp >= 0)
            acc += g_zx[(size_t)(b * SEQ + sp) * DINPROJ + DINNER + ch] * conv_w[ch * 4 + k];
    }
    acc = acc / (1.f + expf(-acc));
    g_xbc[idx] = acc;
}

// ---------------- dt softplus + per-chunk cumulative log-decay ----------------
__global__ void k_dtscan(const float* __restrict__ dt_bias, const float* __restrict__ A_log) {
    __shared__ float s[128];
    int blk = blockIdx.x, l = threadIdx.x;
    int h = blk & 15, c = (blk >> 4) & 15, b = blk >> 8;
    int tok = b * SEQ + c * CHUNK + l;
    float raw = g_zx[(size_t)tok * DINPROJ + 2304 + h] + dt_bias[h];
    float dtv = (raw > 20.f) ? raw : log1pf(expf(raw));
    float A = -expf(A_log[h]);
    g_dt[blk * 128 + l] = dtv;
    s[l] = dtv * A;
    __syncthreads();
    #pragma unroll
    for (int off = 1; off < 128; off <<= 1) {
        float t = (l >= off) ? s[l - off] : 0.f;
        __syncthreads();
        s[l] += t;
        __syncthreads();
    }
    g_acs[blk * 128 + l] = s[l];
}

// ---------------- per-chunk end states (packed) ----------------
__global__ void __launch_bounds__(128) k_states() {
    extern __shared__ __align__(16) float sh[];
    float* Bs = sh;              // 128*128
    float* xs = Bs + 16384;      // 128*64
    float* ws = xs + 8192;       // 128
    int blk = blockIdx.x, tid = threadIdx.x;
    int h = blk & 15, c = (blk >> 4) & 15, b = blk >> 8;
    int base = b * SEQ + c * CHUNK;
    for (int q = tid; q < 16384; q += 128) {
        int l = q >> 7, n = q & 127;
        Bs[q] = g_xbc[(size_t)(base + l) * CONVDIM + DINNER + n];
    }
    for (int q = tid; q < 8192; q += 128) {
        int l = q >> 6, p = q & 63;
        xs[q] = g_xbc[(size_t)(base + l) * CONVDIM + h * 64 + p];
    }
    float acsL = g_acs[blk * 128 + 127];
    ws[tid] = expf(acsL - g_acs[blk * 128 + tid]) * g_dt[blk * 128 + tid];
    __syncthreads();
    ull acc2[32];
    #pragma unroll
    for (int q = 0; q < 32; q++) acc2[q] = 0ull;
    for (int l = 0; l < 128; l++) {
        float bw = Bs[l * 128 + tid] * ws[l];
        ull bwp = pk(bw);
        const ulonglong2* xl = (const ulonglong2*)&xs[l * 64];
        #pragma unroll
        for (int q = 0; q < 16; q++) {
            ulonglong2 v = xl[q];
            acc2[2 * q]     = ffma2(bwp, v.x, acc2[2 * q]);
            acc2[2 * q + 1] = ffma2(bwp, v.y, acc2[2 * q + 1]);
        }
    }
    ulonglong2* dst = (ulonglong2*)&g_states[(size_t)blk * 8192 + tid * 64];
    #pragma unroll
    for (int q = 0; q < 16; q++) {
        ulonglong2 v; v.x = acc2[2 * q]; v.y = acc2[2 * q + 1];
        dst[q] = v;
    }
}

// ---------------- sequential chunk scan ----------------
__global__ void k_scan() {
    int bx = blockIdx.x;
    int b = bx >> 4, h = bx & 15;
    int tid = threadIdx.x;
    for (int e = tid; e < 8192; e += 256) {
        float acc = 0.f;
        #pragma unroll
        for (int c = 0; c < NCHUNK; c++) {
            int blk = ((b * NCHUNK + c) << 4) + h;
            g_prev[(size_t)blk * 8192 + e] = acc;
            float cd = expf(g_acs[blk * 128 + 127]);
            acc = cd * acc + g_states[(size_t)blk * 8192 + e];
        }
    }
}

// ---------------- fused SSD output: Y_diag + Y_off + D*x (packed) ----------------
#define CPAD 132
__global__ void __launch_bounds__(128, 1) k_y(const float* __restrict__ D_head) {
    extern __shared__ __align__(16) float sh[];
    float* Cs   = sh;                 // 128*CPAD
    float* Bs   = Cs + 128 * CPAD;    // 128*128
    float* xs   = Bs + 16384;         // 128*64
    float* ps   = xs + 8192;          // 128*64
    float* acs_s = ps + 8192;         // 128
    float* dt_s  = acs_s + 128;       // 128
    int blk = blockIdx.x, i = threadIdx.x;
    int h = blk & 15, c = (blk >> 4) & 15, b = blk >> 8;
    int base = b * SEQ + c * CHUNK;

    for (int q = i; q < 16384; q += 128) {
        int l = q >> 7, n = q & 127;
        const float* row = &g_xbc[(size_t)(base + l) * CONVDIM];
        Cs[l * CPAD + n] = row[DINNER + DSTATE + n];
        Bs[q]            = row[DINNER + n];
    }
    for (int q = i; q < 8192; q += 128) {
        int l = q >> 6, p = q & 63;
        xs[q] = g_xbc[(size_t)(base + l) * CONVDIM + h * 64 + p];
    }
    {
        const float4* src = (const float4*)&g_prev[(size_t)blk * 8192];
        float4* d = (float4*)ps;
        for (int q = i; q < 2048; q += 128) d[q] = src[q];
    }
    acs_s[i] = g_acs[blk * 128 + i];
    dt_s[i]  = g_dt[blk * 128 + i];
    __syncthreads();

    ull Ci[64];
    {
        const ulonglong2* cp = (const ulonglong2*)&Cs[i * CPAD];
        #pragma unroll
        for (int q = 0; q < 32; q++) { ulonglong2 v = cp[q]; Ci[2 * q] = v.x; Ci[2 * q + 1] = v.y; }
    }
    ull y2[32];
    #pragma unroll
    for (int q = 0; q < 32; q++) y2[q] = 0ull;
    float ai = acs_s[i];

    for (int j = 0; j <= i; ++j) {
        const ulonglong2* Bj = (const ulonglong2*)&Bs[j * 128];
        ull da = 0ull, db = 0ull, dc = 0ull, dd = 0ull;
        #pragma unroll
        for (int q = 0; q < 16; q++) {
            ulonglong2 v0 = Bj[2 * q];
            ulonglong2 v1 = Bj[2 * q + 1];
            da = ffma2(Ci[4 * q + 0], v0.x, da);
            db = ffma2(Ci[4 * q + 1], v0.y, db);
            dc = ffma2(Ci[4 * q + 2], v1.x, dc);
            dd = ffma2(Ci[4 * q + 3], v1.y, dd);
        }
        float2 fa = upk(da), fb = upk(db), fc = upk(dc), fd = upk(dd);
        float d = (fa.x + fa.y) + (fb.x + fb.y) + (fc.x + fc.y) + (fd.x + fd.y);
        float g = expf(ai - acs_s[j]) * dt_s[j] * d;
        ull gp = pk(g);
        const ulonglong2* xj = (const ulonglong2*)&xs[j * 64];
        #pragma unroll
        for (int q = 0; q < 16; q++) {
            ulonglong2 v = xj[q];
            y2[2 * q]     = ffma2(gp, v.x, y2[2 * q]);
            y2[2 * q + 1] = ffma2(gp, v.y, y2[2 * q + 1]);
        }
    }

    float e = expf(ai);
    #pragma unroll 4
    for (int q = 0; q < 64; q++) {
        float2 cf = upk(Ci[q]);
        ull c0 = pk(e * cf.x);
        ull c1 = pk(e * cf.y);
        const ulonglong2* p0 = (const ulonglong2*)&ps[(2 * q) * 64];
        const ulonglong2* p1 = (const ulonglong2*)&ps[(2 * q + 1) * 64];
        #pragma unroll
        for (int r = 0; r < 16; r++) {
            ulonglong2 v0 = p0[r];
            ulonglong2 v1 = p1[r];
            y2[2 * r]     = ffma2(c0, v0.x, y2[2 * r]);
            y2[2 * r + 1] = ffma2(c0, v0.y, y2[2 * r + 1]);
            y2[2 * r]     = ffma2(c1, v1.x, y2[2 * r]);
            y2[2 * r + 1] = ffma2(c1, v1.y, y2[2 * r + 1]);
        }
    }

    float dh = D_head[h];
    ull dhp = pk(dh);
    const ulonglong2* xi = (const ulonglong2*)&xs[i * 64];
    #pragma unroll
    for (int q = 0; q < 16; q++) {
        ulonglong2 v = xi[q];
        y2[2 * q]     = ffma2(dhp, v.x, y2[2 * q]);
        y2[2 * q + 1] = ffma2(dhp, v.y, y2[2 * q + 1]);
    }

    ulonglong2* dst = (ulonglong2*)&g_y[(size_t)(base + i) * DINNER + h * 64];
    #pragma unroll
    for (int q = 0; q < 16; q++) {
        ulonglong2 v; v.x = y2[2 * q]; v.y = y2[2 * q + 1];
        dst[q] = v;
    }
}

// ---------------- gate with silu(z) + RMSNorm * norm_w ----------------
__global__ void k_gate(const float* __restrict__ norm_w) {
    __shared__ float red[64];
    int t = blockIdx.x, tid = threadIdx.x;
    float v[4]; float ss = 0.f, dummy = 0.f;
    #pragma unroll
    for (int k = 0; k < 4; k++) {
        int d = tid + k * 256;
        float yv = g_y[(size_t)t * DINNER + d];
        float zv = g_zx[(size_t)t * DINPROJ + d];
        float sv = yv * (zv / (1.f + expf(-zv)));
        v[k] = sv; ss += sv * sv;
    }
    blockReduce2(ss, dummy, red);
    float sc = rsqrtf(ss * (1.f / 1024.f) + EPSF);
    #pragma unroll
    for (int k = 0; k < 4; k++) {
        int d = tid + k * 256;
        g_gate[(size_t)t * DINNER + d] = v[k] * sc * norm_w[d];
    }
}

// ---------------- out = LayerNorm(a + b) * w + beta (D=512) ----------------
__global__ void k_addln(const float* __restrict__ a, const float* __restrict__ bsrc,
                        const float* __restrict__ w, const float* __restrict__ beta,
                        float* __restrict__ o) {
    __shared__ float red[64];
    int t = blockIdx.x, tid = threadIdx.x;
    float v[4]; float s = 0.f, ssq = 0.f;
    #pragma unroll
    for (int k = 0; k < 4; k++) {
        int d = tid + k * 128;
        float x = a[(size_t)t * DMODEL + d] + bsrc[(size_t)t * DMODEL + d];
        v[k] = x; s += x; ssq += x * x;
    }
    blockReduce2(s, ssq, red);
    float mean = s * (1.f / 512.f);
    float var = ssq * (1.f / 512.f) - mean * mean;
    float inv = rsqrtf(var + EPSF);
    #pragma unroll
    for (int k = 0; k < 4; k++) {
        int d = tid + k * 128;
        o[(size_t)t * DMODEL + d] = (v[k] - mean) * inv * w[d] + beta[d];
    }
}

// ---------------- launch ----------------
extern "C" void kernel_launch(void* const* d_in, const int* in_sizes, int n_in,
                              void* d_out, int out_size) {
    const float* tgt        = (const float*)d_in[0];
    const float* in_proj_w  = (const float*)d_in[5];
    const float* conv_w     = (const float*)d_in[6];
    const float* conv_b     = (const float*)d_in[7];
    const float* dt_bias    = (const float*)d_in[8];
    const float* A_log      = (const float*)d_in[9];
    const float* D_head     = (const float*)d_in[10];
    const float* norm_w     = (const float*)d_in[11];
    const float* out_proj_w = (const float*)d_in[12];
    const float* n1w = (const float*)d_in[13];
    const float* n1b = (const float*)d_in[14];
    const float* w1  = (const float*)d_in[15];
    const float* b1  = (const float*)d_in[16];
    const float* w2  = (const float*)d_in[17];
    const float* b2  = (const float*)d_in[18];
    const float* n3w = (const float*)d_in[19];
    const float* n3b = (const float*)d_in[20];
    float* out = (float*)d_out;

    float *zx, *gate, *mo, *tb, *f1, *f2;
    cudaGetSymbolAddress((void**)&zx,   g_zx);
    cudaGetSymbolAddress((void**)&gate, g_gate);
    cudaGetSymbolAddress((void**)&mo,   g_mo);
    cudaGetSymbolAddress((void**)&tb,   g_t);
    cudaGetSymbolAddress((void**)&f1,   g_f1);
    cudaGetSymbolAddress((void**)&f2,   g_f2);

    const int smem_states = (16384 + 8192 + 128) * 4;
    const int smem_y = (128 * CPAD + 16384 + 8192 + 8192 + 256) * 4;
    cudaFuncSetAttribute(k_states, cudaFuncAttributeMaxDynamicSharedMemorySize, smem_states);
    cudaFuncSetAttribute(k_y,      cudaFuncAttributeMaxDynamicSharedMemorySize, smem_y);

    // 1. in_proj (tensor core)
    k_gemm_tc<0><<<dim3((DINPROJ + 127) / 128, TOK / 128), 256>>>(tgt, in_proj_w, nullptr, zx, DINPROJ, DMODEL);
    // 2. conv + silu
    k_conv<<<(TOK * CONVDIM) / 256, 256>>>(conv_w, conv_b);
    // 3. dt softplus + cumsum
    k_dtscan<<<NBLK, 128>>>(dt_bias, A_log);
    // 4. chunk end-states
    k_states<<<NBLK, 128, smem_states>>>();
    // 5. chunk scan -> prev
    k_scan<<<BATCH * NHEADS, 256>>>();
    // 6. fused SSD output
    k_y<<<NBLK, 128, smem_y>>>(D_head);
    // 7. gate + rmsnorm
    k_gate<<<TOK, 256>>>(norm_w);
    // 8. out_proj (tensor core)
    k_gemm_tc<0><<<dim3(DMODEL / 128, TOK / 128), 256>>>(gate, out_proj_w, nullptr, mo, DMODEL, DINNER);
    // 9. t = LN(tgt + mo)
    k_addln<<<TOK, 128>>>(tgt, mo, n1w, n1b, tb);
    // 10. f1 = gelu(t @ w1^T + b1) (tensor core)
    k_gemm_tc<1><<<dim3(FF / 128, TOK / 128), 256>>>(tb, w1, b1, f1, FF, DMODEL);
    // 11. f2 = f1 @ w2^T + b2 (tensor core)
    k_gemm_tc<0><<<dim3(DMODEL / 128, TOK / 128), 256>>>(f1, w2, b2, f2, DMODEL, FF);
    // 12. out = LN(t + f2)
    k_addln<<<TOK, 128>>>(tb, f2, n3w, n3b, out);
}

// round 6
// speedup vs baseline: 1.6447x; 1.1595x over previous
#include <cuda_runtime.h>
#include <cuda_bf16.h>
#include <math.h>
#include <cstdint>

// ---------------- problem constants ----------------
#define BATCH 8
#define SEQ 2048
#define TOK (BATCH*SEQ)          // 16384
#define DMODEL 512
#define DINNER 1024
#define DSTATE 128
#define NHEADS 16
#define HEADDIM 64
#define CONVDIM 1280
#define DINPROJ 2320
#define FF 2048
#define CHUNK 128
#define NCHUNK (SEQ/CHUNK)       // 16
#define NBLK (BATCH*NCHUNK*NHEADS) // 2048
#define EPSF 1e-5f

typedef unsigned long long ull;

// ---------------- packed f32x2 helpers ----------------
__device__ __forceinline__ ull pk(float x) {
    ull r; asm("mov.b64 %0,{%1,%2};" : "=l"(r) : "f"(x), "f"(x)); return r;
}
__device__ __forceinline__ ull ffma2(ull a, ull b, ull c) {
    ull d; asm("fma.rn.f32x2 %0,%1,%2,%3;" : "=l"(d) : "l"(a), "l"(b), "l"(c)); return d;
}
__device__ __forceinline__ float2 upk(ull v) {
    float2 f; asm("mov.b64 {%0,%1},%2;" : "=f"(f.x), "=f"(f.y) : "l"(v)); return f;
}

#define MMA_BF16(cc, aa, b0, b1) \
    asm volatile("mma.sync.aligned.m16n8k16.row.col.f32.bf16.bf16.f32 " \
        "{%0,%1,%2,%3},{%4,%5,%6,%7},{%8,%9},{%0,%1,%2,%3};" \
        : "+f"(cc[0]), "+f"(cc[1]), "+f"(cc[2]), "+f"(cc[3]) \
        : "r"(aa[0]), "r"(aa[1]), "r"(aa[2]), "r"(aa[3]), "r"(b0), "r"(b1))

// ---------------- scratch ----------------
__device__ __align__(16) float g_zx[TOK*DINPROJ];
__device__ __align__(16) float g_xbc[TOK*CONVDIM];
__device__ __align__(16) float g_dt[NBLK*CHUNK];
__device__ __align__(16) float g_acs[NBLK*CHUNK];
__device__ __align__(16) float g_states[(size_t)NBLK*DSTATE*HEADDIM];
__device__ __align__(16) float g_prev[(size_t)NBLK*DSTATE*HEADDIM];
__device__ __align__(16) float g_y[(size_t)TOK*DINNER];
__device__ __align__(16) float g_gate[(size_t)TOK*DINNER];
__device__ __align__(16) float g_mo[(size_t)TOK*DMODEL];
__device__ __align__(16) float g_t[(size_t)TOK*DMODEL];
__device__ __align__(16) float g_f1[(size_t)TOK*FF];
__device__ __align__(16) float g_f2[(size_t)TOK*DMODEL];
// bf16x3 expanded operands
__device__ __align__(16) __nv_bfloat16 g_A3[(size_t)TOK*3*FF];   // max 16384*6144
__device__ __align__(16) __nv_bfloat16 g_W3[DINPROJ*3*DMODEL];   // max 2320*1536

// ---------------- helpers ----------------
__device__ __forceinline__ void blockReduce2(float& a, float& b, float* sh) {
    int lane = threadIdx.x & 31, w = threadIdx.x >> 5;
    #pragma unroll
    for (int o = 16; o; o >>= 1) {
        a += __shfl_xor_sync(0xffffffffu, a, o);
        b += __shfl_xor_sync(0xffffffffu, b, o);
    }
    if (lane == 0) { sh[w] = a; sh[32 + w] = b; }
    __syncthreads();
    int nw = blockDim.x >> 5;
    if (w == 0) {
        a = (lane < nw) ? sh[lane] : 0.f;
        b = (lane < nw) ? sh[32 + lane] : 0.f;
        #pragma unroll
        for (int o = 16; o; o >>= 1) {
            a += __shfl_xor_sync(0xffffffffu, a, o);
            b += __shfl_xor_sync(0xffffffffu, b, o);
        }
        if (lane == 0) { sh[0] = a; sh[32] = b; }
    }
    __syncthreads();
    a = sh[0]; b = sh[32];
}

// ---------------- bf16x3 split: src[M,K] fp32 -> dst[M,3K] bf16 ----------------
// thirds: [0,K)=hi, [K,2K): LOQ==1?lo:hi, [2K,3K): LOQ==2?lo:hi
template<int LOQ>
__global__ void k_split(const float* __restrict__ src, __nv_bfloat16* __restrict__ dst, int K) {
    size_t i = (size_t)blockIdx.x * 256 + threadIdx.x;   // indexes float4
    int K4 = K >> 2;
    size_t row = i / K4;
    int c4 = (int)(i % K4);
    float4 v = ((const float4*)src)[i];
    __nv_bfloat162 h0, h1, l0, l1;
    h0.x = __float2bfloat16_rn(v.x); h0.y = __float2bfloat16_rn(v.y);
    h1.x = __float2bfloat16_rn(v.z); h1.y = __float2bfloat16_rn(v.w);
    l0.x = __float2bfloat16_rn(v.x - __bfloat162float(h0.x));
    l0.y = __float2bfloat16_rn(v.y - __bfloat162float(h0.y));
    l1.x = __float2bfloat16_rn(v.z - __bfloat162float(h1.x));
    l1.y = __float2bfloat16_rn(v.w - __bfloat162float(h1.y));
    __nv_bfloat162* d = (__nv_bfloat162*)(dst + row * 3 * K);
    int c2 = c4 * 2;
    int K2 = K >> 1;
    d[c2] = h0; d[c2 + 1] = h1;
    d[K2 + c2]     = (LOQ == 1) ? l0 : h0;
    d[K2 + c2 + 1] = (LOQ == 1) ? l1 : h1;
    d[2 * K2 + c2]     = (LOQ == 2) ? l0 : h0;
    d[2 * K2 + c2 + 1] = (LOQ == 2) ? l1 : h1;
}

// ---------------- bf16 tensor-core GEMM: C[M,N] = A3[M,K3] @ W3[N,K3]^T ----------------
// 128x128 tile, 256 threads (8 warps 4x2, warp tile 32x64), BK=32, double-buffered smem.
#define SPITCH 40
template<int ACT>
__global__ void __launch_bounds__(256) k_gemm_bf16(const __nv_bfloat16* __restrict__ A,
                                                   const __nv_bfloat16* __restrict__ W,
                                                   const float* __restrict__ bias,
                                                   float* __restrict__ C,
                                                   int N, int K3) {
    __shared__ __align__(16) __nv_bfloat16 As[2][128][SPITCH];
    __shared__ __align__(16) __nv_bfloat16 Ws[2][128][SPITCH];
    int tid = threadIdx.x;
    int bm = blockIdx.y * 128, bn = blockIdx.x * 128;
    int lr = tid >> 1, lc = (tid & 1) * 16;
    int lane = tid & 31, wid = tid >> 5;
    int wm = (wid & 3) * 32, wn = (wid >> 2) * 64;
    int g = lane >> 2, t4 = lane & 3;

    float c[2][8][4];
    #pragma unroll
    for (int mi = 0; mi < 2; mi++)
        #pragma unroll
        for (int ni = 0; ni < 8; ni++)
            #pragma unroll
            for (int q = 0; q < 4; q++) c[mi][ni][q] = 0.f;

    const __nv_bfloat16* Aptr = A + (size_t)(bm + lr) * K3 + lc;
    int wr = bn + lr;
    const __nv_bfloat16* Wptr = (wr < N) ? (W + (size_t)wr * K3 + lc) : nullptr;

    uint4 a0, a1, w0, w1;
    a0 = *(const uint4*)(Aptr); a1 = *(const uint4*)(Aptr + 8);
    if (Wptr) { w0 = *(const uint4*)(Wptr); w1 = *(const uint4*)(Wptr + 8); }
    else { w0 = make_uint4(0, 0, 0, 0); w1 = w0; }

    int KT = K3 / 32;
    // prologue: store tile 0
    *(uint4*)&As[0][lr][lc] = a0; *(uint4*)&As[0][lr][lc + 8] = a1;
    *(uint4*)&Ws[0][lr][lc] = w0; *(uint4*)&Ws[0][lr][lc + 8] = w1;
    __syncthreads();

    for (int kt = 0; kt < KT; kt++) {
        int cur = kt & 1;
        bool hasNext = (kt + 1 < KT);
        if (hasNext) {
            const __nv_bfloat16* ap = Aptr + (kt + 1) * 32;
            a0 = *(const uint4*)(ap); a1 = *(const uint4*)(ap + 8);
            if (Wptr) {
                const __nv_bfloat16* wp = Wptr + (kt + 1) * 32;
                w0 = *(const uint4*)(wp); w1 = *(const uint4*)(wp + 8);
            }
        }
        #pragma unroll
        for (int kk = 0; kk < 32; kk += 16) {
            uint32_t af[2][4];
            #pragma unroll
            for (int mi = 0; mi < 2; mi++) {
                int rb = wm + mi * 16;
                af[mi][0] = *(const uint32_t*)&As[cur][rb + g][kk + 2 * t4];
                af[mi][1] = *(const uint32_t*)&As[cur][rb + g + 8][kk + 2 * t4];
                af[mi][2] = *(const uint32_t*)&As[cur][rb + g][kk + 8 + 2 * t4];
                af[mi][3] = *(const uint32_t*)&As[cur][rb + g + 8][kk + 8 + 2 * t4];
            }
            #pragma unroll
            for (int ni = 0; ni < 8; ni++) {
                int rn = wn + ni * 8 + g;
                uint32_t b0 = *(const uint32_t*)&Ws[cur][rn][kk + 2 * t4];
                uint32_t b1 = *(const uint32_t*)&Ws[cur][rn][kk + 8 + 2 * t4];
                MMA_BF16(c[0][ni], af[0], b0, b1);
                MMA_BF16(c[1][ni], af[1], b0, b1);
            }
        }
        if (hasNext) {
            int nxt = cur ^ 1;
            *(uint4*)&As[nxt][lr][lc] = a0; *(uint4*)&As[nxt][lr][lc + 8] = a1;
            *(uint4*)&Ws[nxt][lr][lc] = w0; *(uint4*)&Ws[nxt][lr][lc + 8] = w1;
            __syncthreads();
        }
    }

    // epilogue
    #pragma unroll
    for (int mi = 0; mi < 2; mi++) {
        int r0 = bm + wm + mi * 16 + g;
        #pragma unroll
        for (int ni = 0; ni < 8; ni++) {
            int col = bn + wn + ni * 8 + 2 * t4;
            #pragma unroll
            for (int half = 0; half < 2; half++) {
                int r = r0 + half * 8;
                #pragma unroll
                for (int u = 0; u < 2; u++) {
                    int n = col + u;
                    if (n < N) {
                        float v = c[mi][ni][half * 2 + u];
                        if (bias) v += bias[n];
                        if (ACT == 1) v = 0.5f * v * (1.f + erff(v * 0.70710678118654752f));
                        C[(size_t)r * N + n] = v;
                    }
                }
            }
        }
    }
}

// ---------------- causal depthwise conv1d + silu ----------------
__global__ void k_conv(const float* __restrict__ conv_w, const float* __restrict__ conv_b) {
    int idx = blockIdx.x * 256 + threadIdx.x;
    int ch = idx % CONVDIM;
    int s  = (idx / CONVDIM) % SEQ;
    int b  = idx / (CONVDIM * SEQ);
    float acc = conv_b[ch];
    #pragma unroll
    for (int k = 0; k < 4; k++) {
        int sp = s + k - 3;
        if (sp >= 0)
            acc += g_zx[(size_t)(b * SEQ + sp) * DINPROJ + DINNER + ch] * conv_w[ch * 4 + k];
    }
    acc = acc / (1.f + expf(-acc));
    g_xbc[idx] = acc;
}

// ---------------- dt softplus + per-chunk cumulative log-decay ----------------
__global__ void k_dtscan(const float* __restrict__ dt_bias, const float* __restrict__ A_log) {
    __shared__ float s[128];
    int blk = blockIdx.x, l = threadIdx.x;
    int h = blk & 15, c = (blk >> 4) & 15, b = blk >> 8;
    int tok = b * SEQ + c * CHUNK + l;
    float raw = g_zx[(size_t)tok * DINPROJ + 2304 + h] + dt_bias[h];
    float dtv = (raw > 20.f) ? raw : log1pf(expf(raw));
    float A = -expf(A_log[h]);
    g_dt[blk * 128 + l] = dtv;
    s[l] = dtv * A;
    __syncthreads();
    #pragma unroll
    for (int off = 1; off < 128; off <<= 1) {
        float t = (l >= off) ? s[l - off] : 0.f;
        __syncthreads();
        s[l] += t;
        __syncthreads();
    }
    g_acs[blk * 128 + l] = s[l];
}

// ---------------- per-chunk end states (packed) ----------------
__global__ void __launch_bounds__(128) k_states() {
    extern __shared__ __align__(16) float sh[];
    float* Bs = sh;              // 128*128
    float* xs = Bs + 16384;      // 128*64
    float* ws = xs + 8192;       // 128
    int blk = blockIdx.x, tid = threadIdx.x;
    int h = blk & 15, c = (blk >> 4) & 15, b = blk >> 8;
    int base = b * SEQ + c * CHUNK;
    for (int q = tid; q < 16384; q += 128) {
        int l = q >> 7, n = q & 127;
        Bs[q] = g_xbc[(size_t)(base + l) * CONVDIM + DINNER + n];
    }
    for (int q = tid; q < 8192; q += 128) {
        int l = q >> 6, p = q & 63;
        xs[q] = g_xbc[(size_t)(base + l) * CONVDIM + h * 64 + p];
    }
    float acsL = g_acs[blk * 128 + 127];
    ws[tid] = expf(acsL - g_acs[blk * 128 + tid]) * g_dt[blk * 128 + tid];
    __syncthreads();
    ull acc2[32];
    #pragma unroll
    for (int q = 0; q < 32; q++) acc2[q] = 0ull;
    for (int l = 0; l < 128; l++) {
        float bw = Bs[l * 128 + tid] * ws[l];
        ull bwp = pk(bw);
        const ulonglong2* xl = (const ulonglong2*)&xs[l * 64];
        #pragma unroll
        for (int q = 0; q < 16; q++) {
            ulonglong2 v = xl[q];
            acc2[2 * q]     = ffma2(bwp, v.x, acc2[2 * q]);
            acc2[2 * q + 1] = ffma2(bwp, v.y, acc2[2 * q + 1]);
        }
    }
    ulonglong2* dst = (ulonglong2*)&g_states[(size_t)blk * 8192 + tid * 64];
    #pragma unroll
    for (int q = 0; q < 16; q++) {
        ulonglong2 v; v.x = acc2[2 * q]; v.y = acc2[2 * q + 1];
        dst[q] = v;
    }
}

// ---------------- sequential chunk scan ----------------
__global__ void k_scan() {
    int bx = blockIdx.x;
    int b = bx >> 4, h = bx & 15;
    int tid = threadIdx.x;
    for (int e = tid; e < 8192; e += 256) {
        float acc = 0.f;
        #pragma unroll
        for (int c = 0; c < NCHUNK; c++) {
            int blk = ((b * NCHUNK + c) << 4) + h;
            g_prev[(size_t)blk * 8192 + e] = acc;
            float cd = expf(g_acs[blk * 128 + 127]);
            acc = cd * acc + g_states[(size_t)blk * 8192 + e];
        }
    }
}

// ---------------- fused SSD output: Y_diag + Y_off + D*x (packed) ----------------
#define CPAD 132
__global__ void __launch_bounds__(128, 1) k_y(const float* __restrict__ D_head) {
    extern __shared__ __align__(16) float sh[];
    float* Cs   = sh;                 // 128*CPAD
    float* Bs   = Cs + 128 * CPAD;    // 128*128
    float* xs   = Bs + 16384;         // 128*64
    float* ps   = xs + 8192;          // 128*64
    float* acs_s = ps + 8192;         // 128
    float* dt_s  = acs_s + 128;       // 128
    int blk = blockIdx.x, i = threadIdx.x;
    int h = blk & 15, c = (blk >> 4) & 15, b = blk >> 8;
    int base = b * SEQ + c * CHUNK;

    for (int q = i; q < 16384; q += 128) {
        int l = q >> 7, n = q & 127;
        const float* row = &g_xbc[(size_t)(base + l) * CONVDIM];
        Cs[l * CPAD + n] = row[DINNER + DSTATE + n];
        Bs[q]            = row[DINNER + n];
    }
    for (int q = i; q < 8192; q += 128) {
        int l = q >> 6, p = q & 63;
        xs[q] = g_xbc[(size_t)(base + l) * CONVDIM + h * 64 + p];
    }
    {
        const float4* src = (const float4*)&g_prev[(size_t)blk * 8192];
        float4* d = (float4*)ps;
        for (int q = i; q < 2048; q += 128) d[q] = src[q];
    }
    acs_s[i] = g_acs[blk * 128 + i];
    dt_s[i]  = g_dt[blk * 128 + i];
    __syncthreads();

    ull Ci[64];
    {
        const ulonglong2* cp = (const ulonglong2*)&Cs[i * CPAD];
        #pragma unroll
        for (int q = 0; q < 32; q++) { ulonglong2 v = cp[q]; Ci[2 * q] = v.x; Ci[2 * q + 1] = v.y; }
    }
    ull y2[32];
    #pragma unroll
    for (int q = 0; q < 32; q++) y2[q] = 0ull;
    float ai = acs_s[i];

    for (int j = 0; j <= i; ++j) {
        const ulonglong2* Bj = (const ulonglong2*)&Bs[j * 128];
        ull da = 0ull, db = 0ull, dc = 0ull, dd = 0ull;
        #pragma unroll
        for (int q = 0; q < 16; q++) {
            ulonglong2 v0 = Bj[2 * q];
            ulonglong2 v1 = Bj[2 * q + 1];
            da = ffma2(Ci[4 * q + 0], v0.x, da);
            db = ffma2(Ci[4 * q + 1], v0.y, db);
            dc = ffma2(Ci[4 * q + 2], v1.x, dc);
            dd = ffma2(Ci[4 * q + 3], v1.y, dd);
        }
        float2 fa = upk(da), fb = upk(db), fc = upk(dc), fd = upk(dd);
        float d = (fa.x + fa.y) + (fb.x + fb.y) + (fc.x + fc.y) + (fd.x + fd.y);
        float g = expf(ai - acs_s[j]) * dt_s[j] * d;
        ull gp = pk(g);
        const ulonglong2* xj = (const ulonglong2*)&xs[j * 64];
        #pragma unroll
        for (int q = 0; q < 16; q++) {
            ulonglong2 v = xj[q];
            y2[2 * q]     = ffma2(gp, v.x, y2[2 * q]);
            y2[2 * q + 1] = ffma2(gp, v.y, y2[2 * q + 1]);
        }
    }

    float e = expf(ai);
    #pragma unroll 4
    for (int q = 0; q < 64; q++) {
        float2 cf = upk(Ci[q]);
        ull c0 = pk(e * cf.x);
        ull c1 = pk(e * cf.y);
        const ulonglong2* p0 = (const ulonglong2*)&ps[(2 * q) * 64];
        const ulonglong2* p1 = (const ulonglong2*)&ps[(2 * q + 1) * 64];
        #pragma unroll
        for (int r = 0; r < 16; r++) {
            ulonglong2 v0 = p0[r];
            ulonglong2 v1 = p1[r];
            y2[2 * r]     = ffma2(c0, v0.x, y2[2 * r]);
            y2[2 * r + 1] = ffma2(c0, v0.y, y2[2 * r + 1]);
            y2[2 * r]     = ffma2(c1, v1.x, y2[2 * r]);
            y2[2 * r + 1] = ffma2(c1, v1.y, y2[2 * r + 1]);
        }
    }

    float dh = D_head[h];
    ull dhp = pk(dh);
    const ulonglong2* xi = (const ulonglong2*)&xs[i * 64];
    #pragma unroll
    for (int q = 0; q < 16; q++) {
        ulonglong2 v = xi[q];
        y2[2 * q]     = ffma2(dhp, v.x, y2[2 * q]);
        y2[2 * q + 1] = ffma2(dhp, v.y, y2[2 * q + 1]);
    }

    ulonglong2* dst = (ulonglong2*)&g_y[(size_t)(base + i) * DINNER + h * 64];
    #pragma unroll
    for (int q = 0; q < 16; q++) {
        ulonglong2 v; v.x = y2[2 * q]; v.y = y2[2 * q + 1];
        dst[q] = v;
    }
}

// ---------------- gate with silu(z) + RMSNorm * norm_w ----------------
__global__ void k_gate(const float* __restrict__ norm_w) {
    __shared__ float red[64];
    int t = blockIdx.x, tid = threadIdx.x;
    float v[4]; float ss = 0.f, dummy = 0.f;
    #pragma unroll
    for (int k = 0; k < 4; k++) {
        int d = tid + k * 256;
        float yv = g_y[(size_t)t * DINNER + d];
        float zv = g_zx[(size_t)t * DINPROJ + d];
        float sv = yv * (zv / (1.f + expf(-zv)));
        v[k] = sv; ss += sv * sv;
    }
    blockReduce2(ss, dummy, red);
    float sc = rsqrtf(ss * (1.f / 1024.f) + EPSF);
    #pragma unroll
    for (int k = 0; k < 4; k++) {
        int d = tid + k * 256;
        g_gate[(size_t)t * DINNER + d] = v[k] * sc * norm_w[d];
    }
}

// ---------------- out = LayerNorm(a + b) * w + beta (D=512) ----------------
__global__ void k_addln(const float* __restrict__ a, const float* __restrict__ bsrc,
                        const float* __restrict__ w, const float* __restrict__ beta,
                        float* __restrict__ o) {
    __shared__ float red[64];
    int t = blockIdx.x, tid = threadIdx.x;
    float v[4]; float s = 0.f, ssq = 0.f;
    #pragma unroll
    for (int k = 0; k < 4; k++) {
        int d = tid + k * 128;
        float x = a[(size_t)t * DMODEL + d] + bsrc[(size_t)t * DMODEL + d];
        v[k] = x; s += x; ssq += x * x;
    }
    blockReduce2(s, ssq, red);
    float mean = s * (1.f / 512.f);
    float var = ssq * (1.f / 512.f) - mean * mean;
    float inv = rsqrtf(var + EPSF);
    #pragma unroll
    for (int k = 0; k < 4; k++) {
        int d = tid + k * 128;
        o[(size_t)t * DMODEL + d] = (v[k] - mean) * inv * w[d] + beta[d];
    }
}

// ---------------- launch ----------------
static inline void splitA(const float* src, __nv_bfloat16* dst, int M, int K) {
    k_split<2><<<(int)(((size_t)M * K / 4) / 256), 256>>>(src, dst, K);
}
static inline void splitW(const float* src, __nv_bfloat16* dst, int M, int K) {
    k_split<1><<<(int)(((size_t)M * K / 4) / 256), 256>>>(src, dst, K);
}

extern "C" void kernel_launch(void* const* d_in, const int* in_sizes, int n_in,
                              void* d_out, int out_size) {
    const float* tgt        = (const float*)d_in[0];
    const float* in_proj_w  = (const float*)d_in[5];
    const float* conv_w     = (const float*)d_in[6];
    const float* conv_b     = (const float*)d_in[7];
    const float* dt_bias    = (const float*)d_in[8];
    const float* A_log      = (const float*)d_in[9];
    const float* D_head     = (const float*)d_in[10];
    const float* norm_w     = (const float*)d_in[11];
    const float* out_proj_w = (const float*)d_in[12];
    const float* n1w = (const float*)d_in[13];
    const float* n1b = (const float*)d_in[14];
    const float* w1  = (const float*)d_in[15];
    const float* b1  = (const float*)d_in[16];
    const float* w2  = (const float*)d_in[17];
    const float* b2  = (const float*)d_in[18];
    const float* n3w = (const float*)d_in[19];
    const float* n3b = (const float*)d_in[20];
    float* out = (float*)d_out;

    float *zx, *gate, *mo, *tb, *f1, *f2;
    __nv_bfloat16 *A3, *W3;
    cudaGetSymbolAddress((void**)&zx,   g_zx);
    cudaGetSymbolAddress((void**)&gate, g_gate);
    cudaGetSymbolAddress((void**)&mo,   g_mo);
    cudaGetSymbolAddress((void**)&tb,   g_t);
    cudaGetSymbolAddress((void**)&f1,   g_f1);
    cudaGetSymbolAddress((void**)&f2,   g_f2);
    cudaGetSymbolAddress((void**)&A3,   g_A3);
    cudaGetSymbolAddress((void**)&W3,   g_W3);

    const int smem_states = (16384 + 8192 + 128) * 4;
    const int smem_y = (128 * CPAD + 16384 + 8192 + 8192 + 256) * 4;
    cudaFuncSetAttribute(k_states, cudaFuncAttributeMaxDynamicSharedMemorySize, smem_states);
    cudaFuncSetAttribute(k_y,      cudaFuncAttributeMaxDynamicSharedMemorySize, smem_y);

    // 1. in_proj: zx = tgt @ in_proj_w^T
    splitA(tgt, A3, TOK, DMODEL);
    splitW(in_proj_w, W3, DINPROJ, DMODEL);
    k_gemm_bf16<0><<<dim3((DINPROJ + 127) / 128, TOK / 128), 256>>>(A3, W3, nullptr, zx, DINPROJ, 3 * DMODEL);
    // 2. conv + silu
    k_conv<<<(TOK * CONVDIM) / 256, 256>>>(conv_w, conv_b);
    // 3. dt softplus + cumsum
    k_dtscan<<<NBLK, 128>>>(dt_bias, A_log);
    // 4. chunk end-states
    k_states<<<NBLK, 128, smem_states>>>();
    // 5. chunk scan -> prev
    k_scan<<<BATCH * NHEADS, 256>>>();
    // 6. fused SSD output
    k_y<<<NBLK, 128, smem_y>>>(D_head);
    // 7. gate + rmsnorm
    k_gate<<<TOK, 256>>>(norm_w);
    // 8. out_proj: mo = gate @ out_proj_w^T
    splitA(gate, A3, TOK, DINNER);
    splitW(out_proj_w, W3, DMODEL, DINNER);
    k_gemm_bf16<0><<<dim3(DMODEL / 128, TOK / 128), 256>>>(A3, W3, nullptr, mo, DMODEL, 3 * DINNER);
    // 9. t = LN(tgt + mo)
    k_addln<<<TOK, 128>>>(tgt, mo, n1w, n1b, tb);
    // 10. f1 = gelu(t @ w1^T + b1)
    splitA(tb, A3, TOK, DMODEL);
    splitW(w1, W3, FF, DMODEL);
    k_gemm_bf16<1><<<dim3(FF / 128, TOK / 128), 256>>>(A3, W3, b1, f1, FF, 3 * DMODEL);
    // 11. f2 = f1 @ w2^T + b2
    splitA(f1, A3, TOK, FF);
    splitW(w2, W3, DMODEL, FF);
    k_gemm_bf16<0><<<dim3(DMODEL / 128, TOK / 128), 256>>>(A3, W3, b2, f2, DMODEL, 3 * FF);
    // 12. out = LN(t + f2)
    k_addln<<<TOK, 128>>>(tb, f2, n3w, n3b, out);
}

// round 7
// speedup vs baseline: 1.7811x; 1.0830x over previous
#include <cuda_runtime.h>
#include <cuda_bf16.h>
#include <math.h>
#include <cstdint>

// ---------------- problem constants ----------------
#define BATCH 8
#define SEQ 2048
#define TOK (BATCH*SEQ)          // 16384
#define DMODEL 512
#define DINNER 1024
#define DSTATE 128
#define NHEADS 16
#define HEADDIM 64
#define CONVDIM 1280
#define DINPROJ 2320
#define FF 2048
#define CHUNK 128
#define NCHUNK (SEQ/CHUNK)       // 16
#define NBLK (BATCH*NCHUNK*NHEADS) // 2048
#define EPSF 1e-5f

typedef unsigned long long ull;

// ---------------- packed f32x2 helpers ----------------
__device__ __forceinline__ ull pk(float x) {
    ull r; asm("mov.b64 %0,{%1,%2};" : "=l"(r) : "f"(x), "f"(x)); return r;
}
__device__ __forceinline__ ull ffma2(ull a, ull b, ull c) {
    ull d; asm("fma.rn.f32x2 %0,%1,%2,%3;" : "=l"(d) : "l"(a), "l"(b), "l"(c)); return d;
}
__device__ __forceinline__ float2 upk(ull v) {
    float2 f; asm("mov.b64 {%0,%1},%2;" : "=f"(f.x), "=f"(f.y) : "l"(v)); return f;
}

#define MMA_BF16(cc, aa, b0, b1) \
    asm volatile("mma.sync.aligned.m16n8k16.row.col.f32.bf16.bf16.f32 " \
        "{%0,%1,%2,%3},{%4,%5,%6,%7},{%8,%9},{%0,%1,%2,%3};" \
        : "+f"(cc[0]), "+f"(cc[1]), "+f"(cc[2]), "+f"(cc[3]) \
        : "r"(aa[0]), "r"(aa[1]), "r"(aa[2]), "r"(aa[3]), "r"(b0), "r"(b1))

#define LDSM_X4(r, addr) \
    asm volatile("ldmatrix.sync.aligned.m8n8.x4.shared.b16 {%0,%1,%2,%3},[%4];" \
        : "=r"((r)[0]), "=r"((r)[1]), "=r"((r)[2]), "=r"((r)[3]) : "r"(addr))

// ---------------- scratch ----------------
__device__ __align__(16) float g_zx[TOK*DINPROJ];
__device__ __align__(16) float g_xbc[TOK*CONVDIM];
__device__ __align__(16) float g_dt[NBLK*CHUNK];
__device__ __align__(16) float g_acs[NBLK*CHUNK];
__device__ __align__(16) float g_states[(size_t)NBLK*DSTATE*HEADDIM];
__device__ __align__(16) float g_prev[(size_t)NBLK*DSTATE*HEADDIM];
__device__ __align__(16) float g_y[(size_t)TOK*DINNER];
__device__ __align__(16) float g_gate[(size_t)TOK*DINNER];
__device__ __align__(16) float g_mo[(size_t)TOK*DMODEL];
__device__ __align__(16) float g_t[(size_t)TOK*DMODEL];
__device__ __align__(16) float g_f1[(size_t)TOK*FF];
__device__ __align__(16) float g_f2[(size_t)TOK*DMODEL];
// bf16x3 expanded operands
__device__ __align__(16) __nv_bfloat16 g_A3[(size_t)TOK*3*FF];
__device__ __align__(16) __nv_bfloat16 g_W3[DINPROJ*3*DMODEL];

// ---------------- helpers ----------------
__device__ __forceinline__ void blockReduce2(float& a, float& b, float* sh) {
    int lane = threadIdx.x & 31, w = threadIdx.x >> 5;
    #pragma unroll
    for (int o = 16; o; o >>= 1) {
        a += __shfl_xor_sync(0xffffffffu, a, o);
        b += __shfl_xor_sync(0xffffffffu, b, o);
    }
    if (lane == 0) { sh[w] = a; sh[32 + w] = b; }
    __syncthreads();
    int nw = blockDim.x >> 5;
    if (w == 0) {
        a = (lane < nw) ? sh[lane] : 0.f;
        b = (lane < nw) ? sh[32 + lane] : 0.f;
        #pragma unroll
        for (int o = 16; o; o >>= 1) {
            a += __shfl_xor_sync(0xffffffffu, a, o);
            b += __shfl_xor_sync(0xffffffffu, b, o);
        }
        if (lane == 0) { sh[0] = a; sh[32] = b; }
    }
    __syncthreads();
    a = sh[0]; b = sh[32];
}

// ---------------- bf16x3 split: src[M,K] fp32 -> dst[M,3K] bf16 ----------------
template<int LOQ>
__global__ void k_split(const float* __restrict__ src, __nv_bfloat16* __restrict__ dst, int K) {
    size_t i = (size_t)blockIdx.x * 256 + threadIdx.x;
    int K4 = K >> 2;
    size_t row = i / K4;
    int c4 = (int)(i % K4);
    float4 v = ((const float4*)src)[i];
    __nv_bfloat162 h0, h1, l0, l1;
    h0.x = __float2bfloat16_rn(v.x); h0.y = __float2bfloat16_rn(v.y);
    h1.x = __float2bfloat16_rn(v.z); h1.y = __float2bfloat16_rn(v.w);
    l0.x = __float2bfloat16_rn(v.x - __bfloat162float(h0.x));
    l0.y = __float2bfloat16_rn(v.y - __bfloat162float(h0.y));
    l1.x = __float2bfloat16_rn(v.z - __bfloat162float(h1.x));
    l1.y = __float2bfloat16_rn(v.w - __bfloat162float(h1.y));
    __nv_bfloat162* d = (__nv_bfloat162*)(dst + row * 3 * K);
    int c2 = c4 * 2;
    int K2 = K >> 1;
    d[c2] = h0; d[c2 + 1] = h1;
    d[K2 + c2]     = (LOQ == 1) ? l0 : h0;
    d[K2 + c2 + 1] = (LOQ == 1) ? l1 : h1;
    d[2 * K2 + c2]     = (LOQ == 2) ? l0 : h0;
    d[2 * K2 + c2 + 1] = (LOQ == 2) ? l1 : h1;
}

// ---------------- bf16 tensor-core GEMM with ldmatrix fragments ----------------
// 128x128 tile, 256 threads (8 warps 4x2, warp tile 32x64), BK=32, double-buffered smem.
#define SPITCH 40
template<int ACT>
__global__ void __launch_bounds__(256) k_gemm_bf16(const __nv_bfloat16* __restrict__ A,
                                                   const __nv_bfloat16* __restrict__ W,
                                                   const float* __restrict__ bias,
                                                   float* __restrict__ C,
                                                   int N, int K3) {
    __shared__ __align__(16) __nv_bfloat16 As[2][128][SPITCH];
    __shared__ __align__(16) __nv_bfloat16 Ws[2][128][SPITCH];
    int tid = threadIdx.x;
    int bm = blockIdx.y * 128, bn = blockIdx.x * 128;
    int lr = tid >> 1, lc = (tid & 1) * 16;
    int lane = tid & 31, wid = tid >> 5;
    int wm = (wid & 3) * 32, wn = (wid >> 2) * 64;
    int g = lane >> 2, t4 = lane & 3;

    float c[2][8][4];
    #pragma unroll
    for (int mi = 0; mi < 2; mi++)
        #pragma unroll
        for (int ni = 0; ni < 8; ni++)
            #pragma unroll
            for (int q = 0; q < 4; q++) c[mi][ni][q] = 0.f;

    const __nv_bfloat16* Aptr = A + (size_t)(bm + lr) * K3 + lc;
    int wr = bn + lr;
    const __nv_bfloat16* Wptr = (wr < N) ? (W + (size_t)wr * K3 + lc) : nullptr;

    uint32_t sbA = (uint32_t)__cvta_generic_to_shared(&As[0][0][0]);
    uint32_t sbW = (uint32_t)__cvta_generic_to_shared(&Ws[0][0][0]);
    const uint32_t bufStride = 128 * SPITCH * 2;

    // per-lane ldmatrix address components
    int l7 = lane & 7;
    int aRow = wm + ((lane >> 3) & 1) * 8 + l7;   // + mi*16
    int aCol = (lane >> 4) * 8;                   // + kk
    int bRow = wn + (lane >> 4) * 8 + l7;         // + q*16
    int bCol = ((lane >> 3) & 1) * 8;             // + kk

    uint4 a0, a1, w0, w1;
    a0 = *(const uint4*)(Aptr); a1 = *(const uint4*)(Aptr + 8);
    if (Wptr) { w0 = *(const uint4*)(Wptr); w1 = *(const uint4*)(Wptr + 8); }
    else { w0 = make_uint4(0, 0, 0, 0); w1 = w0; }

    int KT = K3 / 32;
    *(uint4*)&As[0][lr][lc] = a0; *(uint4*)&As[0][lr][lc + 8] = a1;
    *(uint4*)&Ws[0][lr][lc] = w0; *(uint4*)&Ws[0][lr][lc + 8] = w1;
    __syncthreads();

    for (int kt = 0; kt < KT; kt++) {
        int cur = kt & 1;
        bool hasNext = (kt + 1 < KT);
        if (hasNext) {
            const __nv_bfloat16* ap = Aptr + (kt + 1) * 32;
            a0 = *(const uint4*)(ap); a1 = *(const uint4*)(ap + 8);
            if (Wptr) {
                const __nv_bfloat16* wp = Wptr + (kt + 1) * 32;
                w0 = *(const uint4*)(wp); w1 = *(const uint4*)(wp + 8);
            }
        }
        uint32_t aBase = sbA + cur * bufStride;
        uint32_t wBase = sbW + cur * bufStride;
        #pragma unroll
        for (int kk = 0; kk < 32; kk += 16) {
            uint32_t af[2][4], bf[4][4];
            #pragma unroll
            for (int mi = 0; mi < 2; mi++) {
                uint32_t addr = aBase + (uint32_t)(((aRow + mi * 16) * SPITCH + aCol + kk) * 2);
                LDSM_X4(af[mi], addr);
            }
            #pragma unroll
            for (int q = 0; q < 4; q++) {
                uint32_t addr = wBase + (uint32_t)(((bRow + q * 16) * SPITCH + bCol + kk) * 2);
                LDSM_X4(bf[q], addr);
            }
            #pragma unroll
            for (int q = 0; q < 4; q++) {
                MMA_BF16(c[0][2 * q],     af[0], bf[q][0], bf[q][1]);
                MMA_BF16(c[1][2 * q],     af[1], bf[q][0], bf[q][1]);
                MMA_BF16(c[0][2 * q + 1], af[0], bf[q][2], bf[q][3]);
                MMA_BF16(c[1][2 * q + 1], af[1], bf[q][2], bf[q][3]);
            }
        }
        if (hasNext) {
            int nxt = cur ^ 1;
            *(uint4*)&As[nxt][lr][lc] = a0; *(uint4*)&As[nxt][lr][lc + 8] = a1;
            *(uint4*)&Ws[nxt][lr][lc] = w0; *(uint4*)&Ws[nxt][lr][lc + 8] = w1;
            __syncthreads();
        }
    }

    // epilogue
    #pragma unroll
    for (int mi = 0; mi < 2; mi++) {
        int r0 = bm + wm + mi * 16 + g;
        #pragma unroll
        for (int ni = 0; ni < 8; ni++) {
            int col = bn + wn + ni * 8 + 2 * t4;
            #pragma unroll
            for (int half = 0; half < 2; half++) {
                int r = r0 + half * 8;
                #pragma unroll
                for (int u = 0; u < 2; u++) {
                    int n = col + u;
                    if (n < N) {
                        float v = c[mi][ni][half * 2 + u];
                        if (bias) v += bias[n];
                        if (ACT == 1) v = 0.5f * v * (1.f + erff(v * 0.70710678118654752f));
                        C[(size_t)r * N + n] = v;
                    }
                }
            }
        }
    }
}

// ---------------- causal depthwise conv1d + silu ----------------
__global__ void k_conv(const float* __restrict__ conv_w, const float* __restrict__ conv_b) {
    int idx = blockIdx.x * 256 + threadIdx.x;
    int ch = idx % CONVDIM;
    int s  = (idx / CONVDIM) % SEQ;
    int b  = idx / (CONVDIM * SEQ);
    float acc = conv_b[ch];
    #pragma unroll
    for (int k = 0; k < 4; k++) {
        int sp = s + k - 3;
        if (sp >= 0)
            acc += g_zx[(size_t)(b * SEQ + sp) * DINPROJ + DINNER + ch] * conv_w[ch * 4 + k];
    }
    acc = acc / (1.f + expf(-acc));
    g_xbc[idx] = acc;
}

// ---------------- dt softplus + per-chunk cumulative log-decay ----------------
__global__ void k_dtscan(const float* __restrict__ dt_bias, const float* __restrict__ A_log) {
    __shared__ float s[128];
    int blk = blockIdx.x, l = threadIdx.x;
    int h = blk & 15, c = (blk >> 4) & 15, b = blk >> 8;
    int tok = b * SEQ + c * CHUNK + l;
    float raw = g_zx[(size_t)tok * DINPROJ + 2304 + h] + dt_bias[h];
    float dtv = (raw > 20.f) ? raw : log1pf(expf(raw));
    float A = -expf(A_log[h]);
    g_dt[blk * 128 + l] = dtv;
    s[l] = dtv * A;
    __syncthreads();
    #pragma unroll
    for (int off = 1; off < 128; off <<= 1) {
        float t = (l >= off) ? s[l - off] : 0.f;
        __syncthreads();
        s[l] += t;
        __syncthreads();
    }
    g_acs[blk * 128 + l] = s[l];
}

// ---------------- per-chunk end states (packed) ----------------
__global__ void __launch_bounds__(128) k_states() {
    extern __shared__ __align__(16) float sh[];
    float* Bs = sh;              // 128*128
    float* xs = Bs + 16384;      // 128*64
    float* ws = xs + 8192;       // 128
    int blk = blockIdx.x, tid = threadIdx.x;
    int h = blk & 15, c = (blk >> 4) & 15, b = blk >> 8;
    int base = b * SEQ + c * CHUNK;
    for (int q = tid; q < 16384; q += 128) {
        int l = q >> 7, n = q & 127;
        Bs[q] = g_xbc[(size_t)(base + l) * CONVDIM + DINNER + n];
    }
    for (int q = tid; q < 8192; q += 128) {
        int l = q >> 6, p = q & 63;
        xs[q] = g_xbc[(size_t)(base + l) * CONVDIM + h * 64 + p];
    }
    float acsL = g_acs[blk * 128 + 127];
    ws[tid] = expf(acsL - g_acs[blk * 128 + tid]) * g_dt[blk * 128 + tid];
    __syncthreads();
    ull acc2[32];
    #pragma unroll
    for (int q = 0; q < 32; q++) acc2[q] = 0ull;
    for (int l = 0; l < 128; l++) {
        float bw = Bs[l * 128 + tid] * ws[l];
        ull bwp = pk(bw);
        const ulonglong2* xl = (const ulonglong2*)&xs[l * 64];
        #pragma unroll
        for (int q = 0; q < 16; q++) {
            ulonglong2 v = xl[q];
            acc2[2 * q]     = ffma2(bwp, v.x, acc2[2 * q]);
            acc2[2 * q + 1] = ffma2(bwp, v.y, acc2[2 * q + 1]);
        }
    }
    ulonglong2* dst = (ulonglong2*)&g_states[(size_t)blk * 8192 + tid * 64];
    #pragma unroll
    for (int q = 0; q < 16; q++) {
        ulonglong2 v; v.x = acc2[2 * q]; v.y = acc2[2 * q + 1];
        dst[q] = v;
    }
}

// ---------------- sequential chunk scan ----------------
__global__ void k_scan() {
    int bx = blockIdx.x;
    int b = bx >> 4, h = bx & 15;
    int tid = threadIdx.x;
    for (int e = tid; e < 8192; e += 256) {
        float acc = 0.f;
        #pragma unroll
        for (int c = 0; c < NCHUNK; c++) {
            int blk = ((b * NCHUNK + c) << 4) + h;
            g_prev[(size_t)blk * 8192 + e] = acc;
            float cd = expf(g_acs[blk * 128 + 127]);
            acc = cd * acc + g_states[(size_t)blk * 8192 + e];
        }
    }
}

// ---------------- fused SSD output: Y_diag + Y_off + D*x (packed) ----------------
#define CPAD 132
__global__ void __launch_bounds__(128, 1) k_y(const float* __restrict__ D_head) {
    extern __shared__ __align__(16) float sh[];
    float* Cs   = sh;                 // 128*CPAD
    float* Bs   = Cs + 128 * CPAD;    // 128*128
    float* xs   = Bs + 16384;         // 128*64
    float* ps   = xs + 8192;          // 128*64
    float* acs_s = ps + 8192;         // 128
    float* dt_s  = acs_s + 128;       // 128
    int blk = blockIdx.x, i = threadIdx.x;
    int h = blk & 15, c = (blk >> 4) & 15, b = blk >> 8;
    int base = b * SEQ + c * CHUNK;

    for (int q = i; q < 16384; q += 128) {
        int l = q >> 7, n = q & 127;
        const float* row = &g_xbc[(size_t)(base + l) * CONVDIM];
        Cs[l * CPAD + n] = row[DINNER + DSTATE + n];
        Bs[q]            = row[DINNER + n];
    }
    for (int q = i; q < 8192; q += 128) {
        int l = q >> 6, p = q & 63;
        xs[q] = g_xbc[(size_t)(base + l) * CONVDIM + h * 64 + p];
    }
    {
        const float4* src = (const float4*)&g_prev[(size_t)blk * 8192];
        float4* d = (float4*)ps;
        for (int q = i; q < 2048; q += 128) d[q] = src[q];
    }
    acs_s[i] = g_acs[blk * 128 + i];
    dt_s[i]  = g_dt[blk * 128 + i];
    __syncthreads();

    ull Ci[64];
    {
        const ulonglong2* cp = (const ulonglong2*)&Cs[i * CPAD];
        #pragma unroll
        for (int q = 0; q < 32; q++) { ulonglong2 v = cp[q]; Ci[2 * q] = v.x; Ci[2 * q + 1] = v.y; }
    }
    ull y2[32];
    #pragma unroll
    for (int q = 0; q < 32; q++) y2[q] = 0ull;
    float ai = acs_s[i];

    for (int j = 0; j <= i; ++j) {
        const ulonglong2* Bj = (const ulonglong2*)&Bs[j * 128];
        ull da = 0ull, db = 0ull, dc = 0ull, dd = 0ull;
        #pragma unroll
        for (int q = 0; q < 16; q++) {
            ulonglong2 v0 = Bj[2 * q];
            ulonglong2 v1 = Bj[2 * q + 1];
            da = ffma2(Ci[4 * q + 0], v0.x, da);
            db = ffma2(Ci[4 * q + 1], v0.y, db);
            dc = ffma2(Ci[4 * q + 2], v1.x, dc);
            dd = ffma2(Ci[4 * q + 3], v1.y, dd);
        }
        float2 fa = upk(da), fb = upk(db), fc = upk(dc), fd = upk(dd);
        float d = (fa.x + fa.y) + (fb.x + fb.y) + (fc.x + fc.y) + (fd.x + fd.y);
        float g = expf(ai - acs_s[j]) * dt_s[j] * d;
        ull gp = pk(g);
        const ulonglong2* xj = (const ulonglong2*)&xs[j * 64];
        #pragma unroll
        for (int q = 0; q < 16; q++) {
            ulonglong2 v = xj[q];
            y2[2 * q]     = ffma2(gp, v.x, y2[2 * q]);
            y2[2 * q + 1] = ffma2(gp, v.y, y2[2 * q + 1]);
        }
    }

    float e = expf(ai);
    #pragma unroll 4
    for (int q = 0; q < 64; q++) {
        float2 cf = upk(Ci[q]);
        ull c0 = pk(e * cf.x);
        ull c1 = pk(e * cf.y);
        const ulonglong2* p0 = (const ulonglong2*)&ps[(2 * q) * 64];
        const ulonglong2* p1 = (const ulonglong2*)&ps[(2 * q + 1) * 64];
        #pragma unroll
        for (int r = 0; r < 16; r++) {
            ulonglong2 v0 = p0[r];
            ulonglong2 v1 = p1[r];
            y2[2 * r]     = ffma2(c0, v0.x, y2[2 * r]);
            y2[2 * r + 1] = ffma2(c0, v0.y, y2[2 * r + 1]);
            y2[2 * r]     = ffma2(c1, v1.x, y2[2 * r]);
            y2[2 * r + 1] = ffma2(c1, v1.y, y2[2 * r + 1]);
        }
    }

    float dh = D_head[h];
    ull dhp = pk(dh);
    const ulonglong2* xi = (const ulonglong2*)&xs[i * 64];
    #pragma unroll
    for (int q = 0; q < 16; q++) {
        ulonglong2 v = xi[q];
        y2[2 * q]     = ffma2(dhp, v.x, y2[2 * q]);
        y2[2 * q + 1] = ffma2(dhp, v.y, y2[2 * q + 1]);
    }

    ulonglong2* dst = (ulonglong2*)&g_y[(size_t)(base + i) * DINNER + h * 64];
    #pragma unroll
    for (int q = 0; q < 16; q++) {
        ulonglong2 v; v.x = y2[2 * q]; v.y = y2[2 * q + 1];
        dst[q] = v;
    }
}

// ---------------- gate with silu(z) + RMSNorm * norm_w ----------------
__global__ void k_gate(const float* __restrict__ norm_w) {
    __shared__ float red[64];
    int t = blockIdx.x, tid = threadIdx.x;
    float v[4]; float ss = 0.f, dummy = 0.f;
    #pragma unroll
    for (int k = 0; k < 4; k++) {
        int d = tid + k * 256;
        float yv = g_y[(size_t)t * DINNER + d];
        float zv = g_zx[(size_t)t * DINPROJ + d];
        float sv = yv * (zv / (1.f + expf(-zv)));
        v[k] = sv; ss += sv * sv;
    }
    blockReduce2(ss, dummy, red);
    float sc = rsqrtf(ss * (1.f / 1024.f) + EPSF);
    #pragma unroll
    for (int k = 0; k < 4; k++) {
        int d = tid + k * 256;
        g_gate[(size_t)t * DINNER + d] = v[k] * sc * norm_w[d];
    }
}

// ---------------- out = LayerNorm(a + b) * w + beta (D=512) ----------------
__global__ void k_addln(const float* __restrict__ a, const float* __restrict__ bsrc,
                        const float* __restrict__ w, const float* __restrict__ beta,
                        float* __restrict__ o) {
    __shared__ float red[64];
    int t = blockIdx.x, tid = threadIdx.x;
    float v[4]; float s = 0.f, ssq = 0.f;
    #pragma unroll
    for (int k = 0; k < 4; k++) {
        int d = tid + k * 128;
        float x = a[(size_t)t * DMODEL + d] + bsrc[(size_t)t * DMODEL + d];
        v[k] = x; s += x; ssq += x * x;
    }
    blockReduce2(s, ssq, red);
    float mean = s * (1.f / 512.f);
    float var = ssq * (1.f / 512.f) - mean * mean;
    float inv = rsqrtf(var + EPSF);
    #pragma unroll
    for (int k = 0; k < 4; k++) {
        int d = tid + k * 128;
        o[(size_t)t * DMODEL + d] = (v[k] - mean) * inv * w[d] + beta[d];
    }
}

// ---------------- launch ----------------
static inline void splitA(const float* src, __nv_bfloat16* dst, int M, int K) {
    k_split<2><<<(int)(((size_t)M * K / 4) / 256), 256>>>(src, dst, K);
}
static inline void splitW(const float* src, __nv_bfloat16* dst, int M, int K) {
    k_split<1><<<(int)(((size_t)M * K / 4) / 256), 256>>>(src, dst, K);
}

extern "C" void kernel_launch(void* const* d_in, const int* in_sizes, int n_in,
                              void* d_out, int out_size) {
    const float* tgt        = (const float*)d_in[0];
    const float* in_proj_w  = (const float*)d_in[5];
    const float* conv_w     = (const float*)d_in[6];
    const float* conv_b     = (const float*)d_in[7];
    const float* dt_bias    = (const float*)d_in[8];
    const float* A_log      = (const float*)d_in[9];
    const float* D_head     = (const float*)d_in[10];
    const float* norm_w     = (const float*)d_in[11];
    const float* out_proj_w = (const float*)d_in[12];
    const float* n1w = (const float*)d_in[13];
    const float* n1b = (const float*)d_in[14];
    const float* w1  = (const float*)d_in[15];
    const float* b1  = (const float*)d_in[16];
    const float* w2  = (const float*)d_in[17];
    const float* b2  = (const float*)d_in[18];
    const float* n3w = (const float*)d_in[19];
    const float* n3b = (const float*)d_in[20];
    float* out = (float*)d_out;

    float *zx, *gate, *mo, *tb, *f1, *f2;
    __nv_bfloat16 *A3, *W3;
    cudaGetSymbolAddress((void**)&zx,   g_zx);
    cudaGetSymbolAddress((void**)&gate, g_gate);
    cudaGetSymbolAddress((void**)&mo,   g_mo);
    cudaGetSymbolAddress((void**)&tb,   g_t);
    cudaGetSymbolAddress((void**)&f1,   g_f1);
    cudaGetSymbolAddress((void**)&f2,   g_f2);
    cudaGetSymbolAddress((void**)&A3,   g_A3);
    cudaGetSymbolAddress((void**)&W3,   g_W3);

    const int smem_states = (16384 + 8192 + 128) * 4;
    const int smem_y = (128 * CPAD + 16384 + 8192 + 8192 + 256) * 4;
    cudaFuncSetAttribute(k_states, cudaFuncAttributeMaxDynamicSharedMemorySize, smem_states);
    cudaFuncSetAttribute(k_y,      cudaFuncAttributeMaxDynamicSharedMemorySize, smem_y);

    // 1. in_proj: zx = tgt @ in_proj_w^T
    splitA(tgt, A3, TOK, DMODEL);
    splitW(in_proj_w, W3, DINPROJ, DMODEL);
    k_gemm_bf16<0><<<dim3((DINPROJ + 127) / 128, TOK / 128), 256>>>(A3, W3, nullptr, zx, DINPROJ, 3 * DMODEL);
    // 2. conv + silu
    k_conv<<<(TOK * CONVDIM) / 256, 256>>>(conv_w, conv_b);
    // 3. dt softplus + cumsum
    k_dtscan<<<NBLK, 128>>>(dt_bias, A_log);
    // 4. chunk end-states
    k_states<<<NBLK, 128, smem_states>>>();
    // 5. chunk scan -> prev
    k_scan<<<BATCH * NHEADS, 256>>>();
    // 6. fused SSD output
    k_y<<<NBLK, 128, smem_y>>>(D_head);
    // 7. gate + rmsnorm
    k_gate<<<TOK, 256>>>(norm_w);
    // 8. out_proj: mo = gate @ out_proj_w^T
    splitA(gate, A3, TOK, DINNER);
    splitW(out_proj_w, W3, DMODEL, DINNER);
    k_gemm_bf16<0><<<dim3(DMODEL / 128, TOK / 128), 256>>>(A3, W3, nullptr, mo, DMODEL, 3 * DINNER);
    // 9. t = LN(tgt + mo)
    k_addln<<<TOK, 128>>>(tgt, mo, n1w, n1b, tb);
    // 10. f1 = gelu(t @ w1^T + b1)
    splitA(tb, A3, TOK, DMODEL);
    splitW(w1, W3, FF, DMODEL);
    k_gemm_bf16<1><<<dim3(FF / 128, TOK / 128), 256>>>(A3, W3, b1, f1, FF, 3 * DMODEL);
    // 11. f2 = f1 @ w2^T + b2
    splitA(f1, A3, TOK, FF);
    splitW(w2, W3, DMODEL, FF);
    k_gemm_bf16<0><<<dim3(DMODEL / 128, TOK / 128), 256>>>(A3, W3, b2, f2, DMODEL, 3 * FF);
    // 12. out = LN(t + f2)
    k_addln<<<TOK, 128>>>(tb, f2, n3w, n3b, out);
}

// round 9
// speedup vs baseline: 2.0017x; 1.1238x over previous
#include <cuda_runtime.h>
#include <cuda_bf16.h>
#include <math.h>
#include <cstdint>

// ---------------- problem constants ----------------
#define BATCH 8
#define SEQ 2048
#define TOK (BATCH*SEQ)          // 16384
#define DMODEL 512
#define DINNER 1024
#define DSTATE 128
#define NHEADS 16
#define HEADDIM 64
#define CONVDIM 1280
#define DINPROJ 2320
#define FF 2048
#define CHUNK 128
#define NCHUNK (SEQ/CHUNK)       // 16
#define NBLK (BATCH*NCHUNK*NHEADS) // 2048
#define EPSF 1e-5f

typedef unsigned long long ull;

// ---------------- packed f32x2 helpers ----------------
__device__ __forceinline__ ull pk(float x) {
    ull r; asm("mov.b64 %0,{%1,%2};" : "=l"(r) : "f"(x), "f"(x)); return r;
}
__device__ __forceinline__ ull ffma2(ull a, ull b, ull c) {
    ull d; asm("fma.rn.f32x2 %0,%1,%2,%3;" : "=l"(d) : "l"(a), "l"(b), "l"(c)); return d;
}
__device__ __forceinline__ float2 upk(ull v) {
    float2 f; asm("mov.b64 {%0,%1},%2;" : "=f"(f.x), "=f"(f.y) : "l"(v)); return f;
}

#define MMA_BF16(cc, aa, b0, b1) \
    asm volatile("mma.sync.aligned.m16n8k16.row.col.f32.bf16.bf16.f32 " \
        "{%0,%1,%2,%3},{%4,%5,%6,%7},{%8,%9},{%0,%1,%2,%3};" \
        : "+f"(cc[0]), "+f"(cc[1]), "+f"(cc[2]), "+f"(cc[3]) \
        : "r"(aa[0]), "r"(aa[1]), "r"(aa[2]), "r"(aa[3]), "r"(b0), "r"(b1))

#define LDSM_X4(r, addr) \
    asm volatile("ldmatrix.sync.aligned.m8n8.x4.shared.b16 {%0,%1,%2,%3},[%4];" \
        : "=r"((r)[0]), "=r"((r)[1]), "=r"((r)[2]), "=r"((r)[3]) : "r"(addr))

// ---------------- scratch ----------------
__device__ __align__(16) float g_zx[TOK*DINPROJ];
__device__ __align__(16) float g_xbc[TOK*CONVDIM];
__device__ __align__(16) float g_dt[NBLK*CHUNK];
__device__ __align__(16) float g_acs[NBLK*CHUNK];
__device__ __align__(16) float g_states[(size_t)NBLK*DSTATE*HEADDIM];
__device__ __align__(16) float g_prev[(size_t)NBLK*DSTATE*HEADDIM];
__device__ __align__(16) float g_y[(size_t)TOK*DINNER];
__device__ __align__(16) float g_mo[(size_t)TOK*DMODEL];
__device__ __align__(16) float g_t[(size_t)TOK*DMODEL];
__device__ __align__(16) float g_f2[(size_t)TOK*DMODEL];
// bf16x3 expanded operands
__device__ __align__(16) __nv_bfloat16 g_A3[(size_t)TOK*3*DINNER];   // A-side (max K=1024)
__device__ __align__(16) __nv_bfloat16 g_A3b[(size_t)TOK*3*FF];      // f1 bf16x3 (K=2048)
__device__ __align__(16) __nv_bfloat16 g_W3[DINPROJ*3*DMODEL];

// ---------------- helpers ----------------
__device__ __forceinline__ void blockReduce2(float& a, float& b, float* sh) {
    int lane = threadIdx.x & 31, w = threadIdx.x >> 5;
    #pragma unroll
    for (int o = 16; o; o >>= 1) {
        a += __shfl_xor_sync(0xffffffffu, a, o);
        b += __shfl_xor_sync(0xffffffffu, b, o);
    }
    if (lane == 0) { sh[w] = a; sh[32 + w] = b; }
    __syncthreads();
    int nw = blockDim.x >> 5;
    if (w == 0) {
        a = (lane < nw) ? sh[lane] : 0.f;
        b = (lane < nw) ? sh[32 + lane] : 0.f;
        #pragma unroll
        for (int o = 16; o; o >>= 1) {
            a += __shfl_xor_sync(0xffffffffu, a, o);
            b += __shfl_xor_sync(0xffffffffu, b, o);
        }
        if (lane == 0) { sh[0] = a; sh[32] = b; }
    }
    __syncthreads();
    a = sh[0]; b = sh[32];
}

__device__ __forceinline__ void bf16x3_store_scalar(__nv_bfloat16* row, int K, int d, float s) {
    __nv_bfloat16 hi = __float2bfloat16_rn(s);
    __nv_bfloat16 lo = __float2bfloat16_rn(s - __bfloat162float(hi));
    row[d] = hi; row[K + d] = hi; row[2 * K + d] = lo;
}

// ---------------- bf16x3 split: src[M,K] fp32 -> dst[M,3K] bf16 ----------------
template<int LOQ>
__global__ void k_split(const float* __restrict__ src, __nv_bfloat16* __restrict__ dst, int K) {
    size_t i = (size_t)blockIdx.x * 256 + threadIdx.x;
    int K4 = K >> 2;
    size_t row = i / K4;
    int c4 = (int)(i % K4);
    float4 v = ((const float4*)src)[i];
    __nv_bfloat162 h0, h1, l0, l1;
    h0.x = __float2bfloat16_rn(v.x); h0.y = __float2bfloat16_rn(v.y);
    h1.x = __float2bfloat16_rn(v.z); h1.y = __float2bfloat16_rn(v.w);
    l0.x = __float2bfloat16_rn(v.x - __bfloat162float(h0.x));
    l0.y = __float2bfloat16_rn(v.y - __bfloat162float(h0.y));
    l1.x = __float2bfloat16_rn(v.z - __bfloat162float(h1.x));
    l1.y = __float2bfloat16_rn(v.w - __bfloat162float(h1.y));
    __nv_bfloat162* d = (__nv_bfloat162*)(dst + row * 3 * K);
    int c2 = c4 * 2;
    int K2 = K >> 1;
    d[c2] = h0; d[c2 + 1] = h1;
    d[K2 + c2]     = (LOQ == 1) ? l0 : h0;
    d[K2 + c2 + 1] = (LOQ == 1) ? l1 : h1;
    d[2 * K2 + c2]     = (LOQ == 2) ? l0 : h0;
    d[2 * K2 + c2 + 1] = (LOQ == 2) ? l1 : h1;
}

// ---------------- bf16 tensor-core GEMM with ldmatrix fragments ----------------
// 128x128 tile, 256 threads (8 warps 4x2, warp tile 32x64), BK=32, double-buffered smem.
// OUT3: write output as bf16x3 A-operand (thirds hi|hi|lo) with pitch 3N. N must be /128.
#define SPITCH 40
template<int ACT, int OUT3>
__global__ void __launch_bounds__(256) k_gemm_bf16(const __nv_bfloat16* __restrict__ A,
                                                   const __nv_bfloat16* __restrict__ W,
                                                   const float* __restrict__ bias,
                                                   void* __restrict__ Cout,
                                                   int N, int K3) {
    __shared__ __align__(16) __nv_bfloat16 As[2][128][SPITCH];
    __shared__ __align__(16) __nv_bfloat16 Ws[2][128][SPITCH];
    int tid = threadIdx.x;
    int bm = blockIdx.y * 128, bn = blockIdx.x * 128;
    int lr = tid >> 1, lc = (tid & 1) * 16;
    int lane = tid & 31, wid = tid >> 5;
    int wm = (wid & 3) * 32, wn = (wid >> 2) * 64;
    int g = lane >> 2, t4 = lane & 3;

    float c[2][8][4];
    #pragma unroll
    for (int mi = 0; mi < 2; mi++)
        #pragma unroll
        for (int ni = 0; ni < 8; ni++)
            #pragma unroll
            for (int q = 0; q < 4; q++) c[mi][ni][q] = 0.f;

    const __nv_bfloat16* Aptr = A + (size_t)(bm + lr) * K3 + lc;
    int wr = bn + lr;
    const __nv_bfloat16* Wptr = (wr < N) ? (W + (size_t)wr * K3 + lc) : nullptr;

    uint32_t sbA = (uint32_t)__cvta_generic_to_shared(&As[0][0][0]);
    uint32_t sbW = (uint32_t)__cvta_generic_to_shared(&Ws[0][0][0]);
    const uint32_t bufStride = 128 * SPITCH * 2;

    int l7 = lane & 7;
    int aRow = wm + ((lane >> 3) & 1) * 8 + l7;
    int aCol = (lane >> 4) * 8;
    int bRow = wn + (lane >> 4) * 8 + l7;
    int bCol = ((lane >> 3) & 1) * 8;

    uint4 a0, a1, w0, w1;
    a0 = *(const uint4*)(Aptr); a1 = *(const uint4*)(Aptr + 8);
    if (Wptr) { w0 = *(const uint4*)(Wptr); w1 = *(const uint4*)(Wptr + 8); }
    else { w0 = make_uint4(0, 0, 0, 0); w1 = w0; }

    int KT = K3 / 32;
    *(uint4*)&As[0][lr][lc] = a0; *(uint4*)&As[0][lr][lc + 8] = a1;
    *(uint4*)&Ws[0][lr][lc] = w0; *(uint4*)&Ws[0][lr][lc + 8] = w1;
    __syncthreads();

    for (int kt = 0; kt < KT; kt++) {
        int cur = kt & 1;
        bool hasNext = (kt + 1 < KT);
        if (hasNext) {
            const __nv_bfloat16* ap = Aptr + (kt + 1) * 32;
            a0 = *(const uint4*)(ap); a1 = *(const uint4*)(ap + 8);
            if (Wptr) {
                const __nv_bfloat16* wp = Wptr + (kt + 1) * 32;
                w0 = *(const uint4*)(wp); w1 = *(const uint4*)(wp + 8);
            }
        }
        uint32_t aBase = sbA + cur * bufStride;
        uint32_t wBase = sbW + cur * bufStride;
        #pragma unroll
        for (int kk = 0; kk < 32; kk += 16) {
            uint32_t af[2][4], bf[4][4];
            #pragma unroll
            for (int mi = 0; mi < 2; mi++) {
                uint32_t addr = aBase + (uint32_t)(((aRow + mi * 16) * SPITCH + aCol + kk) * 2);
                LDSM_X4(af[mi], addr);
            }
            #pragma unroll
            for (int q = 0; q < 4; q++) {
                uint32_t addr = wBase + (uint32_t)(((bRow + q * 16) * SPITCH + bCol + kk) * 2);
                LDSM_X4(bf[q], addr);
            }
            #pragma unroll
            for (int q = 0; q < 4; q++) {
                MMA_BF16(c[0][2 * q],     af[0], bf[q][0], bf[q][1]);
                MMA_BF16(c[1][2 * q],     af[1], bf[q][0], bf[q][1]);
                MMA_BF16(c[0][2 * q + 1], af[0], bf[q][2], bf[q][3]);
                MMA_BF16(c[1][2 * q + 1], af[1], bf[q][2], bf[q][3]);
            }
        }
        if (hasNext) {
            int nxt = cur ^ 1;
            *(uint4*)&As[nxt][lr][lc] = a0; *(uint4*)&As[nxt][lr][lc + 8] = a1;
            *(uint4*)&Ws[nxt][lr][lc] = w0; *(uint4*)&Ws[nxt][lr][lc + 8] = w1;
            __syncthreads();
        }
    }

    // epilogue
    #pragma unroll
    for (int mi = 0; mi < 2; mi++) {
        int r0 = bm + wm + mi * 16 + g;
        #pragma unroll
        for (int ni = 0; ni < 8; ni++) {
            int col = bn + wn + ni * 8 + 2 * t4;
            #pragma unroll
            for (int half = 0; half < 2; half++) {
                int r = r0 + half * 8;
                float v0 = c[mi][ni][half * 2 + 0];
                float v1 = c[mi][ni][half * 2 + 1];
                if (bias) { v0 += bias[col]; v1 += bias[col + 1]; }
                if (ACT == 1) {
                    v0 = 0.5f * v0 * (1.f + erff(v0 * 0.70710678118654752f));
                    v1 = 0.5f * v1 * (1.f + erff(v1 * 0.70710678118654752f));
                }
                if (OUT3) {
                    __nv_bfloat16* O = (__nv_bfloat16*)Cout;
                    __nv_bfloat162 hi, lo;
                    hi.x = __float2bfloat16_rn(v0); hi.y = __float2bfloat16_rn(v1);
                    lo.x = __float2bfloat16_rn(v0 - __bfloat162float(hi.x));
                    lo.y = __float2bfloat16_rn(v1 - __bfloat162float(hi.y));
                    size_t base = (size_t)r * 3 * N + col;
                    *(__nv_bfloat162*)&O[base]         = hi;
                    *(__nv_bfloat162*)&O[base + N]     = hi;
                    *(__nv_bfloat162*)&O[base + 2 * N] = lo;
                } else {
                    float* Cf = (float*)Cout;
                    if (col < N)     Cf[(size_t)r * N + col]     = v0;
                    if (col + 1 < N) Cf[(size_t)r * N + col + 1] = v1;
                }
            }
        }
    }
}

// ---------------- causal depthwise conv1d + silu ----------------
__global__ void k_conv(const float* __restrict__ conv_w, const float* __restrict__ conv_b) {
    int idx = blockIdx.x * 256 + threadIdx.x;
    int ch = idx % CONVDIM;
    int s  = (idx / CONVDIM) % SEQ;
    int b  = idx / (CONVDIM * SEQ);
    float acc = conv_b[ch];
    #pragma unroll
    for (int k = 0; k < 4; k++) {
        int sp = s + k - 3;
        if (sp >= 0)
            acc += g_zx[(size_t)(b * SEQ + sp) * DINPROJ + DINNER + ch] * conv_w[ch * 4 + k];
    }
    acc = acc / (1.f + expf(-acc));
    g_xbc[idx] = acc;
}

// ---------------- dt softplus + per-chunk cumulative log-decay ----------------
__global__ void k_dtscan(const float* __restrict__ dt_bias, const float* __restrict__ A_log) {
    __shared__ float s[128];
    int blk = blockIdx.x, l = threadIdx.x;
    int h = blk & 15, c = (blk >> 4) & 15, b = blk >> 8;
    int tok = b * SEQ + c * CHUNK + l;
    float raw = g_zx[(size_t)tok * DINPROJ + 2304 + h] + dt_bias[h];
    float dtv = (raw > 20.f) ? raw : log1pf(expf(raw));
    float A = -expf(A_log[h]);
    g_dt[blk * 128 + l] = dtv;
    s[l] = dtv * A;
    __syncthreads();
    #pragma unroll
    for (int off = 1; off < 128; off <<= 1) {
        float t = (l >= off) ? s[l - off] : 0.f;
        __syncthreads();
        s[l] += t;
        __syncthreads();
    }
    g_acs[blk * 128 + l] = s[l];
}

// ---------------- per-chunk end states: 256 threads, (n, p-half) per thread ----------------
__global__ void __launch_bounds__(256) k_states() {
    extern __shared__ __align__(16) float sh[];
    float* Bs = sh;              // 128*128
    float* xs = Bs + 16384;      // 128*64
    float* ws = xs + 8192;       // 128
    int blk = blockIdx.x, tid = threadIdx.x;
    int n = tid & 127, half = tid >> 7;
    int h = blk & 15, c = (blk >> 4) & 15, b = blk >> 8;
    int base = b * SEQ + c * CHUNK;
    for (int q = tid; q < 16384; q += 256) {
        int l = q >> 7, nn = q & 127;
        Bs[q] = g_xbc[(size_t)(base + l) * CONVDIM + DINNER + nn];
    }
    for (int q = tid; q < 8192; q += 256) {
        int l = q >> 6, p = q & 63;
        xs[q] = g_xbc[(size_t)(base + l) * CONVDIM + h * 64 + p];
    }
    if (tid < 128) {
        float acsL = g_acs[blk * 128 + 127];
        ws[tid] = expf(acsL - g_acs[blk * 128 + tid]) * g_dt[blk * 128 + tid];
    }
    __syncthreads();
    ull acc2[16];
    #pragma unroll
    for (int q = 0; q < 16; q++) acc2[q] = 0ull;
    for (int l = 0; l < 128; l++) {
        float bw = Bs[l * 128 + n] * ws[l];
        ull bwp = pk(bw);
        const ulonglong2* xl = (const ulonglong2*)&xs[l * 64 + half * 32];
        #pragma unroll
        for (int q = 0; q < 8; q++) {
            ulonglong2 v = xl[q];
            acc2[2 * q]     = ffma2(bwp, v.x, acc2[2 * q]);
            acc2[2 * q + 1] = ffma2(bwp, v.y, acc2[2 * q + 1]);
        }
    }
    ulonglong2* dst = (ulonglong2*)&g_states[(size_t)blk * 8192 + n * 64 + half * 32];
    #pragma unroll
    for (int q = 0; q < 8; q++) {
        ulonglong2 v; v.x = acc2[2 * q]; v.y = acc2[2 * q + 1];
        dst[q] = v;
    }
}

// ---------------- sequential chunk scan ----------------
__global__ void k_scan() {
    int bx = blockIdx.x;
    int b = bx >> 4, h = bx & 15;
    int tid = threadIdx.x;
    for (int e = tid; e < 8192; e += 256) {
        float acc = 0.f;
        #pragma unroll
        for (int c = 0; c < NCHUNK; c++) {
            int blk = ((b * NCHUNK + c) << 4) + h;
            g_prev[(size_t)blk * 8192 + e] = acc;
            float cd = expf(g_acs[blk * 128 + 127]);
            acc = cd * acc + g_states[(size_t)blk * 8192 + e];
        }
    }
}

// ---------------- fused SSD output: 256 threads, j-parity split per row ----------------
#define CPAD 132
__global__ void __launch_bounds__(256, 1) k_y(const float* __restrict__ D_head) {
    extern __shared__ __align__(16) float sh[];
    float* Cs   = sh;                 // 128*CPAD
    float* Bs   = Cs + 128 * CPAD;    // 128*128 (reused as staging at the end)
    float* xs   = Bs + 16384;         // 128*64
    float* ps   = xs + 8192;          // 128*64
    float* acs_s = ps + 8192;         // 128
    float* dt_s  = acs_s + 128;       // 128
    int blk = blockIdx.x, tid = threadIdx.x;
    int i = tid & 127, par = tid >> 7;
    int h = blk & 15, c = (blk >> 4) & 15, b = blk >> 8;
    int base = b * SEQ + c * CHUNK;

    for (int q = tid; q < 16384; q += 256) {
        int l = q >> 7, n = q & 127;
        const float* row = &g_xbc[(size_t)(base + l) * CONVDIM];
        Cs[l * CPAD + n] = row[DINNER + DSTATE + n];
        Bs[q]            = row[DINNER + n];
    }
    for (int q = tid; q < 8192; q += 256) {
        int l = q >> 6, p = q & 63;
        xs[q] = g_xbc[(size_t)(base + l) * CONVDIM + h * 64 + p];
    }
    {
        const float4* src = (const float4*)&g_prev[(size_t)blk * 8192];
        float4* d = (float4*)ps;
        for (int q = tid; q < 2048; q += 256) d[q] = src[q];
    }
    if (tid < 128) {
        acs_s[tid] = g_acs[blk * 128 + tid];
        dt_s[tid]  = g_dt[blk * 128 + tid];
    }
    __syncthreads();

    ull Ci[64];
    {
        const ulonglong2* cp = (const ulonglong2*)&Cs[i * CPAD];
        #pragma unroll
        for (int q = 0; q < 32; q++) { ulonglong2 v = cp[q]; Ci[2 * q] = v.x; Ci[2 * q + 1] = v.y; }
    }
    ull y2[32];
    #pragma unroll
    for (int q = 0; q < 32; q++) y2[q] = 0ull;
    float ai = acs_s[i];

    // Y_diag: this thread does j = par, par+2, ... <= i
    for (int j = par; j <= i; j += 2) {
        const ulonglong2* Bj = (const ulonglong2*)&Bs[j * 128];
        ull da = 0ull, db = 0ull, dc = 0ull, dd = 0ull;
        #pragma unroll
        for (int q = 0; q < 16; q++) {
            ulonglong2 v0 = Bj[2 * q];
            ulonglong2 v1 = Bj[2 * q + 1];
            da = ffma2(Ci[4 * q + 0], v0.x, da);
            db = ffma2(Ci[4 * q + 1], v0.y, db);
            dc = ffma2(Ci[4 * q + 2], v1.x, dc);
            dd = ffma2(Ci[4 * q + 3], v1.y, dd);
        }
        float2 fa = upk(da), fb = upk(db), fc = upk(dc), fd = upk(dd);
        float d = (fa.x + fa.y) + (fb.x + fb.y) + (fc.x + fc.y) + (fd.x + fd.y);
        float g = expf(ai - acs_s[j]) * dt_s[j] * d;
        ull gp = pk(g);
        const ulonglong2* xj = (const ulonglong2*)&xs[j * 64];
        #pragma unroll
        for (int q = 0; q < 16; q++) {
            ulonglong2 v = xj[q];
            y2[2 * q]     = ffma2(gp, v.x, y2[2 * q]);
            y2[2 * q + 1] = ffma2(gp, v.y, y2[2 * q + 1]);
        }
    }

    // Y_off: this thread does n with n&1 == par
    float e = expf(ai);
    #pragma unroll 4
    for (int q = 0; q < 64; q++) {
        float2 cf = upk(Ci[q]);
        float cv = par ? cf.y : cf.x;
        ull c0 = pk(e * cv);
        const ulonglong2* p0 = (const ulonglong2*)&ps[(2 * q + par) * 64];
        #pragma unroll
        for (int r = 0; r < 16; r++) {
            ulonglong2 v0 = p0[r];
            y2[2 * r]     = ffma2(c0, v0.x, y2[2 * r]);
            y2[2 * r + 1] = ffma2(c0, v0.y, y2[2 * r + 1]);
        }
    }

    // + D*x (par 0 only)
    if (par == 0) {
        float dh = D_head[h];
        ull dhp = pk(dh);
        const ulonglong2* xi = (const ulonglong2*)&xs[i * 64];
        #pragma unroll
        for (int q = 0; q < 16; q++) {
            ulonglong2 v = xi[q];
            y2[2 * q]     = ffma2(dhp, v.x, y2[2 * q]);
            y2[2 * q + 1] = ffma2(dhp, v.y, y2[2 * q + 1]);
        }
    }

    // combine halves through Bs (no longer needed)
    __syncthreads();
    if (par == 1) {
        ulonglong2* st = (ulonglong2*)&Bs[i * 64];
        #pragma unroll
        for (int q = 0; q < 16; q++) {
            ulonglong2 v; v.x = y2[2 * q]; v.y = y2[2 * q + 1];
            st[q] = v;
        }
    }
    __syncthreads();
    if (par == 0) {
        const ulonglong2* st = (const ulonglong2*)&Bs[i * 64];
        ull one = pk(1.f);
        #pragma unroll
        for (int q = 0; q < 16; q++) {
            ulonglong2 v = st[q];
            y2[2 * q]     = ffma2(one, v.x, y2[2 * q]);
            y2[2 * q + 1] = ffma2(one, v.y, y2[2 * q + 1]);
        }
        ulonglong2* dst = (ulonglong2*)&g_y[(size_t)(base + i) * DINNER + h * 64];
        #pragma unroll
        for (int q = 0; q < 16; q++) {
            ulonglong2 v; v.x = y2[2 * q]; v.y = y2[2 * q + 1];
            dst[q] = v;
        }
    }
}

// ---------------- gate with silu(z) + RMSNorm * norm_w -> bf16x3 A operand ----------------
__global__ void k_gate(const float* __restrict__ norm_w, __nv_bfloat16* __restrict__ out3) {
    __shared__ float red[64];
    int t = blockIdx.x, tid = threadIdx.x;
    float v[4]; float ss = 0.f, dummy = 0.f;
    #pragma unroll
    for (int k = 0; k < 4; k++) {
        int d = tid + k * 256;
        float yv = g_y[(size_t)t * DINNER + d];
        float zv = g_zx[(size_t)t * DINPROJ + d];
        float sv = yv * (zv / (1.f + expf(-zv)));
        v[k] = sv; ss += sv * sv;
    }
    blockReduce2(ss, dummy, red);
    float sc = rsqrtf(ss * (1.f / 1024.f) + EPSF);
    __nv_bfloat16* row = out3 + (size_t)t * 3 * DINNER;
    #pragma unroll
    for (int k = 0; k < 4; k++) {
        int d = tid + k * 256;
        bf16x3_store_scalar(row, DINNER, d, v[k] * sc * norm_w[d]);
    }
}

// ---------------- out = LayerNorm(a + b) * w + beta (D=512), optional bf16x3 copy ----------------
__global__ void k_addln(const float* __restrict__ a, const float* __restrict__ bsrc,
                        const float* __restrict__ w, const float* __restrict__ beta,
                        float* __restrict__ o, __nv_bfloat16* __restrict__ out3) {
    __shared__ float red[64];
    int t = blockIdx.x, tid = threadIdx.x;
    float v[4]; float s = 0.f, ssq = 0.f;
    #pragma unroll
    for (int k = 0; k < 4; k++) {
        int d = tid + k * 128;
        float x = a[(size_t)t * DMODEL + d] + bsrc[(size_t)t * DMODEL + d];
        v[k] = x; s += x; ssq += x * x;
    }
    blockReduce2(s, ssq, red);
    float mean = s * (1.f / 512.f);
    float var = ssq * (1.f / 512.f) - mean * mean;
    float inv = rsqrtf(var + EPSF);
    #pragma unroll
    for (int k = 0; k < 4; k++) {
        int d = tid + k * 128;
        float r = (v[k] - mean) * inv * w[d] + beta[d];
        o[(size_t)t * DMODEL + d] = r;
        if (out3) bf16x3_store_scalar(out3 + (size_t)t * 3 * DMODEL, DMODEL, d, r);
    }
}

// ---------------- launch ----------------
static inline void splitA(const float* src, __nv_bfloat16* dst, int M, int K) {
    k_split<2><<<(int)(((size_t)M * K / 4) / 256), 256>>>(src, dst, K);
}
static inline void splitW(const float* src, __nv_bfloat16* dst, int M, int K) {
    k_split<1><<<(int)(((size_t)M * K / 4) / 256), 256>>>(src, dst, K);
}

extern "C" void kernel_launch(void* const* d_in, const int* in_sizes, int n_in,
                              void* d_out, int out_size) {
    const float* tgt        = (const float*)d_in[0];
    const float* in_proj_w  = (const float*)d_in[5];
    const float* conv_w     = (const float*)d_in[6];
    const float* conv_b     = (const float*)d_in[7];
    const float* dt_bias    = (const float*)d_in[8];
    const float* A_log      = (const float*)d_in[9];
    const float* D_head     = (const float*)d_in[10];
    const float* norm_w     = (const float*)d_in[11];
    const float* out_proj_w = (const float*)d_in[12];
    const float* n1w = (const float*)d_in[13];
    const float* n1b = (const float*)d_in[14];
    const float* w1  = (const float*)d_in[15];
    const float* b1  = (const float*)d_in[16];
    const float* w2  = (const float*)d_in[17];
    const float* b2  = (const float*)d_in[18];
    const float* n3w = (const float*)d_in[19];
    const float* n3b = (const float*)d_in[20];
    float* out = (float*)d_out;

    float *zx, *mo, *tb, *f2;
    __nv_bfloat16 *A3, *A3b, *W3;
    cudaGetSymbolAddress((void**)&zx,   g_zx);
    cudaGetSymbolAddress((void**)&mo,   g_mo);
    cudaGetSymbolAddress((void**)&tb,   g_t);
    cudaGetSymbolAddress((void**)&f2,   g_f2);
    cudaGetSymbolAddress((void**)&A3,   g_A3);
    cudaGetSymbolAddress((void**)&A3b,  g_A3b);
    cudaGetSymbolAddress((void**)&W3,   g_W3);

    const int smem_states = (16384 + 8192 + 128) * 4;
    const int smem_y = (128 * CPAD + 16384 + 8192 + 8192 + 256) * 4;
    cudaFuncSetAttribute(k_states, cudaFuncAttributeMaxDynamicSharedMemorySize, smem_states);
    cudaFuncSetAttribute(k_y,      cudaFuncAttributeMaxDynamicSharedMemorySize, smem_y);

    // 1. in_proj: zx = tgt @ in_proj_w^T
    splitA(tgt, A3, TOK, DMODEL);
    splitW(in_proj_w, W3, DINPROJ, DMODEL);
    k_gemm_bf16<0, 0><<<dim3((DINPROJ + 127) / 128, TOK / 128), 256>>>(A3, W3, nullptr, zx, DINPROJ, 3 * DMODEL);
    // 2. conv + silu
    k_conv<<<(TOK * CONVDIM) / 256, 256>>>(conv_w, conv_b);
    // 3. dt softplus + cumsum
    k_dtscan<<<NBLK, 128>>>(dt_bias, A_log);
    // 4. chunk end-states
    k_states<<<NBLK, 256, smem_states>>>();
    // 5. chunk scan -> prev
    k_scan<<<BATCH * NHEADS, 256>>>();
    // 6. fused SSD output
    k_y<<<NBLK, 256, smem_y>>>(D_head);
    // 7. gate + rmsnorm -> bf16x3 directly
    k_gate<<<TOK, 256>>>(norm_w, A3);
    // 8. out_proj: mo = gate @ out_proj_w^T
    splitW(out_proj_w, W3, DMODEL, DINNER);
    k_gemm_bf16<0, 0><<<dim3(DMODEL / 128, TOK / 128), 256>>>(A3, W3, nullptr, mo, DMODEL, 3 * DINNER);
    // 9. t = LN(tgt + mo), also emit bf16x3 for FFN GEMM
    k_addln<<<TOK, 128>>>(tgt, mo, n1w, n1b, tb, A3);
    // 10. f1 = gelu(t @ w1^T + b1) -> bf16x3 directly
    splitW(w1, W3, FF, DMODEL);
    k_gemm_bf16<1, 1><<<dim3(FF / 128, TOK / 128), 256>>>(A3, W3, b1, A3b, FF, 3 * DMODEL);
    // 11. f2 = f1 @ w2^T + b2
    splitW(w2, W3, DMODEL, FF);
    k_gemm_bf16<0, 0><<<dim3(DMODEL / 128, TOK / 128), 256>>>(A3b, W3, b2, f2, DMODEL, 3 * FF);
    // 12. out = LN(t + f2)
    k_addln<<<TOK, 128>>>(tb, f2, n3w, n3b, out, nullptr);
}

// round 10
// speedup vs baseline: 2.0590x; 1.0286x over previous
#include <cuda_runtime.h>
#include <cuda_bf16.h>
#include <math.h>
#include <cstdint>

// ---------------- problem constants ----------------
#define BATCH 8
#define SEQ 2048
#define TOK (BATCH*SEQ)          // 16384
#define DMODEL 512
#define DINNER 1024
#define DSTATE 128
#define NHEADS 16
#define HEADDIM 64
#define CONVDIM 1280
#define DINPROJ 2320
#define FF 2048
#define CHUNK 128
#define NCHUNK (SEQ/CHUNK)       // 16
#define NBLK (BATCH*NCHUNK*NHEADS) // 2048
#define EPSF 1e-5f

typedef unsigned long long ull;

// ---------------- packed f32x2 helpers ----------------
__device__ __forceinline__ ull pk(float x) {
    ull r; asm("mov.b64 %0,{%1,%2};" : "=l"(r) : "f"(x), "f"(x)); return r;
}
__device__ __forceinline__ ull ffma2(ull a, ull b, ull c) {
    ull d; asm("fma.rn.f32x2 %0,%1,%2,%3;" : "=l"(d) : "l"(a), "l"(b), "l"(c)); return d;
}
__device__ __forceinline__ float2 upk(ull v) {
    float2 f; asm("mov.b64 {%0,%1},%2;" : "=f"(f.x), "=f"(f.y) : "l"(v)); return f;
}

#define MMA_BF16(cc, aa, b0, b1) \
    asm volatile("mma.sync.aligned.m16n8k16.row.col.f32.bf16.bf16.f32 " \
        "{%0,%1,%2,%3},{%4,%5,%6,%7},{%8,%9},{%0,%1,%2,%3};" \
        : "+f"(cc[0]), "+f"(cc[1]), "+f"(cc[2]), "+f"(cc[3]) \
        : "r"(aa[0]), "r"(aa[1]), "r"(aa[2]), "r"(aa[3]), "r"(b0), "r"(b1))

#define LDSM_X4(r, addr) \
    asm volatile("ldmatrix.sync.aligned.m8n8.x4.shared.b16 {%0,%1,%2,%3},[%4];" \
        : "=r"((r)[0]), "=r"((r)[1]), "=r"((r)[2]), "=r"((r)[3]) : "r"(addr))

#define CP_ASYNC16(dst, src) \
    asm volatile("cp.async.cg.shared.global [%0], [%1], 16;" :: "r"(dst), "l"(src))
#define CP_COMMIT() asm volatile("cp.async.commit_group;" ::: "memory")
#define CP_WAIT3()  asm volatile("cp.async.wait_group 3;" ::: "memory")
#define CP_WAIT0()  asm volatile("cp.async.wait_group 0;" ::: "memory")

// ---------------- scratch ----------------
__device__ __align__(16) float g_zx[TOK*DINPROJ];
__device__ __align__(16) float g_xbc[TOK*CONVDIM];
__device__ __align__(16) float g_dt[NBLK*CHUNK];
__device__ __align__(16) float g_acs[NBLK*CHUNK];
__device__ __align__(16) float g_states[(size_t)NBLK*DSTATE*HEADDIM];
__device__ __align__(16) float g_prev[(size_t)NBLK*DSTATE*HEADDIM];
__device__ __align__(16) float g_y[(size_t)TOK*DINNER];
__device__ __align__(16) float g_mo[(size_t)TOK*DMODEL];
__device__ __align__(16) float g_t[(size_t)TOK*DMODEL];
__device__ __align__(16) float g_f2[(size_t)TOK*DMODEL];
// bf16x3 expanded operands
__device__ __align__(16) __nv_bfloat16 g_A3[(size_t)TOK*3*DINNER];
__device__ __align__(16) __nv_bfloat16 g_A3b[(size_t)TOK*3*FF];
__device__ __align__(16) __nv_bfloat16 g_W3[DINPROJ*3*DMODEL];

// ---------------- helpers ----------------
__device__ __forceinline__ void blockReduce2(float& a, float& b, float* sh) {
    int lane = threadIdx.x & 31, w = threadIdx.x >> 5;
    #pragma unroll
    for (int o = 16; o; o >>= 1) {
        a += __shfl_xor_sync(0xffffffffu, a, o);
        b += __shfl_xor_sync(0xffffffffu, b, o);
    }
    if (lane == 0) { sh[w] = a; sh[32 + w] = b; }
    __syncthreads();
    int nw = blockDim.x >> 5;
    if (w == 0) {
        a = (lane < nw) ? sh[lane] : 0.f;
        b = (lane < nw) ? sh[32 + lane] : 0.f;
        #pragma unroll
        for (int o = 16; o; o >>= 1) {
            a += __shfl_xor_sync(0xffffffffu, a, o);
            b += __shfl_xor_sync(0xffffffffu, b, o);
        }
        if (lane == 0) { sh[0] = a; sh[32] = b; }
    }
    __syncthreads();
    a = sh[0]; b = sh[32];
}

__device__ __forceinline__ void bf16x3_store_scalar(__nv_bfloat16* row, int K, int d, float s) {
    __nv_bfloat16 hi = __float2bfloat16_rn(s);
    __nv_bfloat16 lo = __float2bfloat16_rn(s - __bfloat162float(hi));
    row[d] = hi; row[K + d] = hi; row[2 * K + d] = lo;
}

// ---------------- bf16x3 split: src[M,K] fp32 -> dst[M,3K] bf16 ----------------
template<int LOQ>
__global__ void k_split(const float* __restrict__ src, __nv_bfloat16* __restrict__ dst, int K) {
    size_t i = (size_t)blockIdx.x * 256 + threadIdx.x;
    int K4 = K >> 2;
    size_t row = i / K4;
    int c4 = (int)(i % K4);
    float4 v = ((const float4*)src)[i];
    __nv_bfloat162 h0, h1, l0, l1;
    h0.x = __float2bfloat16_rn(v.x); h0.y = __float2bfloat16_rn(v.y);
    h1.x = __float2bfloat16_rn(v.z); h1.y = __float2bfloat16_rn(v.w);
    l0.x = __float2bfloat16_rn(v.x - __bfloat162float(h0.x));
    l0.y = __float2bfloat16_rn(v.y - __bfloat162float(h0.y));
    l1.x = __float2bfloat16_rn(v.z - __bfloat162float(h1.x));
    l1.y = __float2bfloat16_rn(v.w - __bfloat162float(h1.y));
    __nv_bfloat162* d = (__nv_bfloat162*)(dst + row * 3 * K);
    int c2 = c4 * 2;
    int K2 = K >> 1;
    d[c2] = h0; d[c2 + 1] = h1;
    d[K2 + c2]     = (LOQ == 1) ? l0 : h0;
    d[K2 + c2 + 1] = (LOQ == 1) ? l1 : h1;
    d[2 * K2 + c2]     = (LOQ == 2) ? l0 : h0;
    d[2 * K2 + c2 + 1] = (LOQ == 2) ? l1 : h1;
}

// ---------------- bf16 tensor-core GEMM, 4-stage cp.async pipeline ----------------
// 128x128 tile, 256 threads (8 warps 4x2, warp tile 32x64), BK=32.
#define SPITCH 40
#define NSTG 4
template<int ACT, int OUT3>
__global__ void __launch_bounds__(256) k_gemm_bf16(const __nv_bfloat16* __restrict__ A,
                                                   const __nv_bfloat16* __restrict__ W,
                                                   const float* __restrict__ bias,
                                                   void* __restrict__ Cout,
                                                   int N, int K3) {
    __shared__ __align__(16) __nv_bfloat16 As[NSTG][128][SPITCH];
    __shared__ __align__(16) __nv_bfloat16 Ws[NSTG][128][SPITCH];
    int tid = threadIdx.x;
    int bm = blockIdx.y * 128, bn = blockIdx.x * 128;
    int lr = tid >> 1, lc = (tid & 1) * 16;
    int lane = tid & 31, wid = tid >> 5;
    int wm = (wid & 3) * 32, wn = (wid >> 2) * 64;
    int g = lane >> 2, t4 = lane & 3;

    float c[2][8][4];
    #pragma unroll
    for (int mi = 0; mi < 2; mi++)
        #pragma unroll
        for (int ni = 0; ni < 8; ni++)
            #pragma unroll
            for (int q = 0; q < 4; q++) c[mi][ni][q] = 0.f;

    const __nv_bfloat16* Aptr = A + (size_t)(bm + lr) * K3 + lc;
    int wr = bn + lr; if (wr >= N) wr = N - 1;          // clamp; garbage cols masked in epilogue
    const __nv_bfloat16* Wptr = W + (size_t)wr * K3 + lc;

    uint32_t sbA = (uint32_t)__cvta_generic_to_shared(&As[0][0][0]);
    uint32_t sbW = (uint32_t)__cvta_generic_to_shared(&Ws[0][0][0]);
    const uint32_t bufStride = 128 * SPITCH * 2;
    uint32_t dOff = (uint32_t)((lr * SPITCH + lc) * 2);

    int l7 = lane & 7;
    int aRow = wm + ((lane >> 3) & 1) * 8 + l7;
    int aCol = (lane >> 4) * 8;
    int bRow = wn + (lane >> 4) * 8 + l7;
    int bCol = ((lane >> 3) & 1) * 8;

    int KT = K3 / 32;

    // prologue: issue stages 0..2
    #pragma unroll
    for (int s = 0; s < NSTG - 1; s++) {
        if (s < KT) {
            const __nv_bfloat16* ap = Aptr + s * 32;
            const __nv_bfloat16* wp = Wptr + s * 32;
            uint32_t da = sbA + s * bufStride + dOff;
            uint32_t dw = sbW + s * bufStride + dOff;
            CP_ASYNC16(da, ap); CP_ASYNC16(da + 16, ap + 8);
            CP_ASYNC16(dw, wp); CP_ASYNC16(dw + 16, wp + 8);
        }
        CP_COMMIT();
    }

    for (int kt = 0; kt < KT; kt++) {
        // issue stage kt+3
        {
            int s = kt + NSTG - 1;
            if (s < KT) {
                const __nv_bfloat16* ap = Aptr + s * 32;
                const __nv_bfloat16* wp = Wptr + s * 32;
                uint32_t da = sbA + (s & (NSTG - 1)) * bufStride + dOff;
                uint32_t dw = sbW + (s & (NSTG - 1)) * bufStride + dOff;
                CP_ASYNC16(da, ap); CP_ASYNC16(da + 16, ap + 8);
                CP_ASYNC16(dw, wp); CP_ASYNC16(dw + 16, wp + 8);
            }
            CP_COMMIT();
        }
        CP_WAIT3();
        __syncthreads();

        int cur = kt & (NSTG - 1);
        uint32_t aBase = sbA + cur * bufStride;
        uint32_t wBase = sbW + cur * bufStride;
        #pragma unroll
        for (int kk = 0; kk < 32; kk += 16) {
            uint32_t af[2][4], bf[4][4];
            #pragma unroll
            for (int mi = 0; mi < 2; mi++) {
                uint32_t addr = aBase + (uint32_t)(((aRow + mi * 16) * SPITCH + aCol + kk) * 2);
                LDSM_X4(af[mi], addr);
            }
            #pragma unroll
            for (int q = 0; q < 4; q++) {
                uint32_t addr = wBase + (uint32_t)(((bRow + q * 16) * SPITCH + bCol + kk) * 2);
                LDSM_X4(bf[q], addr);
            }
            #pragma unroll
            for (int q = 0; q < 4; q++) {
                MMA_BF16(c[0][2 * q],     af[0], bf[q][0], bf[q][1]);
                MMA_BF16(c[1][2 * q],     af[1], bf[q][0], bf[q][1]);
                MMA_BF16(c[0][2 * q + 1], af[0], bf[q][2], bf[q][3]);
                MMA_BF16(c[1][2 * q + 1], af[1], bf[q][2], bf[q][3]);
            }
        }
        __syncthreads();
    }
    CP_WAIT0();

    // epilogue
    #pragma unroll
    for (int mi = 0; mi < 2; mi++) {
        int r0 = bm + wm + mi * 16 + g;
        #pragma unroll
        for (int ni = 0; ni < 8; ni++) {
            int col = bn + wn + ni * 8 + 2 * t4;
            #pragma unroll
            for (int half = 0; half < 2; half++) {
                int r = r0 + half * 8;
                float v0 = c[mi][ni][half * 2 + 0];
                float v1 = c[mi][ni][half * 2 + 1];
                if (bias) { v0 += bias[col]; v1 += bias[col + 1]; }
                if (ACT == 1) {
                    v0 = 0.5f * v0 * (1.f + erff(v0 * 0.70710678118654752f));
                    v1 = 0.5f * v1 * (1.f + erff(v1 * 0.70710678118654752f));
                }
                if (OUT3) {
                    __nv_bfloat16* O = (__nv_bfloat16*)Cout;
                    __nv_bfloat162 hi, lo;
                    hi.x = __float2bfloat16_rn(v0); hi.y = __float2bfloat16_rn(v1);
                    lo.x = __float2bfloat16_rn(v0 - __bfloat162float(hi.x));
                    lo.y = __float2bfloat16_rn(v1 - __bfloat162float(hi.y));
                    size_t base = (size_t)r * 3 * N + col;
                    *(__nv_bfloat162*)&O[base]         = hi;
                    *(__nv_bfloat162*)&O[base + N]     = hi;
                    *(__nv_bfloat162*)&O[base + 2 * N] = lo;
                } else {
                    float* Cf = (float*)Cout;
                    if (col < N)     Cf[(size_t)r * N + col]     = v0;
                    if (col + 1 < N) Cf[(size_t)r * N + col + 1] = v1;
                }
            }
        }
    }
}

// ---------------- causal depthwise conv1d + silu ----------------
__global__ void k_conv(const float* __restrict__ conv_w, const float* __restrict__ conv_b) {
    int idx = blockIdx.x * 256 + threadIdx.x;
    int ch = idx % CONVDIM;
    int s  = (idx / CONVDIM) % SEQ;
    int b  = idx / (CONVDIM * SEQ);
    float acc = conv_b[ch];
    #pragma unroll
    for (int k = 0; k < 4; k++) {
        int sp = s + k - 3;
        if (sp >= 0)
            acc += g_zx[(size_t)(b * SEQ + sp) * DINPROJ + DINNER + ch] * conv_w[ch * 4 + k];
    }
    acc = acc / (1.f + expf(-acc));
    g_xbc[idx] = acc;
}

// ---------------- dt softplus + per-chunk cumulative log-decay ----------------
__global__ void k_dtscan(const float* __restrict__ dt_bias, const float* __restrict__ A_log) {
    __shared__ float s[128];
    int blk = blockIdx.x, l = threadIdx.x;
    int h = blk & 15, c = (blk >> 4) & 15, b = blk >> 8;
    int tok = b * SEQ + c * CHUNK + l;
    float raw = g_zx[(size_t)tok * DINPROJ + 2304 + h] + dt_bias[h];
    float dtv = (raw > 20.f) ? raw : log1pf(expf(raw));
    float A = -expf(A_log[h]);
    g_dt[blk * 128 + l] = dtv;
    s[l] = dtv * A;
    __syncthreads();
    #pragma unroll
    for (int off = 1; off < 128; off <<= 1) {
        float t = (l >= off) ? s[l - off] : 0.f;
        __syncthreads();
        s[l] += t;
        __syncthreads();
    }
    g_acs[blk * 128 + l] = s[l];
}

// ---------------- per-chunk end states: 256 threads, (n, p-half) per thread ----------------
__global__ void __launch_bounds__(256) k_states() {
    extern __shared__ __align__(16) float sh[];
    float* Bs = sh;              // 128*128
    float* xs = Bs + 16384;      // 128*64
    float* ws = xs + 8192;       // 128
    int blk = blockIdx.x, tid = threadIdx.x;
    int n = tid & 127, half = tid >> 7;
    int h = blk & 15, c = (blk >> 4) & 15, b = blk >> 8;
    int base = b * SEQ + c * CHUNK;
    for (int q = tid; q < 16384; q += 256) {
        int l = q >> 7, nn = q & 127;
        Bs[q] = g_xbc[(size_t)(base + l) * CONVDIM + DINNER + nn];
    }
    for (int q = tid; q < 8192; q += 256) {
        int l = q >> 6, p = q & 63;
        xs[q] = g_xbc[(size_t)(base + l) * CONVDIM + h * 64 + p];
    }
    if (tid < 128) {
        float acsL = g_acs[blk * 128 + 127];
        ws[tid] = expf(acsL - g_acs[blk * 128 + tid]) * g_dt[blk * 128 + tid];
    }
    __syncthreads();
    ull acc2[16];
    #pragma unroll
    for (int q = 0; q < 16; q++) acc2[q] = 0ull;
    for (int l = 0; l < 128; l++) {
        float bw = Bs[l * 128 + n] * ws[l];
        ull bwp = pk(bw);
        const ulonglong2* xl = (const ulonglong2*)&xs[l * 64 + half * 32];
        #pragma unroll
        for (int q = 0; q < 8; q++) {
            ulonglong2 v = xl[q];
            acc2[2 * q]     = ffma2(bwp, v.x, acc2[2 * q]);
            acc2[2 * q + 1] = ffma2(bwp, v.y, acc2[2 * q + 1]);
        }
    }
    ulonglong2* dst = (ulonglong2*)&g_states[(size_t)blk * 8192 + n * 64 + half * 32];
    #pragma unroll
    for (int q = 0; q < 8; q++) {
        ulonglong2 v; v.x = acc2[2 * q]; v.y = acc2[2 * q + 1];
        dst[q] = v;
    }
}

// ---------------- sequential chunk scan ----------------
__global__ void k_scan() {
    int bx = blockIdx.x;
    int b = bx >> 4, h = bx & 15;
    int tid = threadIdx.x;
    for (int e = tid; e < 8192; e += 256) {
        float acc = 0.f;
        #pragma unroll
        for (int c = 0; c < NCHUNK; c++) {
            int blk = ((b * NCHUNK + c) << 4) + h;
            g_prev[(size_t)blk * 8192 + e] = acc;
            float cd = expf(g_acs[blk * 128 + 127]);
            acc = cd * acc + g_states[(size_t)blk * 8192 + e];
        }
    }
}

// ---------------- fused SSD output: 256 threads, j-parity split per row ----------------
#define CPAD 132
__global__ void __launch_bounds__(256, 1) k_y(const float* __restrict__ D_head) {
    extern __shared__ __align__(16) float sh[];
    float* Cs   = sh;                 // 128*CPAD
    float* Bs   = Cs + 128 * CPAD;    // 128*128 (reused as staging at the end)
    float* xs   = Bs + 16384;         // 128*64
    float* ps   = xs + 8192;          // 128*64
    float* acs_s = ps + 8192;         // 128
    float* dt_s  = acs_s + 128;       // 128
    int blk = blockIdx.x, tid = threadIdx.x;
    int i = tid & 127, par = tid >> 7;
    int h = blk & 15, c = (blk >> 4) & 15, b = blk >> 8;
    int base = b * SEQ + c * CHUNK;

    for (int q = tid; q < 16384; q += 256) {
        int l = q >> 7, n = q & 127;
        const float* row = &g_xbc[(size_t)(base + l) * CONVDIM];
        Cs[l * CPAD + n] = row[DINNER + DSTATE + n];
        Bs[q]            = row[DINNER + n];
    }
    for (int q = tid; q < 8192; q += 256) {
        int l = q >> 6, p = q & 63;
        xs[q] = g_xbc[(size_t)(base + l) * CONVDIM + h * 64 + p];
    }
    {
        const float4* src = (const float4*)&g_prev[(size_t)blk * 8192];
        float4* d = (float4*)ps;
        for (int q = tid; q < 2048; q += 256) d[q] = src[q];
    }
    if (tid < 128) {
        acs_s[tid] = g_acs[blk * 128 + tid];
        dt_s[tid]  = g_dt[blk * 128 + tid];
    }
    __syncthreads();

    ull Ci[64];
    {
        const ulonglong2* cp = (const ulonglong2*)&Cs[i * CPAD];
        #pragma unroll
        for (int q = 0; q < 32; q++) { ulonglong2 v = cp[q]; Ci[2 * q] = v.x; Ci[2 * q + 1] = v.y; }
    }
    ull y2[32];
    #pragma unroll
    for (int q = 0; q < 32; q++) y2[q] = 0ull;
    float ai = acs_s[i];

    for (int j = par; j <= i; j += 2) {
        const ulonglong2* Bj = (const ulonglong2*)&Bs[j * 128];
        ull da = 0ull, db = 0ull, dc = 0ull, dd = 0ull;
        #pragma unroll
        for (int q = 0; q < 16; q++) {
            ulonglong2 v0 = Bj[2 * q];
            ulonglong2 v1 = Bj[2 * q + 1];
            da = ffma2(Ci[4 * q + 0], v0.x, da);
            db = ffma2(Ci[4 * q + 1], v0.y, db);
            dc = ffma2(Ci[4 * q + 2], v1.x, dc);
            dd = ffma2(Ci[4 * q + 3], v1.y, dd);
        }
        float2 fa = upk(da), fb = upk(db), fc = upk(dc), fd = upk(dd);
        float d = (fa.x + fa.y) + (fb.x + fb.y) + (fc.x + fc.y) + (fd.x + fd.y);
        float g = expf(ai - acs_s[j]) * dt_s[j] * d;
        ull gp = pk(g);
        const ulonglong2* xj = (const ulonglong2*)&xs[j * 64];
        #pragma unroll
        for (int q = 0; q < 16; q++) {
            ulonglong2 v = xj[q];
            y2[2 * q]     = ffma2(gp, v.x, y2[2 * q]);
            y2[2 * q + 1] = ffma2(gp, v.y, y2[2 * q + 1]);
        }
    }

    float e = expf(ai);
    #pragma unroll 4
    for (int q = 0; q < 64; q++) {
        float2 cf = upk(Ci[q]);
        float cv = par ? cf.y : cf.x;
        ull c0 = pk(e * cv);
        const ulonglong2* p0 = (const ulonglong2*)&ps[(2 * q + par) * 64];
        #pragma unroll
        for (int r = 0; r < 16; r++) {
            ulonglong2 v0 = p0[r];
            y2[2 * r]     = ffma2(c0, v0.x, y2[2 * r]);
            y2[2 * r + 1] = ffma2(c0, v0.y, y2[2 * r + 1]);
        }
    }

    if (par == 0) {
        float dh = D_head[h];
        ull dhp = pk(dh);
        const ulonglong2* xi = (const ulonglong2*)&xs[i * 64];
        #pragma unroll
        for (int q = 0; q < 16; q++) {
            ulonglong2 v = xi[q];
            y2[2 * q]     = ffma2(dhp, v.x, y2[2 * q]);
            y2[2 * q + 1] = ffma2(dhp, v.y, y2[2 * q + 1]);
        }
    }

    __syncthreads();
    if (par == 1) {
        ulonglong2* st = (ulonglong2*)&Bs[i * 64];
        #pragma unroll
        for (int q = 0; q < 16; q++) {
            ulonglong2 v; v.x = y2[2 * q]; v.y = y2[2 * q + 1];
            st[q] = v;
        }
    }
    __syncthreads();
    if (par == 0) {
        const ulonglong2* st = (const ulonglong2*)&Bs[i * 64];
        ull one = pk(1.f);
        #pragma unroll
        for (int q = 0; q < 16; q++) {
            ulonglong2 v = st[q];
            y2[2 * q]     = ffma2(one, v.x, y2[2 * q]);
            y2[2 * q + 1] = ffma2(one, v.y, y2[2 * q + 1]);
        }
        ulonglong2* dst = (ulonglong2*)&g_y[(size_t)(base + i) * DINNER + h * 64];
        #pragma unroll
        for (int q = 0; q < 16; q++) {
            ulonglong2 v; v.x = y2[2 * q]; v.y = y2[2 * q + 1];
            dst[q] = v;
        }
    }
}

// ---------------- gate with silu(z) + RMSNorm * norm_w -> bf16x3 A operand ----------------
__global__ void k_gate(const float* __restrict__ norm_w, __nv_bfloat16* __restrict__ out3) {
    __shared__ float red[64];
    int t = blockIdx.x, tid = threadIdx.x;
    float v[4]; float ss = 0.f, dummy = 0.f;
    #pragma unroll
    for (int k = 0; k < 4; k++) {
        int d = tid + k * 256;
        float yv = g_y[(size_t)t * DINNER + d];
        float zv = g_zx[(size_t)t * DINPROJ + d];
        float sv = yv * (zv / (1.f + expf(-zv)));
        v[k] = sv; ss += sv * sv;
    }
    blockReduce2(ss, dummy, red);
    float sc = rsqrtf(ss * (1.f / 1024.f) + EPSF);
    __nv_bfloat16* row = out3 + (size_t)t * 3 * DINNER;
    #pragma unroll
    for (int k = 0; k < 4; k++) {
        int d = tid + k * 256;
        bf16x3_store_scalar(row, DINNER, d, v[k] * sc * norm_w[d]);
    }
}

// ---------------- out = LayerNorm(a + b) * w + beta (D=512), optional bf16x3 copy ----------------
__global__ void k_addln(const float* __restrict__ a, const float* __restrict__ bsrc,
                        const float* __restrict__ w, const float* __restrict__ beta,
                        float* __restrict__ o, __nv_bfloat16* __restrict__ out3) {
    __shared__ float red[64];
    int t = blockIdx.x, tid = threadIdx.x;
    float v[4]; float s = 0.f, ssq = 0.f;
    #pragma unroll
    for (int k = 0; k < 4; k++) {
        int d = tid + k * 128;
        float x = a[(size_t)t * DMODEL + d] + bsrc[(size_t)t * DMODEL + d];
        v[k] = x; s += x; ssq += x * x;
    }
    blockReduce2(s, ssq, red);
    float mean = s * (1.f / 512.f);
    float var = ssq * (1.f / 512.f) - mean * mean;
    float inv = rsqrtf(var + EPSF);
    #pragma unroll
    for (int k = 0; k < 4; k++) {
        int d = tid + k * 128;
        float r = (v[k] - mean) * inv * w[d] + beta[d];
        o[(size_t)t * DMODEL + d] = r;
        if (out3) bf16x3_store_scalar(out3 + (size_t)t * 3 * DMODEL, DMODEL, d, r);
    }
}

// ---------------- launch ----------------
static inline void splitA(const float* src, __nv_bfloat16* dst, int M, int K) {
    k_split<2><<<(int)(((size_t)M * K / 4) / 256), 256>>>(src, dst, K);
}
static inline void splitW(const float* src, __nv_bfloat16* dst, int M, int K) {
    k_split<1><<<(int)(((size_t)M * K / 4) / 256), 256>>>(src, dst, K);
}

extern "C" void kernel_launch(void* const* d_in, const int* in_sizes, int n_in,
                              void* d_out, int out_size) {
    const float* tgt        = (const float*)d_in[0];
    const float* in_proj_w  = (const float*)d_in[5];
    const float* conv_w     = (const float*)d_in[6];
    const float* conv_b     = (const float*)d_in[7];
    const float* dt_bias    = (const float*)d_in[8];
    const float* A_log      = (const float*)d_in[9];
    const float* D_head     = (const float*)d_in[10];
    const float* norm_w     = (const float*)d_in[11];
    const float* out_proj_w = (const float*)d_in[12];
    const float* n1w = (const float*)d_in[13];
    const float* n1b = (const float*)d_in[14];
    const float* w1  = (const float*)d_in[15];
    const float* b1  = (const float*)d_in[16];
    const float* w2  = (const float*)d_in[17];
    const float* b2  = (const float*)d_in[18];
    const float* n3w = (const float*)d_in[19];
    const float* n3b = (const float*)d_in[20];
    float* out = (float*)d_out;

    float *zx, *mo, *tb, *f2;
    __nv_bfloat16 *A3, *A3b, *W3;
    cudaGetSymbolAddress((void**)&zx,   g_zx);
    cudaGetSymbolAddress((void**)&mo,   g_mo);
    cudaGetSymbolAddress((void**)&tb,   g_t);
    cudaGetSymbolAddress((void**)&f2,   g_f2);
    cudaGetSymbolAddress((void**)&A3,   g_A3);
    cudaGetSymbolAddress((void**)&A3b,  g_A3b);
    cudaGetSymbolAddress((void**)&W3,   g_W3);

    const int smem_states = (16384 + 8192 + 128) * 4;
    const int smem_y = (128 * CPAD + 16384 + 8192 + 8192 + 256) * 4;
    cudaFuncSetAttribute(k_states, cudaFuncAttributeMaxDynamicSharedMemorySize, smem_states);
    cudaFuncSetAttribute(k_y,      cudaFuncAttributeMaxDynamicSharedMemorySize, smem_y);

    // 1. in_proj: zx = tgt @ in_proj_w^T
    splitA(tgt, A3, TOK, DMODEL);
    splitW(in_proj_w, W3, DINPROJ, DMODEL);
    k_gemm_bf16<0, 0><<<dim3((DINPROJ + 127) / 128, TOK / 128), 256>>>(A3, W3, nullptr, zx, DINPROJ, 3 * DMODEL);
    // 2. conv + silu
    k_conv<<<(TOK * CONVDIM) / 256, 256>>>(conv_w, conv_b);
    // 3. dt softplus + cumsum
    k_dtscan<<<NBLK, 128>>>(dt_bias, A_log);
    // 4. chunk end-states
    k_states<<<NBLK, 256, smem_states>>>();
    // 5. chunk scan -> prev
    k_scan<<<BATCH * NHEADS, 256>>>();
    // 6. fused SSD output
    k_y<<<NBLK, 256, smem_y>>>(D_head);
    // 7. gate + rmsnorm -> bf16x3 directly
    k_gate<<<TOK, 256>>>(norm_w, A3);
    // 8. out_proj: mo = gate @ out_proj_w^T
    splitW(out_proj_w, W3, DMODEL, DINNER);
    k_gemm_bf16<0, 0><<<dim3(DMODEL / 128, TOK / 128), 256>>>(A3, W3, nullptr, mo, DMODEL, 3 * DINNER);
    // 9. t = LN(tgt + mo), also emit bf16x3 for FFN GEMM
    k_addln<<<TOK, 128>>>(tgt, mo, n1w, n1b, tb, A3);
    // 10. f1 = gelu(t @ w1^T + b1) -> bf16x3 directly
    splitW(w1, W3, FF, DMODEL);
    k_gemm_bf16<1, 1><<<dim3(FF / 128, TOK / 128), 256>>>(A3, W3, b1, A3b, FF, 3 * DMODEL);
    // 11. f2 = f1 @ w2^T + b2
    splitW(w2, W3, DMODEL, FF);
    k_gemm_bf16<0, 0><<<dim3(DMODEL / 128, TOK / 128), 256>>>(A3b, W3, b2, f2, DMODEL, 3 * FF);
    // 12. out = LN(t + f2)
    k_addln<<<TOK, 128>>>(tb, f2, n3w, n3b, out, nullptr);
}

// round 11
// speedup vs baseline: 2.2167x; 1.0766x over previous
#include <cuda_runtime.h>
#include <cuda_bf16.h>
#include <math.h>
#include <cstdint>

// ---------------- problem constants ----------------
#define BATCH 8
#define SEQ 2048
#define TOK (BATCH*SEQ)          // 16384
#define DMODEL 512
#define DINNER 1024
#define DSTATE 128
#define NHEADS 16
#define HEADDIM 64
#define CONVDIM 1280
#define DINPROJ 2320
#define FF 2048
#define CHUNK 128
#define NCHUNK (SEQ/CHUNK)       // 16
#define NBLK (BATCH*NCHUNK*NHEADS) // 2048
#define EPSF 1e-5f

typedef unsigned long long ull;

// ---------------- packed f32x2 helpers ----------------
__device__ __forceinline__ ull pk(float x) {
    ull r; asm("mov.b64 %0,{%1,%2};" : "=l"(r) : "f"(x), "f"(x)); return r;
}
__device__ __forceinline__ ull ffma2(ull a, ull b, ull c) {
    ull d; asm("fma.rn.f32x2 %0,%1,%2,%3;" : "=l"(d) : "l"(a), "l"(b), "l"(c)); return d;
}
__device__ __forceinline__ float2 upk(ull v) {
    float2 f; asm("mov.b64 {%0,%1},%2;" : "=f"(f.x), "=f"(f.y) : "l"(v)); return f;
}

#define MMA_BF16(cc, aa, b0, b1) \
    asm volatile("mma.sync.aligned.m16n8k16.row.col.f32.bf16.bf16.f32 " \
        "{%0,%1,%2,%3},{%4,%5,%6,%7},{%8,%9},{%0,%1,%2,%3};" \
        : "+f"(cc[0]), "+f"(cc[1]), "+f"(cc[2]), "+f"(cc[3]) \
        : "r"(aa[0]), "r"(aa[1]), "r"(aa[2]), "r"(aa[3]), "r"(b0), "r"(b1))

#define LDSM_X4(r, addr) \
    asm volatile("ldmatrix.sync.aligned.m8n8.x4.shared.b16 {%0,%1,%2,%3},[%4];" \
        : "=r"((r)[0]), "=r"((r)[1]), "=r"((r)[2]), "=r"((r)[3]) : "r"(addr))

#define CP_ASYNC16(dst, src) \
    asm volatile("cp.async.cg.shared.global [%0], [%1], 16;" :: "r"(dst), "l"(src))
#define CP_COMMIT() asm volatile("cp.async.commit_group;" ::: "memory")
#define CP_WAIT2()  asm volatile("cp.async.wait_group 2;" ::: "memory")
#define CP_WAIT0()  asm volatile("cp.async.wait_group 0;" ::: "memory")

// ---------------- scratch ----------------
__device__ __align__(16) float g_zx[TOK*DINPROJ];
__device__ __align__(16) float g_xbc[TOK*CONVDIM];
__device__ __align__(16) float g_dt[NBLK*CHUNK];
__device__ __align__(16) float g_acs[NBLK*CHUNK];
__device__ __align__(16) float g_states[(size_t)NBLK*DSTATE*HEADDIM];
__device__ __align__(16) float g_prev[(size_t)NBLK*DSTATE*HEADDIM];
__device__ __align__(16) float g_y[(size_t)TOK*DINNER];
__device__ __align__(16) float g_mo[(size_t)TOK*DMODEL];
__device__ __align__(16) float g_t[(size_t)TOK*DMODEL];
__device__ __align__(16) float g_f2[(size_t)TOK*DMODEL];
// bf16x3 expanded operands
__device__ __align__(16) __nv_bfloat16 g_A3[(size_t)TOK*3*DINNER];
__device__ __align__(16) __nv_bfloat16 g_A3b[(size_t)TOK*3*FF];
__device__ __align__(16) __nv_bfloat16 g_W3[DINPROJ*3*DMODEL];

// ---------------- helpers ----------------
__device__ __forceinline__ void blockReduce2(float& a, float& b, float* sh) {
    int lane = threadIdx.x & 31, w = threadIdx.x >> 5;
    #pragma unroll
    for (int o = 16; o; o >>= 1) {
        a += __shfl_xor_sync(0xffffffffu, a, o);
        b += __shfl_xor_sync(0xffffffffu, b, o);
    }
    if (lane == 0) { sh[w] = a; sh[32 + w] = b; }
    __syncthreads();
    int nw = blockDim.x >> 5;
    if (w == 0) {
        a = (lane < nw) ? sh[lane] : 0.f;
        b = (lane < nw) ? sh[32 + lane] : 0.f;
        #pragma unroll
        for (int o = 16; o; o >>= 1) {
            a += __shfl_xor_sync(0xffffffffu, a, o);
            b += __shfl_xor_sync(0xffffffffu, b, o);
        }
        if (lane == 0) { sh[0] = a; sh[32] = b; }
    }
    __syncthreads();
    a = sh[0]; b = sh[32];
}

__device__ __forceinline__ void bf16x3_store_scalar(__nv_bfloat16* row, int K, int d, float s) {
    __nv_bfloat16 hi = __float2bfloat16_rn(s);
    __nv_bfloat16 lo = __float2bfloat16_rn(s - __bfloat162float(hi));
    row[d] = hi; row[K + d] = hi; row[2 * K + d] = lo;
}

// ---------------- bf16x3 split: src[M,K] fp32 -> dst[M,3K] bf16 ----------------
template<int LOQ>
__global__ void k_split(const float* __restrict__ src, __nv_bfloat16* __restrict__ dst, int K) {
    size_t i = (size_t)blockIdx.x * 256 + threadIdx.x;
    int K4 = K >> 2;
    size_t row = i / K4;
    int c4 = (int)(i % K4);
    float4 v = ((const float4*)src)[i];
    __nv_bfloat162 h0, h1, l0, l1;
    h0.x = __float2bfloat16_rn(v.x); h0.y = __float2bfloat16_rn(v.y);
    h1.x = __float2bfloat16_rn(v.z); h1.y = __float2bfloat16_rn(v.w);
    l0.x = __float2bfloat16_rn(v.x - __bfloat162float(h0.x));
    l0.y = __float2bfloat16_rn(v.y - __bfloat162float(h0.y));
    l1.x = __float2bfloat16_rn(v.z - __bfloat162float(h1.x));
    l1.y = __float2bfloat16_rn(v.w - __bfloat162float(h1.y));
    __nv_bfloat162* d = (__nv_bfloat162*)(dst + row * 3 * K);
    int c2 = c4 * 2;
    int K2 = K >> 1;
    d[c2] = h0; d[c2 + 1] = h1;
    d[K2 + c2]     = (LOQ == 1) ? l0 : h0;
    d[K2 + c2 + 1] = (LOQ == 1) ? l1 : h1;
    d[2 * K2 + c2]     = (LOQ == 2) ? l0 : h0;
    d[2 * K2 + c2 + 1] = (LOQ == 2) ? l1 : h1;
}

// ---------------- bf16 tensor-core GEMM, 4-stage cp.async, single-sync mainloop ----------------
// 128x128 tile, 256 threads (8 warps 4x2, warp tile 32x64), BK=32.
#define SPITCH 40
#define NSTG 4
template<int ACT, int OUT3>
__global__ void __launch_bounds__(256) k_gemm_bf16(const __nv_bfloat16* __restrict__ A,
                                                   const __nv_bfloat16* __restrict__ W,
                                                   const float* __restrict__ bias,
                                                   void* __restrict__ Cout,
                                                   int N, int K3) {
    __shared__ __align__(16) __nv_bfloat16 As[NSTG][128][SPITCH];
    __shared__ __align__(16) __nv_bfloat16 Ws[NSTG][128][SPITCH];
    int tid = threadIdx.x;
    int bm = blockIdx.y * 128, bn = blockIdx.x * 128;
    int lr = tid >> 1, lc = (tid & 1) * 16;
    int lane = tid & 31, wid = tid >> 5;
    int wm = (wid & 3) * 32, wn = (wid >> 2) * 64;
    int g = lane >> 2, t4 = lane & 3;

    float c[2][8][4];
    #pragma unroll
    for (int mi = 0; mi < 2; mi++)
        #pragma unroll
        for (int ni = 0; ni < 8; ni++)
            #pragma unroll
            for (int q = 0; q < 4; q++) c[mi][ni][q] = 0.f;

    const __nv_bfloat16* Aptr = A + (size_t)(bm + lr) * K3 + lc;
    int wr = bn + lr; if (wr >= N) wr = N - 1;   // clamp; garbage cols masked in epilogue
    const __nv_bfloat16* Wptr = W + (size_t)wr * K3 + lc;

    uint32_t sbA = (uint32_t)__cvta_generic_to_shared(&As[0][0][0]);
    uint32_t sbW = (uint32_t)__cvta_generic_to_shared(&Ws[0][0][0]);
    const uint32_t bufStride = 128 * SPITCH * 2;
    uint32_t dOff = (uint32_t)((lr * SPITCH + lc) * 2);

    int l7 = lane & 7;
    int aRow = wm + ((lane >> 3) & 1) * 8 + l7;
    int aCol = (lane >> 4) * 8;
    int bRow = wn + (lane >> 4) * 8 + l7;
    int bCol = ((lane >> 3) & 1) * 8;

    int KT = K3 / 32;

    // prologue: issue stages 0..2
    #pragma unroll
    for (int s = 0; s < NSTG - 1; s++) {
        if (s < KT) {
            const __nv_bfloat16* ap = Aptr + s * 32;
            const __nv_bfloat16* wp = Wptr + s * 32;
            uint32_t da = sbA + s * bufStride + dOff;
            uint32_t dw = sbW + s * bufStride + dOff;
            CP_ASYNC16(da, ap); CP_ASYNC16(da + 16, ap + 8);
            CP_ASYNC16(dw, wp); CP_ASYNC16(dw + 16, wp + 8);
        }
        CP_COMMIT();
    }

    for (int kt = 0; kt < KT; kt++) {
        CP_WAIT2();            // stage kt resident (<=2 groups pending)
        __syncthreads();       // visibility + buffer-reuse guard

        int cur = kt & (NSTG - 1);
        uint32_t aBase = sbA + cur * bufStride;
        uint32_t wBase = sbW + cur * bufStride;
        #pragma unroll
        for (int kk = 0; kk < 32; kk += 16) {
            uint32_t af[2][4], bf[4][4];
            #pragma unroll
            for (int mi = 0; mi < 2; mi++) {
                uint32_t addr = aBase + (uint32_t)(((aRow + mi * 16) * SPITCH + aCol + kk) * 2);
                LDSM_X4(af[mi], addr);
            }
            #pragma unroll
            for (int q = 0; q < 4; q++) {
                uint32_t addr = wBase + (uint32_t)(((bRow + q * 16) * SPITCH + bCol + kk) * 2);
                LDSM_X4(bf[q], addr);
            }
            #pragma unroll
            for (int q = 0; q < 4; q++) {
                MMA_BF16(c[0][2 * q],     af[0], bf[q][0], bf[q][1]);
                MMA_BF16(c[1][2 * q],     af[1], bf[q][0], bf[q][1]);
                MMA_BF16(c[0][2 * q + 1], af[0], bf[q][2], bf[q][3]);
                MMA_BF16(c[1][2 * q + 1], af[1], bf[q][2], bf[q][3]);
            }
        }

        // issue stage kt+3 into buffer (kt+3)&3 == (kt-1)&3 — safe: all threads
        // passed the sync above, so nobody is still reading that buffer.
        {
            int s = kt + NSTG - 1;
            if (s < KT) {
                const __nv_bfloat16* ap = Aptr + s * 32;
                const __nv_bfloat16* wp = Wptr + s * 32;
                uint32_t da = sbA + (s & (NSTG - 1)) * bufStride + dOff;
                uint32_t dw = sbW + (s & (NSTG - 1)) * bufStride + dOff;
                CP_ASYNC16(da, ap); CP_ASYNC16(da + 16, ap + 8);
                CP_ASYNC16(dw, wp); CP_ASYNC16(dw + 16, wp + 8);
            }
            CP_COMMIT();
        }
    }
    CP_WAIT0();

    // epilogue (float2 stores)
    #pragma unroll
    for (int mi = 0; mi < 2; mi++) {
        int r0 = bm + wm + mi * 16 + g;
        #pragma unroll
        for (int ni = 0; ni < 8; ni++) {
            int col = bn + wn + ni * 8 + 2 * t4;
            #pragma unroll
            for (int half = 0; half < 2; half++) {
                int r = r0 + half * 8;
                float v0 = c[mi][ni][half * 2 + 0];
                float v1 = c[mi][ni][half * 2 + 1];
                if (bias) { v0 += bias[col]; v1 += bias[col + 1]; }
                if (ACT == 1) {
                    v0 = 0.5f * v0 * (1.f + erff(v0 * 0.70710678118654752f));
                    v1 = 0.5f * v1 * (1.f + erff(v1 * 0.70710678118654752f));
                }
                if (OUT3) {
                    __nv_bfloat16* O = (__nv_bfloat16*)Cout;
                    __nv_bfloat162 hi, lo;
                    hi.x = __float2bfloat16_rn(v0); hi.y = __float2bfloat16_rn(v1);
                    lo.x = __float2bfloat16_rn(v0 - __bfloat162float(hi.x));
                    lo.y = __float2bfloat16_rn(v1 - __bfloat162float(hi.y));
                    size_t base = (size_t)r * 3 * N + col;
                    *(__nv_bfloat162*)&O[base]         = hi;
                    *(__nv_bfloat162*)&O[base + N]     = hi;
                    *(__nv_bfloat162*)&O[base + 2 * N] = lo;
                } else {
                    float* Cf = (float*)Cout;
                    if (col + 1 < N) {
                        float2 v; v.x = v0; v.y = v1;
                        *(float2*)&Cf[(size_t)r * N + col] = v;
                    } else if (col < N) {
                        Cf[(size_t)r * N + col] = v0;
                    }
                }
            }
        }
    }
}

// ---------------- causal depthwise conv1d + silu ----------------
__global__ void k_conv(const float* __restrict__ conv_w, const float* __restrict__ conv_b) {
    int idx = blockIdx.x * 256 + threadIdx.x;
    int ch = idx % CONVDIM;
    int s  = (idx / CONVDIM) % SEQ;
    int b  = idx / (CONVDIM * SEQ);
    float acc = conv_b[ch];
    #pragma unroll
    for (int k = 0; k < 4; k++) {
        int sp = s + k - 3;
        if (sp >= 0)
            acc += g_zx[(size_t)(b * SEQ + sp) * DINPROJ + DINNER + ch] * conv_w[ch * 4 + k];
    }
    acc = acc / (1.f + expf(-acc));
    g_xbc[idx] = acc;
}

// ---------------- dt softplus + per-chunk cumulative log-decay ----------------
__global__ void k_dtscan(const float* __restrict__ dt_bias, const float* __restrict__ A_log) {
    __shared__ float s[128];
    int blk = blockIdx.x, l = threadIdx.x;
    int h = blk & 15, c = (blk >> 4) & 15, b = blk >> 8;
    int tok = b * SEQ + c * CHUNK + l;
    float raw = g_zx[(size_t)tok * DINPROJ + 2304 + h] + dt_bias[h];
    float dtv = (raw > 20.f) ? raw : log1pf(expf(raw));
    float A = -expf(A_log[h]);
    g_dt[blk * 128 + l] = dtv;
    s[l] = dtv * A;
    __syncthreads();
    #pragma unroll
    for (int off = 1; off < 128; off <<= 1) {
        float t = (l >= off) ? s[l - off] : 0.f;
        __syncthreads();
        s[l] += t;
        __syncthreads();
    }
    g_acs[blk * 128 + l] = s[l];
}

// ---------------- per-chunk end states: 256 threads, (n, p-half) per thread ----------------
__global__ void __launch_bounds__(256) k_states() {
    extern __shared__ __align__(16) float sh[];
    float* Bs = sh;              // 128*128
    float* xs = Bs + 16384;      // 128*64
    float* ws = xs + 8192;       // 128
    int blk = blockIdx.x, tid = threadIdx.x;
    int n = tid & 127, half = tid >> 7;
    int h = blk & 15, c = (blk >> 4) & 15, b = blk >> 8;
    int base = b * SEQ + c * CHUNK;
    for (int q = tid; q < 16384; q += 256) {
        int l = q >> 7, nn = q & 127;
        Bs[q] = g_xbc[(size_t)(base + l) * CONVDIM + DINNER + nn];
    }
    for (int q = tid; q < 8192; q += 256) {
        int l = q >> 6, p = q & 63;
        xs[q] = g_xbc[(size_t)(base + l) * CONVDIM + h * 64 + p];
    }
    if (tid < 128) {
        float acsL = g_acs[blk * 128 + 127];
        ws[tid] = expf(acsL - g_acs[blk * 128 + tid]) * g_dt[blk * 128 + tid];
    }
    __syncthreads();
    ull acc2[16];
    #pragma unroll
    for (int q = 0; q < 16; q++) acc2[q] = 0ull;
    for (int l = 0; l < 128; l++) {
        float bw = Bs[l * 128 + n] * ws[l];
        ull bwp = pk(bw);
        const ulonglong2* xl = (const ulonglong2*)&xs[l * 64 + half * 32];
        #pragma unroll
        for (int q = 0; q < 8; q++) {
            ulonglong2 v = xl[q];
            acc2[2 * q]     = ffma2(bwp, v.x, acc2[2 * q]);
            acc2[2 * q + 1] = ffma2(bwp, v.y, acc2[2 * q + 1]);
        }
    }
    ulonglong2* dst = (ulonglong2*)&g_states[(size_t)blk * 8192 + n * 64 + half * 32];
    #pragma unroll
    for (int q = 0; q < 8; q++) {
        ulonglong2 v; v.x = acc2[2 * q]; v.y = acc2[2 * q + 1];
        dst[q] = v;
    }
}

// ---------------- sequential chunk scan (parallelized over e-chunks) ----------------
__global__ void k_scan() {
    int bx = blockIdx.x;              // 1024 blocks: (b, h, e8)
    int e8 = bx & 7;
    int bh = bx >> 3;
    int b = bh >> 4, h = bh & 15;
    int e = e8 * 1024 + threadIdx.x;  // 256 threads, 4 elems each
    for (int k = 0; k < 4; k++, e += 256) {
        float acc = 0.f;
        #pragma unroll
        for (int c = 0; c < NCHUNK; c++) {
            int blk = ((b * NCHUNK + c) << 4) + h;
            g_prev[(size_t)blk * 8192 + e] = acc;
            float cd = expf(g_acs[blk * 128 + 127]);
            acc = cd * acc + g_states[(size_t)blk * 8192 + e];
        }
    }
}

// ---------------- fused SSD output: 256 threads, j-parity split per row ----------------
#define CPAD 132
__global__ void __launch_bounds__(256, 1) k_y(const float* __restrict__ D_head) {
    extern __shared__ __align__(16) float sh[];
    float* Cs   = sh;                 // 128*CPAD
    float* Bs   = Cs + 128 * CPAD;    // 128*128 (reused as staging at the end)
    float* xs   = Bs + 16384;         // 128*64
    float* ps   = xs + 8192;          // 128*64
    float* acs_s = ps + 8192;         // 128
    float* dt_s  = acs_s + 128;       // 128
    int blk = blockIdx.x, tid = threadIdx.x;
    int i = tid & 127, par = tid >> 7;
    int h = blk & 15, c = (blk >> 4) & 15, b = blk >> 8;
    int base = b * SEQ + c * CHUNK;

    for (int q = tid; q < 16384; q += 256) {
        int l = q >> 7, n = q & 127;
        const float* row = &g_xbc[(size_t)(base + l) * CONVDIM];
        Cs[l * CPAD + n] = row[DINNER + DSTATE + n];
        Bs[q]            = row[DINNER + n];
    }
    for (int q = tid; q < 8192; q += 256) {
        int l = q >> 6, p = q & 63;
        xs[q] = g_xbc[(size_t)(base + l) * CONVDIM + h * 64 + p];
    }
    {
        const float4* src = (const float4*)&g_prev[(size_t)blk * 8192];
        float4* d = (float4*)ps;
        for (int q = tid; q < 2048; q += 256) d[q] = src[q];
    }
    if (tid < 128) {
        acs_s[tid] = g_acs[blk * 128 + tid];
        dt_s[tid]  = g_dt[blk * 128 + tid];
    }
    __syncthreads();

    ull Ci[64];
    {
        const ulonglong2* cp = (const ulonglong2*)&Cs[i * CPAD];
        #pragma unroll
        for (int q = 0; q < 32; q++) { ulonglong2 v = cp[q]; Ci[2 * q] = v.x; Ci[2 * q + 1] = v.y; }
    }
    ull y2[32];
    #pragma unroll
    for (int q = 0; q < 32; q++) y2[q] = 0ull;
    float ai = acs_s[i];

    for (int j = par; j <= i; j += 2) {
        const ulonglong2* Bj = (const ulonglong2*)&Bs[j * 128];
        ull da = 0ull, db = 0ull, dc = 0ull, dd = 0ull;
        #pragma unroll
        for (int q = 0; q < 16; q++) {
            ulonglong2 v0 = Bj[2 * q];
            ulonglong2 v1 = Bj[2 * q + 1];
            da = ffma2(Ci[4 * q + 0], v0.x, da);
            db = ffma2(Ci[4 * q + 1], v0.y, db);
            dc = ffma2(Ci[4 * q + 2], v1.x, dc);
            dd = ffma2(Ci[4 * q + 3], v1.y, dd);
        }
        float2 fa = upk(da), fb = upk(db), fc = upk(dc), fd = upk(dd);
        float d = (fa.x + fa.y) + (fb.x + fb.y) + (fc.x + fc.y) + (fd.x + fd.y);
        float g = expf(ai - acs_s[j]) * dt_s[j] * d;
        ull gp = pk(g);
        const ulonglong2* xj = (const ulonglong2*)&xs[j * 64];
        #pragma unroll
        for (int q = 0; q < 16; q++) {
            ulonglong2 v = xj[q];
            y2[2 * q]     = ffma2(gp, v.x, y2[2 * q]);
            y2[2 * q + 1] = ffma2(gp, v.y, y2[2 * q + 1]);
        }
    }

    float e = expf(ai);
    #pragma unroll 4
    for (int q = 0; q < 64; q++) {
        float2 cf = upk(Ci[q]);
        float cv = par ? cf.y : cf.x;
        ull c0 = pk(e * cv);
        const ulonglong2* p0 = (const ulonglong2*)&ps[(2 * q + par) * 64];
        #pragma unroll
        for (int r = 0; r < 16; r++) {
            ulonglong2 v0 = p0[r];
            y2[2 * r]     = ffma2(c0, v0.x, y2[2 * r]);
            y2[2 * r + 1] = ffma2(c0, v0.y, y2[2 * r + 1]);
        }
    }

    if (par == 0) {
        float dh = D_head[h];
        ull dhp = pk(dh);
        const ulonglong2* xi = (const ulonglong2*)&xs[i * 64];
        #pragma unroll
        for (int q = 0; q < 16; q++) {
            ulonglong2 v = xi[q];
            y2[2 * q]     = ffma2(dhp, v.x, y2[2 * q]);
            y2[2 * q + 1] = ffma2(dhp, v.y, y2[2 * q + 1]);
        }
    }

    __syncthreads();
    if (par == 1) {
        ulonglong2* st = (ulonglong2*)&Bs[i * 64];
        #pragma unroll
        for (int q = 0; q < 16; q++) {
            ulonglong2 v; v.x = y2[2 * q]; v.y = y2[2 * q + 1];
            st[q] = v;
        }
    }
    __syncthreads();
    if (par == 0) {
        const ulonglong2* st = (const ulonglong2*)&Bs[i * 64];
        ull one = pk(1.f);
        #pragma unroll
        for (int q = 0; q < 16; q++) {
            ulonglong2 v = st[q];
            y2[2 * q]     = ffma2(one, v.x, y2[2 * q]);
            y2[2 * q + 1] = ffma2(one, v.y, y2[2 * q + 1]);
        }
        ulonglong2* dst = (ulonglong2*)&g_y[(size_t)(base + i) * DINNER + h * 64];
        #pragma unroll
        for (int q = 0; q < 16; q++) {
            ulonglong2 v; v.x = y2[2 * q]; v.y = y2[2 * q + 1];
            dst[q] = v;
        }
    }
}

// ---------------- gate with silu(z) + RMSNorm * norm_w -> bf16x3 A operand ----------------
__global__ void k_gate(const float* __restrict__ norm_w, __nv_bfloat16* __restrict__ out3) {
    __shared__ float red[64];
    int t = blockIdx.x, tid = threadIdx.x;
    float v[4]; float ss = 0.f, dummy = 0.f;
    #pragma unroll
    for (int k = 0; k < 4; k++) {
        int d = tid + k * 256;
        float yv = g_y[(size_t)t * DINNER + d];
        float zv = g_zx[(size_t)t * DINPROJ + d];
        float sv = yv * (zv / (1.f + expf(-zv)));
        v[k] = sv; ss += sv * sv;
    }
    blockReduce2(ss, dummy, red);
    float sc = rsqrtf(ss * (1.f / 1024.f) + EPSF);
    __nv_bfloat16* row = out3 + (size_t)t * 3 * DINNER;
    #pragma unroll
    for (int k = 0; k < 4; k++) {
        int d = tid + k * 256;
        bf16x3_store_scalar(row, DINNER, d, v[k] * sc * norm_w[d]);
    }
}

// ---------------- out = LayerNorm(a + b) * w + beta (D=512), optional bf16x3 copy ----------------
__global__ void k_addln(const float* __restrict__ a, const float* __restrict__ bsrc,
                        const float* __restrict__ w, const float* __restrict__ beta,
                        float* __restrict__ o, __nv_bfloat16* __restrict__ out3) {
    __shared__ float red[64];
    int t = blockIdx.x, tid = threadIdx.x;
    float v[4]; float s = 0.f, ssq = 0.f;
    #pragma unroll
    for (int k = 0; k < 4; k++) {
        int d = tid + k * 128;
        float x = a[(size_t)t * DMODEL + d] + bsrc[(size_t)t * DMODEL + d];
        v[k] = x; s += x; ssq += x * x;
    }
    blockReduce2(s, ssq, red);
    float mean = s * (1.f / 512.f);
    float var = ssq * (1.f / 512.f) - mean * mean;
    float inv = rsqrtf(var + EPSF);
    #pragma unroll
    for (int k = 0; k < 4; k++) {
        int d = tid + k * 128;
        float r = (v[k] - mean) * inv * w[d] + beta[d];
        o[(size_t)t * DMODEL + d] = r;
        if (out3) bf16x3_store_scalar(out3 + (size_t)t * 3 * DMODEL, DMODEL, d, r);
    }
}

// ---------------- launch ----------------
static inline void splitA(const float* src, __nv_bfloat16* dst, int M, int K) {
    k_split<2><<<(int)(((size_t)M * K / 4) / 256), 256>>>(src, dst, K);
}
static inline void splitW(const float* src, __nv_bfloat16* dst, int M, int K) {
    k_split<1><<<(int)(((size_t)M * K / 4) / 256), 256>>>(src, dst, K);
}

extern "C" void kernel_launch(void* const* d_in, const int* in_sizes, int n_in,
                              void* d_out, int out_size) {
    const float* tgt        = (const float*)d_in[0];
    const float* in_proj_w  = (const float*)d_in[5];
    const float* conv_w     = (const float*)d_in[6];
    const float* conv_b     = (const float*)d_in[7];
    const float* dt_bias    = (const float*)d_in[8];
    const float* A_log      = (const float*)d_in[9];
    const float* D_head     = (const float*)d_in[10];
    const float* norm_w     = (const float*)d_in[11];
    const float* out_proj_w = (const float*)d_in[12];
    const float* n1w = (const float*)d_in[13];
    const float* n1b = (const float*)d_in[14];
    const float* w1  = (const float*)d_in[15];
    const float* b1  = (const float*)d_in[16];
    const float* w2  = (const float*)d_in[17];
    const float* b2  = (const float*)d_in[18];
    const float* n3w = (const float*)d_in[19];
    const float* n3b = (const float*)d_in[20];
    float* out = (float*)d_out;

    float *zx, *mo, *tb, *f2;
    __nv_bfloat16 *A3, *A3b, *W3;
    cudaGetSymbolAddress((void**)&zx,   g_zx);
    cudaGetSymbolAddress((void**)&mo,   g_mo);
    cudaGetSymbolAddress((void**)&tb,   g_t);
    cudaGetSymbolAddress((void**)&f2,   g_f2);
    cudaGetSymbolAddress((void**)&A3,   g_A3);
    cudaGetSymbolAddress((void**)&A3b,  g_A3b);
    cudaGetSymbolAddress((void**)&W3,   g_W3);

    const int smem_states = (16384 + 8192 + 128) * 4;
    const int smem_y = (128 * CPAD + 16384 + 8192 + 8192 + 256) * 4;
    cudaFuncSetAttribute(k_states, cudaFuncAttributeMaxDynamicSharedMemorySize, smem_states);
    cudaFuncSetAttribute(k_y,      cudaFuncAttributeMaxDynamicSharedMemorySize, smem_y);

    // 1. in_proj: zx = tgt @ in_proj_w^T
    splitA(tgt, A3, TOK, DMODEL);
    splitW(in_proj_w, W3, DINPROJ, DMODEL);
    k_gemm_bf16<0, 0><<<dim3((DINPROJ + 127) / 128, TOK / 128), 256>>>(A3, W3, nullptr, zx, DINPROJ, 3 * DMODEL);
    // 2. conv + silu
    k_conv<<<(TOK * CONVDIM) / 256, 256>>>(conv_w, conv_b);
    // 3. dt softplus + cumsum
    k_dtscan<<<NBLK, 128>>>(dt_bias, A_log);
    // 4. chunk end-states
    k_states<<<NBLK, 256, smem_states>>>();
    // 5. chunk scan -> prev
    k_scan<<<BATCH * NHEADS * 8, 256>>>();
    // 6. fused SSD output
    k_y<<<NBLK, 256, smem_y>>>(D_head);
    // 7. gate + rmsnorm -> bf16x3 directly
    k_gate<<<TOK, 256>>>(norm_w, A3);
    // 8. out_proj: mo = gate @ out_proj_w^T
    splitW(out_proj_w, W3, DMODEL, DINNER);
    k_gemm_bf16<0, 0><<<dim3(DMODEL / 128, TOK / 128), 256>>>(A3, W3, nullptr, mo, DMODEL, 3 * DINNER);
    // 9. t = LN(tgt + mo), also emit bf16x3 for FFN GEMM
    k_addln<<<TOK, 128>>>(tgt, mo, n1w, n1b, tb, A3);
    // 10. f1 = gelu(t @ w1^T + b1) -> bf16x3 directly
    splitW(w1, W3, FF, DMODEL);
    k_gemm_bf16<1, 1><<<dim3(FF / 128, TOK / 128), 256>>>(A3, W3, b1, A3b, FF, 3 * DMODEL);
    // 11. f2 = f1 @ w2^T + b2
    splitW(w2, W3, DMODEL, FF);
    k_gemm_bf16<0, 0><<<dim3(DMODEL / 128, TOK / 128), 256>>>(A3b, W3, b2, f2, DMODEL, 3 * FF);
    // 12. out = LN(t + f2)
    k_addln<<<TOK, 128>>>(tb, f2, n3w, n3b, out, nullptr);
}

// round 12
// speedup vs baseline: 2.2816x; 1.0293x over previous
#include <cuda_runtime.h>
#include <cuda_bf16.h>
#include <math.h>
#include <cstdint>

// ---------------- problem constants ----------------
#define BATCH 8
#define SEQ 2048
#define TOK (BATCH*SEQ)          // 16384
#define DMODEL 512
#define DINNER 1024
#define DSTATE 128
#define NHEADS 16
#define HEADDIM 64
#define CONVDIM 1280
#define DINPROJ 2320
#define FF 2048
#define CHUNK 128
#define NCHUNK (SEQ/CHUNK)       // 16
#define NBLK (BATCH*NCHUNK*NHEADS) // 2048
#define NGC (BATCH*NCHUNK)       // 128
#define EPSF 1e-5f

typedef unsigned long long ull;

// ---------------- packed f32x2 helpers ----------------
__device__ __forceinline__ ull pk(float x) {
    ull r; asm("mov.b64 %0,{%1,%2};" : "=l"(r) : "f"(x), "f"(x)); return r;
}
__device__ __forceinline__ ull ffma2(ull a, ull b, ull c) {
    ull d; asm("fma.rn.f32x2 %0,%1,%2,%3;" : "=l"(d) : "l"(a), "l"(b), "l"(c)); return d;
}
__device__ __forceinline__ float2 upk(ull v) {
    float2 f; asm("mov.b64 {%0,%1},%2;" : "=f"(f.x), "=f"(f.y) : "l"(v)); return f;
}

#define MMA_BF16(cc, aa, b0, b1) \
    asm volatile("mma.sync.aligned.m16n8k16.row.col.f32.bf16.bf16.f32 " \
        "{%0,%1,%2,%3},{%4,%5,%6,%7},{%8,%9},{%0,%1,%2,%3};" \
        : "+f"(cc[0]), "+f"(cc[1]), "+f"(cc[2]), "+f"(cc[3]) \
        : "r"(aa[0]), "r"(aa[1]), "r"(aa[2]), "r"(aa[3]), "r"(b0), "r"(b1))

#define LDSM_X4(r, addr) \
    asm volatile("ldmatrix.sync.aligned.m8n8.x4.shared.b16 {%0,%1,%2,%3},[%4];" \
        : "=r"((r)[0]), "=r"((r)[1]), "=r"((r)[2]), "=r"((r)[3]) : "r"(addr))

#define CP_ASYNC16(dst, src) \
    asm volatile("cp.async.cg.shared.global [%0], [%1], 16;" :: "r"(dst), "l"(src))
#define CP_COMMIT() asm volatile("cp.async.commit_group;" ::: "memory")
#define CP_WAIT2()  asm volatile("cp.async.wait_group 2;" ::: "memory")
#define CP_WAIT0()  asm volatile("cp.async.wait_group 0;" ::: "memory")

// ---------------- scratch ----------------
__device__ __align__(16) float g_zx[TOK*DINPROJ];
__device__ __align__(16) float g_xbc[TOK*CONVDIM];
__device__ __align__(16) float g_dt[NBLK*CHUNK];
__device__ __align__(16) float g_acs[NBLK*CHUNK];
__device__ __align__(16) float g_states[(size_t)NBLK*DSTATE*HEADDIM];
__device__ __align__(16) float g_prev[(size_t)NBLK*DSTATE*HEADDIM];
__device__ __align__(16) float g_y[(size_t)TOK*DINNER];
__device__ __align__(16) float g_mo[(size_t)TOK*DMODEL];
__device__ __align__(16) float g_t[(size_t)TOK*DMODEL];
__device__ __align__(16) float g_f2[(size_t)TOK*DMODEL];
__device__ __align__(16) float g_G[(size_t)NGC*CHUNK*CHUNK];   // 8 MB score matrices
// bf16x3 expanded operands
__device__ __align__(16) __nv_bfloat16 g_A3[(size_t)TOK*3*DINNER];
__device__ __align__(16) __nv_bfloat16 g_A3b[(size_t)TOK*3*FF];
__device__ __align__(16) __nv_bfloat16 g_W3[DINPROJ*3*DMODEL];

// ---------------- helpers ----------------
__device__ __forceinline__ void blockReduce2(float& a, float& b, float* sh) {
    int lane = threadIdx.x & 31, w = threadIdx.x >> 5;
    #pragma unroll
    for (int o = 16; o; o >>= 1) {
        a += __shfl_xor_sync(0xffffffffu, a, o);
        b += __shfl_xor_sync(0xffffffffu, b, o);
    }
    if (lane == 0) { sh[w] = a; sh[32 + w] = b; }
    __syncthreads();
    int nw = blockDim.x >> 5;
    if (w == 0) {
        a = (lane < nw) ? sh[lane] : 0.f;
        b = (lane < nw) ? sh[32 + lane] : 0.f;
        #pragma unroll
        for (int o = 16; o; o >>= 1) {
            a += __shfl_xor_sync(0xffffffffu, a, o);
            b += __shfl_xor_sync(0xffffffffu, b, o);
        }
        if (lane == 0) { sh[0] = a; sh[32] = b; }
    }
    __syncthreads();
    a = sh[0]; b = sh[32];
}

__device__ __forceinline__ void bf16x3_store_scalar(__nv_bfloat16* row, int K, int d, float s) {
    __nv_bfloat16 hi = __float2bfloat16_rn(s);
    __nv_bfloat16 lo = __float2bfloat16_rn(s - __bfloat162float(hi));
    row[d] = hi; row[K + d] = hi; row[2 * K + d] = lo;
}

// ---------------- bf16x3 split: src[M,K] fp32 -> dst[M,3K] bf16 ----------------
template<int LOQ>
__global__ void k_split(const float* __restrict__ src, __nv_bfloat16* __restrict__ dst, int K) {
    size_t i = (size_t)blockIdx.x * 256 + threadIdx.x;
    int K4 = K >> 2;
    size_t row = i / K4;
    int c4 = (int)(i % K4);
    float4 v = ((const float4*)src)[i];
    __nv_bfloat162 h0, h1, l0, l1;
    h0.x = __float2bfloat16_rn(v.x); h0.y = __float2bfloat16_rn(v.y);
    h1.x = __float2bfloat16_rn(v.z); h1.y = __float2bfloat16_rn(v.w);
    l0.x = __float2bfloat16_rn(v.x - __bfloat162float(h0.x));
    l0.y = __float2bfloat16_rn(v.y - __bfloat162float(h0.y));
    l1.x = __float2bfloat16_rn(v.z - __bfloat162float(h1.x));
    l1.y = __float2bfloat16_rn(v.w - __bfloat162float(h1.y));
    __nv_bfloat162* d = (__nv_bfloat162*)(dst + row * 3 * K);
    int c2 = c4 * 2;
    int K2 = K >> 1;
    d[c2] = h0; d[c2 + 1] = h1;
    d[K2 + c2]     = (LOQ == 1) ? l0 : h0;
    d[K2 + c2 + 1] = (LOQ == 1) ? l1 : h1;
    d[2 * K2 + c2]     = (LOQ == 2) ? l0 : h0;
    d[2 * K2 + c2 + 1] = (LOQ == 2) ? l1 : h1;
}

// ---------------- bf16 tensor-core GEMM, 4-stage cp.async, single-sync mainloop ----------------
#define SPITCH 40
#define NSTG 4
template<int ACT, int OUT3>
__global__ void __launch_bounds__(256) k_gemm_bf16(const __nv_bfloat16* __restrict__ A,
                                                   const __nv_bfloat16* __restrict__ W,
                                                   const float* __restrict__ bias,
                                                   void* __restrict__ Cout,
                                                   int N, int K3) {
    __shared__ __align__(16) __nv_bfloat16 As[NSTG][128][SPITCH];
    __shared__ __align__(16) __nv_bfloat16 Ws[NSTG][128][SPITCH];
    int tid = threadIdx.x;
    int bm = blockIdx.y * 128, bn = blockIdx.x * 128;
    int lr = tid >> 1, lc = (tid & 1) * 16;
    int lane = tid & 31, wid = tid >> 5;
    int wm = (wid & 3) * 32, wn = (wid >> 2) * 64;
    int g = lane >> 2, t4 = lane & 3;

    float c[2][8][4];
    #pragma unroll
    for (int mi = 0; mi < 2; mi++)
        #pragma unroll
        for (int ni = 0; ni < 8; ni++)
            #pragma unroll
            for (int q = 0; q < 4; q++) c[mi][ni][q] = 0.f;

    const __nv_bfloat16* Aptr = A + (size_t)(bm + lr) * K3 + lc;
    int wr = bn + lr; if (wr >= N) wr = N - 1;
    const __nv_bfloat16* Wptr = W + (size_t)wr * K3 + lc;

    uint32_t sbA = (uint32_t)__cvta_generic_to_shared(&As[0][0][0]);
    uint32_t sbW = (uint32_t)__cvta_generic_to_shared(&Ws[0][0][0]);
    const uint32_t bufStride = 128 * SPITCH * 2;
    uint32_t dOff = (uint32_t)((lr * SPITCH + lc) * 2);

    int l7 = lane & 7;
    int aRow = wm + ((lane >> 3) & 1) * 8 + l7;
    int aCol = (lane >> 4) * 8;
    int bRow = wn + (lane >> 4) * 8 + l7;
    int bCol = ((lane >> 3) & 1) * 8;

    int KT = K3 / 32;

    #pragma unroll
    for (int s = 0; s < NSTG - 1; s++) {
        if (s < KT) {
            const __nv_bfloat16* ap = Aptr + s * 32;
            const __nv_bfloat16* wp = Wptr + s * 32;
            uint32_t da = sbA + s * bufStride + dOff;
            uint32_t dw = sbW + s * bufStride + dOff;
            CP_ASYNC16(da, ap); CP_ASYNC16(da + 16, ap + 8);
            CP_ASYNC16(dw, wp); CP_ASYNC16(dw + 16, wp + 8);
        }
        CP_COMMIT();
    }

    for (int kt = 0; kt < KT; kt++) {
        CP_WAIT2();
        __syncthreads();

        int cur = kt & (NSTG - 1);
        uint32_t aBase = sbA + cur * bufStride;
        uint32_t wBase = sbW + cur * bufStride;
        #pragma unroll
        for (int kk = 0; kk < 32; kk += 16) {
            uint32_t af[2][4], bf[4][4];
            #pragma unroll
            for (int mi = 0; mi < 2; mi++) {
                uint32_t addr = aBase + (uint32_t)(((aRow + mi * 16) * SPITCH + aCol + kk) * 2);
                LDSM_X4(af[mi], addr);
            }
            #pragma unroll
            for (int q = 0; q < 4; q++) {
                uint32_t addr = wBase + (uint32_t)(((bRow + q * 16) * SPITCH + bCol + kk) * 2);
                LDSM_X4(bf[q], addr);
            }
            #pragma unroll
            for (int q = 0; q < 4; q++) {
                MMA_BF16(c[0][2 * q],     af[0], bf[q][0], bf[q][1]);
                MMA_BF16(c[1][2 * q],     af[1], bf[q][0], bf[q][1]);
                MMA_BF16(c[0][2 * q + 1], af[0], bf[q][2], bf[q][3]);
                MMA_BF16(c[1][2 * q + 1], af[1], bf[q][2], bf[q][3]);
            }
        }
        {
            int s = kt + NSTG - 1;
            if (s < KT) {
                const __nv_bfloat16* ap = Aptr + s * 32;
                const __nv_bfloat16* wp = Wptr + s * 32;
                uint32_t da = sbA + (s & (NSTG - 1)) * bufStride + dOff;
                uint32_t dw = sbW + (s & (NSTG - 1)) * bufStride + dOff;
                CP_ASYNC16(da, ap); CP_ASYNC16(da + 16, ap + 8);
                CP_ASYNC16(dw, wp); CP_ASYNC16(dw + 16, wp + 8);
            }
            CP_COMMIT();
        }
    }
    CP_WAIT0();

    #pragma unroll
    for (int mi = 0; mi < 2; mi++) {
        int r0 = bm + wm + mi * 16 + g;
        #pragma unroll
        for (int ni = 0; ni < 8; ni++) {
            int col = bn + wn + ni * 8 + 2 * t4;
            #pragma unroll
            for (int half = 0; half < 2; half++) {
                int r = r0 + half * 8;
                float v0 = c[mi][ni][half * 2 + 0];
                float v1 = c[mi][ni][half * 2 + 1];
                if (bias) { v0 += bias[col]; v1 += bias[col + 1]; }
                if (ACT == 1) {
                    v0 = 0.5f * v0 * (1.f + erff(v0 * 0.70710678118654752f));
                    v1 = 0.5f * v1 * (1.f + erff(v1 * 0.70710678118654752f));
                }
                if (OUT3) {
                    __nv_bfloat16* O = (__nv_bfloat16*)Cout;
                    __nv_bfloat162 hi, lo;
                    hi.x = __float2bfloat16_rn(v0); hi.y = __float2bfloat16_rn(v1);
                    lo.x = __float2bfloat16_rn(v0 - __bfloat162float(hi.x));
                    lo.y = __float2bfloat16_rn(v1 - __bfloat162float(hi.y));
                    size_t base = (size_t)r * 3 * N + col;
                    *(__nv_bfloat162*)&O[base]         = hi;
                    *(__nv_bfloat162*)&O[base + N]     = hi;
                    *(__nv_bfloat162*)&O[base + 2 * N] = lo;
                } else {
                    float* Cf = (float*)Cout;
                    if (col + 1 < N) {
                        float2 v; v.x = v0; v.y = v1;
                        *(float2*)&Cf[(size_t)r * N + col] = v;
                    } else if (col < N) {
                        Cf[(size_t)r * N + col] = v0;
                    }
                }
            }
        }
    }
}

// ---------------- k_G: per (b,c) score matrix G = C @ B^T via MMA (bf16 hi/lo 3-term) ----------------
#define GP 136
__global__ void __launch_bounds__(256) k_G() {
    extern __shared__ __align__(16) char sg[];
    __nv_bfloat16* Chi = (__nv_bfloat16*)sg;
    __nv_bfloat16* Clo = Chi + 128 * GP;
    __nv_bfloat16* Bhi = Clo + 128 * GP;
    __nv_bfloat16* Blo = Bhi + 128 * GP;
    int tid = threadIdx.x, lane = tid & 31, wid = tid >> 5;
    int blk = blockIdx.x;                    // 0..127, token base = blk*128
    int base = blk * 128;
    int wm = (wid & 3) * 32, wn = (wid >> 2) * 64;
    int g = lane >> 2, t4 = lane & 3;

    // load C,B rows, split hi/lo
    for (int q = tid; q < 4096; q += 256) {
        int row = q >> 5, c4 = (q & 31) * 4;
        const float* rp = &g_xbc[(size_t)(base + row) * CONVDIM + DINNER];
        float4 vB = *(const float4*)(rp + c4);
        float4 vC = *(const float4*)(rp + DSTATE + c4);
        __nv_bfloat162 h, l;
        int o = row * GP + c4;
        h.x = __float2bfloat16_rn(vC.x); h.y = __float2bfloat16_rn(vC.y);
        l.x = __float2bfloat16_rn(vC.x - __bfloat162float(h.x));
        l.y = __float2bfloat16_rn(vC.y - __bfloat162float(h.y));
        *(__nv_bfloat162*)&Chi[o] = h; *(__nv_bfloat162*)&Clo[o] = l;
        h.x = __float2bfloat16_rn(vC.z); h.y = __float2bfloat16_rn(vC.w);
        l.x = __float2bfloat16_rn(vC.z - __bfloat162float(h.x));
        l.y = __float2bfloat16_rn(vC.w - __bfloat162float(h.y));
        *(__nv_bfloat162*)&Chi[o + 2] = h; *(__nv_bfloat162*)&Clo[o + 2] = l;
        h.x = __float2bfloat16_rn(vB.x); h.y = __float2bfloat16_rn(vB.y);
        l.x = __float2bfloat16_rn(vB.x - __bfloat162float(h.x));
        l.y = __float2bfloat16_rn(vB.y - __bfloat162float(h.y));
        *(__nv_bfloat162*)&Bhi[o] = h; *(__nv_bfloat162*)&Blo[o] = l;
        h.x = __float2bfloat16_rn(vB.z); h.y = __float2bfloat16_rn(vB.w);
        l.x = __float2bfloat16_rn(vB.z - __bfloat162float(h.x));
        l.y = __float2bfloat16_rn(vB.w - __bfloat162float(h.y));
        *(__nv_bfloat162*)&Bhi[o + 2] = h; *(__nv_bfloat162*)&Blo[o + 2] = l;
    }
    __syncthreads();

    uint32_t bChi = (uint32_t)__cvta_generic_to_shared(Chi);
    uint32_t bClo = (uint32_t)__cvta_generic_to_shared(Clo);
    uint32_t bBhi = (uint32_t)__cvta_generic_to_shared(Bhi);
    uint32_t bBlo = (uint32_t)__cvta_generic_to_shared(Blo);

    int l7 = lane & 7;
    int aRow = wm + ((lane >> 3) & 1) * 8 + l7;
    int aCol = (lane >> 4) * 8;
    int bRow = wn + (lane >> 4) * 8 + l7;
    int bCol = ((lane >> 3) & 1) * 8;

    float c[2][8][4];
    #pragma unroll
    for (int mi = 0; mi < 2; mi++)
        #pragma unroll
        for (int ni = 0; ni < 8; ni++)
            #pragma unroll
            for (int q = 0; q < 4; q++) c[mi][ni][q] = 0.f;

    #pragma unroll
    for (int term = 0; term < 3; term++) {
        uint32_t aB = (term == 2) ? bClo : bChi;
        uint32_t bB = (term == 1) ? bBlo : bBhi;
        #pragma unroll
        for (int kk = 0; kk < 128; kk += 16) {
            uint32_t af[2][4], bf[4][4];
            #pragma unroll
            for (int mi = 0; mi < 2; mi++) {
                uint32_t addr = aB + (uint32_t)(((aRow + mi * 16) * GP + aCol + kk) * 2);
                LDSM_X4(af[mi], addr);
            }
            #pragma unroll
            for (int q = 0; q < 4; q++) {
                uint32_t addr = bB + (uint32_t)(((bRow + q * 16) * GP + bCol + kk) * 2);
                LDSM_X4(bf[q], addr);
            }
            #pragma unroll
            for (int q = 0; q < 4; q++) {
                MMA_BF16(c[0][2 * q],     af[0], bf[q][0], bf[q][1]);
                MMA_BF16(c[1][2 * q],     af[1], bf[q][0], bf[q][1]);
                MMA_BF16(c[0][2 * q + 1], af[0], bf[q][2], bf[q][3]);
                MMA_BF16(c[1][2 * q + 1], af[1], bf[q][2], bf[q][3]);
            }
        }
    }

    float* Gout = &g_G[(size_t)blk * 16384];
    #pragma unroll
    for (int mi = 0; mi < 2; mi++) {
        int r0 = wm + mi * 16 + g;
        #pragma unroll
        for (int ni = 0; ni < 8; ni++) {
            int col = wn + ni * 8 + 2 * t4;
            #pragma unroll
            for (int half = 0; half < 2; half++) {
                int r = r0 + half * 8;
                float2 v; v.x = c[mi][ni][half * 2]; v.y = c[mi][ni][half * 2 + 1];
                *(float2*)&Gout[r * 128 + col] = v;
            }
        }
    }
}

// ---------------- causal depthwise conv1d + silu (4 s-positions/thread) ----------------
__global__ void k_conv(const float* __restrict__ conv_w, const float* __restrict__ conv_b) {
    int idx = blockIdx.x * 256 + threadIdx.x;    // (b, s4, ch)
    int ch = idx % CONVDIM;
    int r  = idx / CONVDIM;
    int s4 = r % (SEQ / 4);
    int b  = r / (SEQ / 4);
    int s0 = s4 * 4;
    float w0 = conv_w[ch * 4], w1 = conv_w[ch * 4 + 1], w2 = conv_w[ch * 4 + 2], w3 = conv_w[ch * 4 + 3];
    float bias = conv_b[ch];
    float in[7];
    #pragma unroll
    for (int k = 0; k < 7; k++) {
        int sp = s0 + k - 3;
        in[k] = (sp >= 0) ? g_zx[(size_t)(b * SEQ + sp) * DINPROJ + DINNER + ch] : 0.f;
    }
    #pragma unroll
    for (int s = 0; s < 4; s++) {
        float acc = bias + in[s] * w0 + in[s + 1] * w1 + in[s + 2] * w2 + in[s + 3] * w3;
        acc = acc / (1.f + expf(-acc));
        g_xbc[(size_t)(b * SEQ + s0 + s) * CONVDIM + ch] = acc;
    }
}

// ---------------- dt softplus + per-chunk cumulative log-decay ----------------
__global__ void k_dtscan(const float* __restrict__ dt_bias, const float* __restrict__ A_log) {
    __shared__ float s[128];
    int blk = blockIdx.x, l = threadIdx.x;
    int h = blk & 15, c = (blk >> 4) & 15, b = blk >> 8;
    int tok = b * SEQ + c * CHUNK + l;
    float raw = g_zx[(size_t)tok * DINPROJ + 2304 + h] + dt_bias[h];
    float dtv = (raw > 20.f) ? raw : log1pf(expf(raw));
    float A = -expf(A_log[h]);
    g_dt[blk * 128 + l] = dtv;
    s[l] = dtv * A;
    __syncthreads();
    #pragma unroll
    for (int off = 1; off < 128; off <<= 1) {
        float t = (l >= off) ? s[l - off] : 0.f;
        __syncthreads();
        s[l] += t;
        __syncthreads();
    }
    g_acs[blk * 128 + l] = s[l];
}

// ---------------- per-chunk end states: 256 threads, (n, p-half) per thread ----------------
__global__ void __launch_bounds__(256) k_states() {
    extern __shared__ __align__(16) float sh[];
    float* Bs = sh;              // 128*128
    float* xs = Bs + 16384;      // 128*64
    float* ws = xs + 8192;       // 128
    int blk = blockIdx.x, tid = threadIdx.x;
    int n = tid & 127, half = tid >> 7;
    int h = blk & 15, c = (blk >> 4) & 15, b = blk >> 8;
    int base = b * SEQ + c * CHUNK;
    for (int q = tid; q < 16384; q += 256) {
        int l = q >> 7, nn = q & 127;
        Bs[q] = g_xbc[(size_t)(base + l) * CONVDIM + DINNER + nn];
    }
    for (int q = tid; q < 8192; q += 256) {
        int l = q >> 6, p = q & 63;
        xs[q] = g_xbc[(size_t)(base + l) * CONVDIM + h * 64 + p];
    }
    if (tid < 128) {
        float acsL = g_acs[blk * 128 + 127];
        ws[tid] = expf(acsL - g_acs[blk * 128 + tid]) * g_dt[blk * 128 + tid];
    }
    __syncthreads();
    ull acc2[16];
    #pragma unroll
    for (int q = 0; q < 16; q++) acc2[q] = 0ull;
    for (int l = 0; l < 128; l++) {
        float bw = Bs[l * 128 + n] * ws[l];
        ull bwp = pk(bw);
        const ulonglong2* xl = (const ulonglong2*)&xs[l * 64 + half * 32];
        #pragma unroll
        for (int q = 0; q < 8; q++) {
            ulonglong2 v = xl[q];
            acc2[2 * q]     = ffma2(bwp, v.x, acc2[2 * q]);
            acc2[2 * q + 1] = ffma2(bwp, v.y, acc2[2 * q + 1]);
        }
    }
    ulonglong2* dst = (ulonglong2*)&g_states[(size_t)blk * 8192 + n * 64 + half * 32];
    #pragma unroll
    for (int q = 0; q < 8; q++) {
        ulonglong2 v; v.x = acc2[2 * q]; v.y = acc2[2 * q + 1];
        dst[q] = v;
    }
}

// ---------------- sequential chunk scan (parallelized over e-chunks) ----------------
__global__ void k_scan() {
    int bx = blockIdx.x;              // 1024 blocks: (b, h, e8)
    int e8 = bx & 7;
    int bh = bx >> 3;
    int b = bh >> 4, h = bh & 15;
    int e = e8 * 1024 + threadIdx.x;
    for (int k = 0; k < 4; k++, e += 256) {
        float acc = 0.f;
        #pragma unroll
        for (int c = 0; c < NCHUNK; c++) {
            int blk = ((b * NCHUNK + c) << 4) + h;
            g_prev[(size_t)blk * 8192 + e] = acc;
            float cd = expf(g_acs[blk * 128 + 127]);
            acc = cd * acc + g_states[(size_t)blk * 8192 + e];
        }
    }
}

// ---------------- fused SSD output v3: 512 threads, 4-way split, G from gmem ----------------
#define CPAD 132
__global__ void __launch_bounds__(512, 1) k_y(const float* __restrict__ D_head) {
    extern __shared__ __align__(16) float sh[];
    float* Cs   = sh;                 // 128*CPAD (also staging for q2/q3)
    float* xs   = Cs + 128 * CPAD;    // 128*64 (also staging for q1)
    float* ps   = xs + 8192;          // 128*64
    float* acs_s = ps + 8192;         // 128
    float* dt_s  = acs_s + 128;       // 128
    int blk = blockIdx.x, tid = threadIdx.x;
    int i = tid & 127, q4 = tid >> 7;
    int h = blk & 15, c = (blk >> 4) & 15, b = blk >> 8;
    int base = b * SEQ + c * CHUNK;
    const float* Grow = &g_G[(size_t)(blk >> 4) * 16384 + i * 128];

    for (int q = tid; q < 16384; q += 512) {
        int l = q >> 7, n = q & 127;
        Cs[l * CPAD + n] = g_xbc[(size_t)(base + l) * CONVDIM + DINNER + DSTATE + n];
    }
    for (int q = tid; q < 8192; q += 512) {
        int l = q >> 6, p = q & 63;
        xs[q] = g_xbc[(size_t)(base + l) * CONVDIM + h * 64 + p];
    }
    {
        const float4* src = (const float4*)&g_prev[(size_t)blk * 8192];
        float4* d = (float4*)ps;
        for (int q = tid; q < 2048; q += 512) d[q] = src[q];
    }
    if (tid < 128) {
        acs_s[tid] = g_acs[blk * 128 + tid];
        dt_s[tid]  = g_dt[blk * 128 + tid];
    }
    __syncthreads();

    ull y2[32];
    #pragma unroll
    for (int q = 0; q < 32; q++) y2[q] = 0ull;
    float ai = acs_s[i];

    // Y_diag: j = q4, q4+4, ... <= i ; G read (warp-uniform -> broadcast)
    for (int j = q4; j <= i; j += 4) {
        float g = expf(ai - acs_s[j]) * dt_s[j] * Grow[j];
        ull gp = pk(g);
        const ulonglong2* xj = (const ulonglong2*)&xs[j * 64];
        #pragma unroll
        for (int q = 0; q < 16; q++) {
            ulonglong2 v = xj[q];
            y2[2 * q]     = ffma2(gp, v.x, y2[2 * q]);
            y2[2 * q + 1] = ffma2(gp, v.y, y2[2 * q + 1]);
        }
    }

    // Y_off: n covered by (pair parity, element parity) = q4
    float e = expf(ai);
    for (int pi = (q4 >> 1); pi < 64; pi += 2) {
        int n = 2 * pi + (q4 & 1);
        float cv = Cs[i * CPAD + n];
        ull c0 = pk(e * cv);
        const ulonglong2* p0 = (const ulonglong2*)&ps[n * 64];
        #pragma unroll
        for (int r = 0; r < 16; r++) {
            ulonglong2 v0 = p0[r];
            y2[2 * r]     = ffma2(c0, v0.x, y2[2 * r]);
            y2[2 * r + 1] = ffma2(c0, v0.y, y2[2 * r + 1]);
        }
    }

    // + D*x (q4 == 0)
    if (q4 == 0) {
        float dh = D_head[h];
        ull dhp = pk(dh);
        const ulonglong2* xi = (const ulonglong2*)&xs[i * 64];
        #pragma unroll
        for (int q = 0; q < 16; q++) {
            ulonglong2 v = xi[q];
            y2[2 * q]     = ffma2(dhp, v.x, y2[2 * q]);
            y2[2 * q + 1] = ffma2(dhp, v.y, y2[2 * q + 1]);
        }
    }

    __syncthreads();   // all xs/ps/Cs reads complete
    if (q4 == 1) {
        ulonglong2* st = (ulonglong2*)&xs[i * 64];
        #pragma unroll
        for (int q = 0; q < 16; q++) { ulonglong2 v; v.x = y2[2 * q]; v.y = y2[2 * q + 1]; st[q] = v; }
    } else if (q4 == 2) {
        ulonglong2* st = (ulonglong2*)&Cs[i * 64];
        #pragma unroll
        for (int q = 0; q < 16; q++) { ulonglong2 v; v.x = y2[2 * q]; v.y = y2[2 * q + 1]; st[q] = v; }
    } else if (q4 == 3) {
        ulonglong2* st = (ulonglong2*)&Cs[8192 + i * 64];
        #pragma unroll
        for (int q = 0; q < 16; q++) { ulonglong2 v; v.x = y2[2 * q]; v.y = y2[2 * q + 1]; st[q] = v; }
    }
    __syncthreads();
    if (q4 == 0) {
        const ulonglong2* s1 = (const ulonglong2*)&xs[i * 64];
        const ulonglong2* s2 = (const ulonglong2*)&Cs[i * 64];
        const ulonglong2* s3 = (const ulonglong2*)&Cs[8192 + i * 64];
        ull one = pk(1.f);
        #pragma unroll
        for (int q = 0; q < 16; q++) {
            ulonglong2 v1 = s1[q], v2 = s2[q], v3 = s3[q];
            y2[2 * q]     = ffma2(one, v1.x, y2[2 * q]);
            y2[2 * q + 1] = ffma2(one, v1.y, y2[2 * q + 1]);
            y2[2 * q]     = ffma2(one, v2.x, y2[2 * q]);
            y2[2 * q + 1] = ffma2(one, v2.y, y2[2 * q + 1]);
            y2[2 * q]     = ffma2(one, v3.x, y2[2 * q]);
            y2[2 * q + 1] = ffma2(one, v3.y, y2[2 * q + 1]);
        }
        ulonglong2* dst = (ulonglong2*)&g_y[(size_t)(base + i) * DINNER + h * 64];
        #pragma unroll
        for (int q = 0; q < 16; q++) {
            ulonglong2 v; v.x = y2[2 * q]; v.y = y2[2 * q + 1];
            dst[q] = v;
        }
    }
}

// ---------------- gate with silu(z) + RMSNorm * norm_w -> bf16x3 A operand ----------------
__global__ void k_gate(const float* __restrict__ norm_w, __nv_bfloat16* __restrict__ out3) {
    __shared__ float red[64];
    int t = blockIdx.x, tid = threadIdx.x;
    float v[4]; float ss = 0.f, dummy = 0.f;
    #pragma unroll
    for (int k = 0; k < 4; k++) {
        int d = tid + k * 256;
        float yv = g_y[(size_t)t * DINNER + d];
        float zv = g_zx[(size_t)t * DINPROJ + d];
        float sv = yv * (zv / (1.f + expf(-zv)));
        v[k] = sv; ss += sv * sv;
    }
    blockReduce2(ss, dummy, red);
    float sc = rsqrtf(ss * (1.f / 1024.f) + EPSF);
    __nv_bfloat16* row = out3 + (size_t)t * 3 * DINNER;
    #pragma unroll
    for (int k = 0; k < 4; k++) {
        int d = tid + k * 256;
        bf16x3_store_scalar(row, DINNER, d, v[k] * sc * norm_w[d]);
    }
}

// ---------------- out = LayerNorm(a + b) * w + beta (D=512), optional bf16x3 copy ----------------
__global__ void k_addln(const float* __restrict__ a, const float* __restrict__ bsrc,
                        const float* __restrict__ w, const float* __restrict__ beta,
                        float* __restrict__ o, __nv_bfloat16* __restrict__ out3) {
    __shared__ float red[64];
    int t = blockIdx.x, tid = threadIdx.x;
    float v[4]; float s = 0.f, ssq = 0.f;
    #pragma unroll
    for (int k = 0; k < 4; k++) {
        int d = tid + k * 128;
        float x = a[(size_t)t * DMODEL + d] + bsrc[(size_t)t * DMODEL + d];
        v[k] = x; s += x; ssq += x * x;
    }
    blockReduce2(s, ssq, red);
    float mean = s * (1.f / 512.f);
    float var = ssq * (1.f / 512.f) - mean * mean;
    float inv = rsqrtf(var + EPSF);
    #pragma unroll
    for (int k = 0; k < 4; k++) {
        int d = tid + k * 128;
        float r = (v[k] - mean) * inv * w[d] + beta[d];
        o[(size_t)t * DMODEL + d] = r;
        if (out3) bf16x3_store_scalar(out3 + (size_t)t * 3 * DMODEL, DMODEL, d, r);
    }
}

// ---------------- launch ----------------
static inline void splitA(const float* src, __nv_bfloat16* dst, int M, int K) {
    k_split<2><<<(int)(((size_t)M * K / 4) / 256), 256>>>(src, dst, K);
}
static inline void splitW(const float* src, __nv_bfloat16* dst, int M, int K) {
    k_split<1><<<(int)(((size_t)M * K / 4) / 256), 256>>>(src, dst, K);
}

extern "C" void kernel_launch(void* const* d_in, const int* in_sizes, int n_in,
                              void* d_out, int out_size) {
    const float* tgt        = (const float*)d_in[0];
    const float* in_proj_w  = (const float*)d_in[5];
    const float* conv_w     = (const float*)d_in[6];
    const float* conv_b     = (const float*)d_in[7];
    const float* dt_bias    = (const float*)d_in[8];
    const float* A_log      = (const float*)d_in[9];
    const float* D_head     = (const float*)d_in[10];
    const float* norm_w     = (const float*)d_in[11];
    const float* out_proj_w = (const float*)d_in[12];
    const float* n1w = (const float*)d_in[13];
    const float* n1b = (const float*)d_in[14];
    const float* w1  = (const float*)d_in[15];
    const float* b1  = (const float*)d_in[16];
    const float* w2  = (const float*)d_in[17];
    const float* b2  = (const float*)d_in[18];
    const float* n3w = (const float*)d_in[19];
    const float* n3b = (const float*)d_in[20];
    float* out = (float*)d_out;

    float *zx, *mo, *tb, *f2;
    __nv_bfloat16 *A3, *A3b, *W3;
    cudaGetSymbolAddress((void**)&zx,   g_zx);
    cudaGetSymbolAddress((void**)&mo,   g_mo);
    cudaGetSymbolAddress((void**)&tb,   g_t);
    cudaGetSymbolAddress((void**)&f2,   g_f2);
    cudaGetSymbolAddress((void**)&A3,   g_A3);
    cudaGetSymbolAddress((void**)&A3b,  g_A3b);
    cudaGetSymbolAddress((void**)&W3,   g_W3);

    const int smem_states = (16384 + 8192 + 128) * 4;
    const int smem_y = (128 * CPAD + 8192 + 8192 + 256) * 4;     // 134144
    const int smem_g = 4 * 128 * GP * 2;                          // 139264
    cudaFuncSetAttribute(k_states, cudaFuncAttributeMaxDynamicSharedMemorySize, smem_states);
    cudaFuncSetAttribute(k_y,      cudaFuncAttributeMaxDynamicSharedMemorySize, smem_y);
    cudaFuncSetAttribute(k_G,      cudaFuncAttributeMaxDynamicSharedMemorySize, smem_g);

    // 1. in_proj: zx = tgt @ in_proj_w^T
    splitA(tgt, A3, TOK, DMODEL);
    splitW(in_proj_w, W3, DINPROJ, DMODEL);
    k_gemm_bf16<0, 0><<<dim3((DINPROJ + 127) / 128, TOK / 128), 256>>>(A3, W3, nullptr, zx, DINPROJ, 3 * DMODEL);
    // 2. conv + silu
    k_conv<<<(TOK / 4 * CONVDIM) / 256, 256>>>(conv_w, conv_b);
    // 3. dt softplus + cumsum
    k_dtscan<<<NBLK, 128>>>(dt_bias, A_log);
    // 4. shared score matrices G = C @ B^T (per (b,c))
    k_G<<<NGC, 256, smem_g>>>();
    // 5. chunk end-states
    k_states<<<NBLK, 256, smem_states>>>();
    // 6. chunk scan -> prev
    k_scan<<<BATCH * NHEADS * 8, 256>>>();
    // 7. fused SSD output
    k_y<<<NBLK, 512, smem_y>>>(D_head);
    // 8. gate + rmsnorm -> bf16x3 directly
    k_gate<<<TOK, 256>>>(norm_w, A3);
    // 9. out_proj: mo = gate @ out_proj_w^T
    splitW(out_proj_w, W3, DMODEL, DINNER);
    k_gemm_bf16<0, 0><<<dim3(DMODEL / 128, TOK / 128), 256>>>(A3, W3, nullptr, mo, DMODEL, 3 * DINNER);
    // 10. t = LN(tgt + mo), also emit bf16x3 for FFN GEMM
    k_addln<<<TOK, 128>>>(tgt, mo, n1w, n1b, tb, A3);
    // 11. f1 = gelu(t @ w1^T + b1) -> bf16x3 directly
    splitW(w1, W3, FF, DMODEL);
    k_gemm_bf16<1, 1><<<dim3(FF / 128, TOK / 128), 256>>>(A3, W3, b1, A3b, FF, 3 * DMODEL);
    // 12. f2 = f1 @ w2^T + b2
    splitW(w2, W3, DMODEL, FF);
    k_gemm_bf16<0, 0><<<dim3(DMODEL / 128, TOK / 128), 256>>>(A3b, W3, b2, f2, DMODEL, 3 * FF);
    // 13. out = LN(t + f2)
    k_addln<<<TOK, 128>>>(tb, f2, n3w, n3b, out, nullptr);
}

// round 13
// speedup vs baseline: 2.7827x; 1.2196x over previous
#include <cuda_runtime.h>
#include <cuda_bf16.h>
#include <cuda_fp16.h>
#include <math.h>
#include <cstdint>

// ---------------- problem constants ----------------
#define BATCH 8
#define SEQ 2048
#define TOK (BATCH*SEQ)          // 16384
#define DMODEL 512
#define DINNER 1024
#define DSTATE 128
#define NHEADS 16
#define HEADDIM 64
#define CONVDIM 1280
#define DINPROJ 2320
#define FF 2048
#define CHUNK 128
#define NCHUNK (SEQ/CHUNK)       // 16
#define NBLK (BATCH*NCHUNK*NHEADS) // 2048
#define NGC (BATCH*NCHUNK)       // 128
#define EPSF 1e-5f

typedef unsigned long long ull;

// ---------------- packed f32x2 helpers ----------------
__device__ __forceinline__ ull pk(float x) {
    ull r; asm("mov.b64 %0,{%1,%2};" : "=l"(r) : "f"(x), "f"(x)); return r;
}
__device__ __forceinline__ ull ffma2(ull a, ull b, ull c) {
    ull d; asm("fma.rn.f32x2 %0,%1,%2,%3;" : "=l"(d) : "l"(a), "l"(b), "l"(c)); return d;
}
__device__ __forceinline__ float2 upk(ull v) {
    float2 f; asm("mov.b64 {%0,%1},%2;" : "=f"(f.x), "=f"(f.y) : "l"(v)); return f;
}

#define MMA_F16(cc, aa, b0, b1) \
    asm volatile("mma.sync.aligned.m16n8k16.row.col.f32.f16.f16.f32 " \
        "{%0,%1,%2,%3},{%4,%5,%6,%7},{%8,%9},{%0,%1,%2,%3};" \
        : "+f"(cc[0]), "+f"(cc[1]), "+f"(cc[2]), "+f"(cc[3]) \
        : "r"(aa[0]), "r"(aa[1]), "r"(aa[2]), "r"(aa[3]), "r"(b0), "r"(b1))

#define MMA_BF16(cc, aa, b0, b1) \
    asm volatile("mma.sync.aligned.m16n8k16.row.col.f32.bf16.bf16.f32 " \
        "{%0,%1,%2,%3},{%4,%5,%6,%7},{%8,%9},{%0,%1,%2,%3};" \
        : "+f"(cc[0]), "+f"(cc[1]), "+f"(cc[2]), "+f"(cc[3]) \
        : "r"(aa[0]), "r"(aa[1]), "r"(aa[2]), "r"(aa[3]), "r"(b0), "r"(b1))

#define LDSM_X4(r, addr) \
    asm volatile("ldmatrix.sync.aligned.m8n8.x4.shared.b16 {%0,%1,%2,%3},[%4];" \
        : "=r"((r)[0]), "=r"((r)[1]), "=r"((r)[2]), "=r"((r)[3]) : "r"(addr))

#define CP_ASYNC16(dst, src) \
    asm volatile("cp.async.cg.shared.global [%0], [%1], 16;" :: "r"(dst), "l"(src))
#define CP_COMMIT() asm volatile("cp.async.commit_group;" ::: "memory")
#define CP_WAIT2()  asm volatile("cp.async.wait_group 2;" ::: "memory")
#define CP_WAIT0()  asm volatile("cp.async.wait_group 0;" ::: "memory")

// ---------------- scratch ----------------
__device__ __align__(16) float g_zx[TOK*DINPROJ];
__device__ __align__(16) float g_xbc[TOK*CONVDIM];
__device__ __align__(16) float g_dt[NBLK*CHUNK];
__device__ __align__(16) float g_acs[NBLK*CHUNK];
__device__ __align__(16) float g_states[(size_t)NBLK*DSTATE*HEADDIM];
__device__ __align__(16) float g_prev[(size_t)NBLK*DSTATE*HEADDIM];
__device__ __align__(16) float g_y[(size_t)TOK*DINNER];
__device__ __align__(16) float g_mo[(size_t)TOK*DMODEL];
__device__ __align__(16) float g_t[(size_t)TOK*DMODEL];
__device__ __align__(16) float g_f2[(size_t)TOK*DMODEL];
__device__ __align__(16) float g_G[(size_t)NGC*CHUNK*CHUNK];   // 8 MB score matrices
// fp16x2 expanded operands
__device__ __align__(16) __half g_A2[(size_t)TOK*2*DINNER];    // A-side (max K=1024)
__device__ __align__(16) __half g_A2b[(size_t)TOK*2*FF];       // f1 fp16x2 (K=2048)
__device__ __align__(16) __half g_W2[DINPROJ*2*DMODEL];

// ---------------- helpers ----------------
__device__ __forceinline__ void blockReduce2(float& a, float& b, float* sh) {
    int lane = threadIdx.x & 31, w = threadIdx.x >> 5;
    #pragma unroll
    for (int o = 16; o; o >>= 1) {
        a += __shfl_xor_sync(0xffffffffu, a, o);
        b += __shfl_xor_sync(0xffffffffu, b, o);
    }
    if (lane == 0) { sh[w] = a; sh[32 + w] = b; }
    __syncthreads();
    int nw = blockDim.x >> 5;
    if (w == 0) {
        a = (lane < nw) ? sh[lane] : 0.f;
        b = (lane < nw) ? sh[32 + lane] : 0.f;
        #pragma unroll
        for (int o = 16; o; o >>= 1) {
            a += __shfl_xor_sync(0xffffffffu, a, o);
            b += __shfl_xor_sync(0xffffffffu, b, o);
        }
        if (lane == 0) { sh[0] = a; sh[32] = b; }
    }
    __syncthreads();
    a = sh[0]; b = sh[32];
}

__device__ __forceinline__ void f16x2_store_scalar(__half* row, int K, int d, float s) {
    __half hi = __float2half_rn(s);
    __half lo = __float2half_rn(s - __half2float(hi));
    row[d] = hi; row[K + d] = lo;
}

// ---------------- fp16x2 split: src[M,K] fp32 -> dst[M,2K] f16 (hi | DUP?hi:lo) ----------------
template<int DUP>
__global__ void k_split2(const float* __restrict__ src, __half* __restrict__ dst, int K) {
    size_t i = (size_t)blockIdx.x * 256 + threadIdx.x;
    int K4 = K >> 2;
    size_t row = i / K4;
    int c4 = (int)(i % K4);
    float4 v = ((const float4*)src)[i];
    __half2 h0, h1, l0, l1;
    h0.x = __float2half_rn(v.x); h0.y = __float2half_rn(v.y);
    h1.x = __float2half_rn(v.z); h1.y = __float2half_rn(v.w);
    l0.x = __float2half_rn(v.x - __half2float(h0.x));
    l0.y = __float2half_rn(v.y - __half2float(h0.y));
    l1.x = __float2half_rn(v.z - __half2float(h1.x));
    l1.y = __float2half_rn(v.w - __half2float(h1.y));
    __half2* d = (__half2*)(dst + row * 2 * K);
    int c2 = c4 * 2;
    int K2 = K >> 1;
    d[c2] = h0; d[c2 + 1] = h1;
    d[K2 + c2]     = DUP ? h0 : l0;
    d[K2 + c2 + 1] = DUP ? h1 : l1;
}

// ---------------- fp16 tensor-core GEMM, 4-stage cp.async, single-sync mainloop ----------------
// A2 = [hiA|loA] (pitch 2K), W2 = [hiW|hiW] (pitch 2K): result = A@W^T + O(2^-11) correction.
#define SPITCH 40
#define NSTG 4
template<int ACT, int OUT2>
__global__ void __launch_bounds__(256) k_gemm_f16(const __half* __restrict__ A,
                                                  const __half* __restrict__ W,
                                                  const float* __restrict__ bias,
                                                  void* __restrict__ Cout,
                                                  int N, int K2) {
    __shared__ __align__(16) __half As[NSTG][128][SPITCH];
    __shared__ __align__(16) __half Ws[NSTG][128][SPITCH];
    int tid = threadIdx.x;
    int bm = blockIdx.y * 128, bn = blockIdx.x * 128;
    int lr = tid >> 1, lc = (tid & 1) * 16;
    int lane = tid & 31, wid = tid >> 5;
    int wm = (wid & 3) * 32, wn = (wid >> 2) * 64;
    int g = lane >> 2, t4 = lane & 3;

    float c[2][8][4];
    #pragma unroll
    for (int mi = 0; mi < 2; mi++)
        #pragma unroll
        for (int ni = 0; ni < 8; ni++)
            #pragma unroll
            for (int q = 0; q < 4; q++) c[mi][ni][q] = 0.f;

    const __half* Aptr = A + (size_t)(bm + lr) * K2 + lc;
    int wr = bn + lr; if (wr >= N) wr = N - 1;
    const __half* Wptr = W + (size_t)wr * K2 + lc;

    uint32_t sbA = (uint32_t)__cvta_generic_to_shared(&As[0][0][0]);
    uint32_t sbW = (uint32_t)__cvta_generic_to_shared(&Ws[0][0][0]);
    const uint32_t bufStride = 128 * SPITCH * 2;
    uint32_t dOff = (uint32_t)((lr * SPITCH + lc) * 2);

    int l7 = lane & 7;
    int aRow = wm + ((lane >> 3) & 1) * 8 + l7;
    int aCol = (lane >> 4) * 8;
    int bRow = wn + (lane >> 4) * 8 + l7;
    int bCol = ((lane >> 3) & 1) * 8;

    int KT = K2 / 32;

    #pragma unroll
    for (int s = 0; s < NSTG - 1; s++) {
        if (s < KT) {
            const __half* ap = Aptr + s * 32;
            const __half* wp = Wptr + s * 32;
            uint32_t da = sbA + s * bufStride + dOff;
            uint32_t dw = sbW + s * bufStride + dOff;
            CP_ASYNC16(da, ap); CP_ASYNC16(da + 16, ap + 8);
            CP_ASYNC16(dw, wp); CP_ASYNC16(dw + 16, wp + 8);
        }
        CP_COMMIT();
    }

    for (int kt = 0; kt < KT; kt++) {
        CP_WAIT2();
        __syncthreads();

        int cur = kt & (NSTG - 1);
        uint32_t aBase = sbA + cur * bufStride;
        uint32_t wBase = sbW + cur * bufStride;
        #pragma unroll
        for (int kk = 0; kk < 32; kk += 16) {
            uint32_t af[2][4], bf[4][4];
            #pragma unroll
            for (int mi = 0; mi < 2; mi++) {
                uint32_t addr = aBase + (uint32_t)(((aRow + mi * 16) * SPITCH + aCol + kk) * 2);
                LDSM_X4(af[mi], addr);
            }
            #pragma unroll
            for (int q = 0; q < 4; q++) {
                uint32_t addr = wBase + (uint32_t)(((bRow + q * 16) * SPITCH + bCol + kk) * 2);
                LDSM_X4(bf[q], addr);
            }
            #pragma unroll
            for (int q = 0; q < 4; q++) {
                MMA_F16(c[0][2 * q],     af[0], bf[q][0], bf[q][1]);
                MMA_F16(c[1][2 * q],     af[1], bf[q][0], bf[q][1]);
                MMA_F16(c[0][2 * q + 1], af[0], bf[q][2], bf[q][3]);
                MMA_F16(c[1][2 * q + 1], af[1], bf[q][2], bf[q][3]);
            }
        }
        {
            int s = kt + NSTG - 1;
            if (s < KT) {
                const __half* ap = Aptr + s * 32;
                const __half* wp = Wptr + s * 32;
                uint32_t da = sbA + (s & (NSTG - 1)) * bufStride + dOff;
                uint32_t dw = sbW + (s & (NSTG - 1)) * bufStride + dOff;
                CP_ASYNC16(da, ap); CP_ASYNC16(da + 16, ap + 8);
                CP_ASYNC16(dw, wp); CP_ASYNC16(dw + 16, wp + 8);
            }
            CP_COMMIT();
        }
    }
    CP_WAIT0();

    #pragma unroll
    for (int mi = 0; mi < 2; mi++) {
        int r0 = bm + wm + mi * 16 + g;
        #pragma unroll
        for (int ni = 0; ni < 8; ni++) {
            int col = bn + wn + ni * 8 + 2 * t4;
            #pragma unroll
            for (int half = 0; half < 2; half++) {
                int r = r0 + half * 8;
                float v0 = c[mi][ni][half * 2 + 0];
                float v1 = c[mi][ni][half * 2 + 1];
                if (bias) { v0 += bias[col]; v1 += bias[col + 1]; }
                if (ACT == 1) {
                    v0 = 0.5f * v0 * (1.f + erff(v0 * 0.70710678118654752f));
                    v1 = 0.5f * v1 * (1.f + erff(v1 * 0.70710678118654752f));
                }
                if (OUT2) {
                    __half* O = (__half*)Cout;
                    __half2 hi, lo;
                    hi.x = __float2half_rn(v0); hi.y = __float2half_rn(v1);
                    lo.x = __float2half_rn(v0 - __half2float(hi.x));
                    lo.y = __float2half_rn(v1 - __half2float(hi.y));
                    size_t base = (size_t)r * 2 * N + col;
                    *(__half2*)&O[base]     = hi;
                    *(__half2*)&O[base + N] = lo;
                } else {
                    float* Cf = (float*)Cout;
                    if (col + 1 < N) {
                        float2 v; v.x = v0; v.y = v1;
                        *(float2*)&Cf[(size_t)r * N + col] = v;
                    } else if (col < N) {
                        Cf[(size_t)r * N + col] = v0;
                    }
                }
            }
        }
    }
}

// ---------------- k_G: per (b,c) score matrix G = C @ B^T via MMA (bf16 hi/lo 3-term) ----------------
#define GP 136
__global__ void __launch_bounds__(256) k_G() {
    extern __shared__ __align__(16) char sg[];
    __nv_bfloat16* Chi = (__nv_bfloat16*)sg;
    __nv_bfloat16* Clo = Chi + 128 * GP;
    __nv_bfloat16* Bhi = Clo + 128 * GP;
    __nv_bfloat16* Blo = Bhi + 128 * GP;
    int tid = threadIdx.x, lane = tid & 31, wid = tid >> 5;
    int blk = blockIdx.x;
    int base = blk * 128;
    int wm = (wid & 3) * 32, wn = (wid >> 2) * 64;
    int g = lane >> 2, t4 = lane & 3;

    for (int q = tid; q < 4096; q += 256) {
        int row = q >> 5, c4 = (q & 31) * 4;
        const float* rp = &g_xbc[(size_t)(base + row) * CONVDIM + DINNER];
        float4 vB = *(const float4*)(rp + c4);
        float4 vC = *(const float4*)(rp + DSTATE + c4);
        __nv_bfloat162 h, l;
        int o = row * GP + c4;
        h.x = __float2bfloat16_rn(vC.x); h.y = __float2bfloat16_rn(vC.y);
        l.x = __float2bfloat16_rn(vC.x - __bfloat162float(h.x));
        l.y = __float2bfloat16_rn(vC.y - __bfloat162float(h.y));
        *(__nv_bfloat162*)&Chi[o] = h; *(__nv_bfloat162*)&Clo[o] = l;
        h.x = __float2bfloat16_rn(vC.z); h.y = __float2bfloat16_rn(vC.w);
        l.x = __float2bfloat16_rn(vC.z - __bfloat162float(h.x));
        l.y = __float2bfloat16_rn(vC.w - __bfloat162float(h.y));
        *(__nv_bfloat162*)&Chi[o + 2] = h; *(__nv_bfloat162*)&Clo[o + 2] = l;
        h.x = __float2bfloat16_rn(vB.x); h.y = __float2bfloat16_rn(vB.y);
        l.x = __float2bfloat16_rn(vB.x - __bfloat162float(h.x));
        l.y = __float2bfloat16_rn(vB.y - __bfloat162float(h.y));
        *(__nv_bfloat162*)&Bhi[o] = h; *(__nv_bfloat162*)&Blo[o] = l;
        h.x = __float2bfloat16_rn(vB.z); h.y = __float2bfloat16_rn(vB.w);
        l.x = __float2bfloat16_rn(vB.z - __bfloat162float(h.x));
        l.y = __float2bfloat16_rn(vB.w - __bfloat162float(h.y));
        *(__nv_bfloat162*)&Bhi[o + 2] = h; *(__nv_bfloat162*)&Blo[o + 2] = l;
    }
    __syncthreads();

    uint32_t bChi = (uint32_t)__cvta_generic_to_shared(Chi);
    uint32_t bClo = (uint32_t)__cvta_generic_to_shared(Clo);
    uint32_t bBhi = (uint32_t)__cvta_generic_to_shared(Bhi);
    uint32_t bBlo = (uint32_t)__cvta_generic_to_shared(Blo);

    int l7 = lane & 7;
    int aRow = wm + ((lane >> 3) & 1) * 8 + l7;
    int aCol = (lane >> 4) * 8;
    int bRow = wn + (lane >> 4) * 8 + l7;
    int bCol = ((lane >> 3) & 1) * 8;

    float c[2][8][4];
    #pragma unroll
    for (int mi = 0; mi < 2; mi++)
        #pragma unroll
        for (int ni = 0; ni < 8; ni++)
            #pragma unroll
            for (int q = 0; q < 4; q++) c[mi][ni][q] = 0.f;

    #pragma unroll
    for (int term = 0; term < 3; term++) {
        uint32_t aB = (term == 2) ? bClo : bChi;
        uint32_t bB = (term == 1) ? bBlo : bBhi;
        #pragma unroll
        for (int kk = 0; kk < 128; kk += 16) {
            uint32_t af[2][4], bf[4][4];
            #pragma unroll
            for (int mi = 0; mi < 2; mi++) {
                uint32_t addr = aB + (uint32_t)(((aRow + mi * 16) * GP + aCol + kk) * 2);
                LDSM_X4(af[mi], addr);
            }
            #pragma unroll
            for (int q = 0; q < 4; q++) {
                uint32_t addr = bB + (uint32_t)(((bRow + q * 16) * GP + bCol + kk) * 2);
                LDSM_X4(bf[q], addr);
            }
            #pragma unroll
            for (int q = 0; q < 4; q++) {
                MMA_BF16(c[0][2 * q],     af[0], bf[q][0], bf[q][1]);
                MMA_BF16(c[1][2 * q],     af[1], bf[q][0], bf[q][1]);
                MMA_BF16(c[0][2 * q + 1], af[0], bf[q][2], bf[q][3]);
                MMA_BF16(c[1][2 * q + 1], af[1], bf[q][2], bf[q][3]);
            }
        }
    }

    float* Gout = &g_G[(size_t)blk * 16384];
    #pragma unroll
    for (int mi = 0; mi < 2; mi++) {
        int r0 = wm + mi * 16 + g;
        #pragma unroll
        for (int ni = 0; ni < 8; ni++) {
            int col = wn + ni * 8 + 2 * t4;
            #pragma unroll
            for (int half = 0; half < 2; half++) {
                int r = r0 + half * 8;
                float2 v; v.x = c[mi][ni][half * 2]; v.y = c[mi][ni][half * 2 + 1];
                *(float2*)&Gout[r * 128 + col] = v;
            }
        }
    }
}

// ---------------- causal depthwise conv1d + silu (4 s-positions/thread) ----------------
__global__ void k_conv(const float* __restrict__ conv_w, const float* __restrict__ conv_b) {
    int idx = blockIdx.x * 256 + threadIdx.x;
    int ch = idx % CONVDIM;
    int r  = idx / CONVDIM;
    int s4 = r % (SEQ / 4);
    int b  = r / (SEQ / 4);
    int s0 = s4 * 4;
    float w0 = conv_w[ch * 4], w1 = conv_w[ch * 4 + 1], w2 = conv_w[ch * 4 + 2], w3 = conv_w[ch * 4 + 3];
    float bias = conv_b[ch];
    float in[7];
    #pragma unroll
    for (int k = 0; k < 7; k++) {
        int sp = s0 + k - 3;
        in[k] = (sp >= 0) ? g_zx[(size_t)(b * SEQ + sp) * DINPROJ + DINNER + ch] : 0.f;
    }
    #pragma unroll
    for (int s = 0; s < 4; s++) {
        float acc = bias + in[s] * w0 + in[s + 1] * w1 + in[s + 2] * w2 + in[s + 3] * w3;
        acc = acc / (1.f + expf(-acc));
        g_xbc[(size_t)(b * SEQ + s0 + s) * CONVDIM + ch] = acc;
    }
}

// ---------------- dt softplus + per-chunk cumulative log-decay ----------------
__global__ void k_dtscan(const float* __restrict__ dt_bias, const float* __restrict__ A_log) {
    __shared__ float s[128];
    int blk = blockIdx.x, l = threadIdx.x;
    int h = blk & 15, c = (blk >> 4) & 15, b = blk >> 8;
    int tok = b * SEQ + c * CHUNK + l;
    float raw = g_zx[(size_t)tok * DINPROJ + 2304 + h] + dt_bias[h];
    float dtv = (raw > 20.f) ? raw : log1pf(expf(raw));
    float A = -expf(A_log[h]);
    g_dt[blk * 128 + l] = dtv;
    s[l] = dtv * A;
    __syncthreads();
    #pragma unroll
    for (int off = 1; off < 128; off <<= 1) {
        float t = (l >= off) ? s[l - off] : 0.f;
        __syncthreads();
        s[l] += t;
        __syncthreads();
    }
    g_acs[blk * 128 + l] = s[l];
}

// ---------------- per-chunk end states: 256 threads, (n, p-half) per thread ----------------
__global__ void __launch_bounds__(256) k_states() {
    extern __shared__ __align__(16) float sh[];
    float* Bs = sh;              // 128*128
    float* xs = Bs + 16384;      // 128*64
    float* ws = xs + 8192;       // 128
    int blk = blockIdx.x, tid = threadIdx.x;
    int n = tid & 127, half = tid >> 7;
    int h = blk & 15, c = (blk >> 4) & 15, b = blk >> 8;
    int base = b * SEQ + c * CHUNK;
    for (int q = tid; q < 16384; q += 256) {
        int l = q >> 7, nn = q & 127;
        Bs[q] = g_xbc[(size_t)(base + l) * CONVDIM + DINNER + nn];
    }
    for (int q = tid; q < 8192; q += 256) {
        int l = q >> 6, p = q & 63;
        xs[q] = g_xbc[(size_t)(base + l) * CONVDIM + h * 64 + p];
    }
    if (tid < 128) {
        float acsL = g_acs[blk * 128 + 127];
        ws[tid] = expf(acsL - g_acs[blk * 128 + tid]) * g_dt[blk * 128 + tid];
    }
    __syncthreads();
    ull acc2[16];
    #pragma unroll
    for (int q = 0; q < 16; q++) acc2[q] = 0ull;
    for (int l = 0; l < 128; l++) {
        float bw = Bs[l * 128 + n] * ws[l];
        ull bwp = pk(bw);
        const ulonglong2* xl = (const ulonglong2*)&xs[l * 64 + half * 32];
        #pragma unroll
        for (int q = 0; q < 8; q++) {
            ulonglong2 v = xl[q];
            acc2[2 * q]     = ffma2(bwp, v.x, acc2[2 * q]);
            acc2[2 * q + 1] = ffma2(bwp, v.y, acc2[2 * q + 1]);
        }
    }
    ulonglong2* dst = (ulonglong2*)&g_states[(size_t)blk * 8192 + n * 64 + half * 32];
    #pragma unroll
    for (int q = 0; q < 8; q++) {
        ulonglong2 v; v.x = acc2[2 * q]; v.y = acc2[2 * q + 1];
        dst[q] = v;
    }
}

// ---------------- sequential chunk scan (parallelized over e-chunks) ----------------
__global__ void k_scan() {
    int bx = blockIdx.x;
    int e8 = bx & 7;
    int bh = bx >> 3;
    int b = bh >> 4, h = bh & 15;
    int e = e8 * 1024 + threadIdx.x;
    for (int k = 0; k < 4; k++, e += 256) {
        float acc = 0.f;
        #pragma unroll
        for (int c = 0; c < NCHUNK; c++) {
            int blk = ((b * NCHUNK + c) << 4) + h;
            g_prev[(size_t)blk * 8192 + e] = acc;
            float cd = expf(g_acs[blk * 128 + 127]);
            acc = cd * acc + g_states[(size_t)blk * 8192 + e];
        }
    }
}

// ---------------- fused SSD output v3: 512 threads, 4-way split, G from gmem ----------------
#define CPAD 132
__global__ void __launch_bounds__(512, 1) k_y(const float* __restrict__ D_head) {
    extern __shared__ __align__(16) float sh[];
    float* Cs   = sh;                 // 128*CPAD
    float* xs   = Cs + 128 * CPAD;    // 128*64
    float* ps   = xs + 8192;          // 128*64
    float* acs_s = ps + 8192;         // 128
    float* dt_s  = acs_s + 128;       // 128
    int blk = blockIdx.x, tid = threadIdx.x;
    int i = tid & 127, q4 = tid >> 7;
    int h = blk & 15, c = (blk >> 4) & 15, b = blk >> 8;
    int base = b * SEQ + c * CHUNK;
    const float* Grow = &g_G[(size_t)(blk >> 4) * 16384 + i * 128];

    for (int q = tid; q < 16384; q += 512) {
        int l = q >> 7, n = q & 127;
        Cs[l * CPAD + n] = g_xbc[(size_t)(base + l) * CONVDIM + DINNER + DSTATE + n];
    }
    for (int q = tid; q < 8192; q += 512) {
        int l = q >> 6, p = q & 63;
        xs[q] = g_xbc[(size_t)(base + l) * CONVDIM + h * 64 + p];
    }
    {
        const float4* src = (const float4*)&g_prev[(size_t)blk * 8192];
        float4* d = (float4*)ps;
        for (int q = tid; q < 2048; q += 512) d[q] = src[q];
    }
    if (tid < 128) {
        acs_s[tid] = g_acs[blk * 128 + tid];
        dt_s[tid]  = g_dt[blk * 128 + tid];
    }
    __syncthreads();

    ull y2[32];
    #pragma unroll
    for (int q = 0; q < 32; q++) y2[q] = 0ull;
    float ai = acs_s[i];

    for (int j = q4; j <= i; j += 4) {
        float g = expf(ai - acs_s[j]) * dt_s[j] * Grow[j];
        ull gp = pk(g);
        const ulonglong2* xj = (const ulonglong2*)&xs[j * 64];
        #pragma unroll
        for (int q = 0; q < 16; q++) {
            ulonglong2 v = xj[q];
            y2[2 * q]     = ffma2(gp, v.x, y2[2 * q]);
            y2[2 * q + 1] = ffma2(gp, v.y, y2[2 * q + 1]);
        }
    }

    float e = expf(ai);
    for (int pi = (q4 >> 1); pi < 64; pi += 2) {
        int n = 2 * pi + (q4 & 1);
        float cv = Cs[i * CPAD + n];
        ull c0 = pk(e * cv);
        const ulonglong2* p0 = (const ulonglong2*)&ps[n * 64];
        #pragma unroll
        for (int r = 0; r < 16; r++) {
            ulonglong2 v0 = p0[r];
            y2[2 * r]     = ffma2(c0, v0.x, y2[2 * r]);
            y2[2 * r + 1] = ffma2(c0, v0.y, y2[2 * r + 1]);
        }
    }

    if (q4 == 0) {
        float dh = D_head[h];
        ull dhp = pk(dh);
        const ulonglong2* xi = (const ulonglong2*)&xs[i * 64];
        #pragma unroll
        for (int q = 0; q < 16; q++) {
            ulonglong2 v = xi[q];
            y2[2 * q]     = ffma2(dhp, v.x, y2[2 * q]);
            y2[2 * q + 1] = ffma2(dhp, v.y, y2[2 * q + 1]);
        }
    }

    __syncthreads();
    if (q4 == 1) {
        ulonglong2* st = (ulonglong2*)&xs[i * 64];
        #pragma unroll
        for (int q = 0; q < 16; q++) { ulonglong2 v; v.x = y2[2 * q]; v.y = y2[2 * q + 1]; st[q] = v; }
    } else if (q4 == 2) {
        ulonglong2* st = (ulonglong2*)&Cs[i * 64];
        #pragma unroll
        for (int q = 0; q < 16; q++) { ulonglong2 v; v.x = y2[2 * q]; v.y = y2[2 * q + 1]; st[q] = v; }
    } else if (q4 == 3) {
        ulonglong2* st = (ulonglong2*)&Cs[8192 + i * 64];
        #pragma unroll
        for (int q = 0; q < 16; q++) { ulonglong2 v; v.x = y2[2 * q]; v.y = y2[2 * q + 1]; st[q] = v; }
    }
    __syncthreads();
    if (q4 == 0) {
        const ulonglong2* s1 = (const ulonglong2*)&xs[i * 64];
        const ulonglong2* s2 = (const ulonglong2*)&Cs[i * 64];
        const ulonglong2* s3 = (const ulonglong2*)&Cs[8192 + i * 64];
        ull one = pk(1.f);
        #pragma unroll
        for (int q = 0; q < 16; q++) {
            ulonglong2 v1 = s1[q], v2 = s2[q], v3 = s3[q];
            y2[2 * q]     = ffma2(one, v1.x, y2[2 * q]);
            y2[2 * q + 1] = ffma2(one, v1.y, y2[2 * q + 1]);
            y2[2 * q]     = ffma2(one, v2.x, y2[2 * q]);
            y2[2 * q + 1] = ffma2(one, v2.y, y2[2 * q + 1]);
            y2[2 * q]     = ffma2(one, v3.x, y2[2 * q]);
            y2[2 * q + 1] = ffma2(one, v3.y, y2[2 * q + 1]);
        }
        ulonglong2* dst = (ulonglong2*)&g_y[(size_t)(base + i) * DINNER + h * 64];
        #pragma unroll
        for (int q = 0; q < 16; q++) {
            ulonglong2 v; v.x = y2[2 * q]; v.y = y2[2 * q + 1];
            dst[q] = v;
        }
    }
}

// ---------------- gate with silu(z) + RMSNorm * norm_w -> fp16x2 A operand ----------------
__global__ void k_gate(const float* __restrict__ norm_w, __half* __restrict__ out2) {
    __shared__ float red[64];
    int t = blockIdx.x, tid = threadIdx.x;
    float v[4]; float ss = 0.f, dummy = 0.f;
    #pragma unroll
    for (int k = 0; k < 4; k++) {
        int d = tid + k * 256;
        float yv = g_y[(size_t)t * DINNER + d];
        float zv = g_zx[(size_t)t * DINPROJ + d];
        float sv = yv * (zv / (1.f + expf(-zv)));
        v[k] = sv; ss += sv * sv;
    }
    blockReduce2(ss, dummy, red);
    float sc = rsqrtf(ss * (1.f / 1024.f) + EPSF);
    __half* row = out2 + (size_t)t * 2 * DINNER;
    #pragma unroll
    for (int k = 0; k < 4; k++) {
        int d = tid + k * 256;
        f16x2_store_scalar(row, DINNER, d, v[k] * sc * norm_w[d]);
    }
}

// ---------------- out = LayerNorm(a + b) * w + beta (D=512), optional fp16x2 copy ----------------
__global__ void k_addln(const float* __restrict__ a, const float* __restrict__ bsrc,
                        const float* __restrict__ w, const float* __restrict__ beta,
                        float* __restrict__ o, __half* __restrict__ out2) {
    __shared__ float red[64];
    int t = blockIdx.x, tid = threadIdx.x;
    float v[4]; float s = 0.f, ssq = 0.f;
    #pragma unroll
    for (int k = 0; k < 4; k++) {
        int d = tid + k * 128;
        float x = a[(size_t)t * DMODEL + d] + bsrc[(size_t)t * DMODEL + d];
        v[k] = x; s += x; ssq += x * x;
    }
    blockReduce2(s, ssq, red);
    float mean = s * (1.f / 512.f);
    float var = ssq * (1.f / 512.f) - mean * mean;
    float inv = rsqrtf(var + EPSF);
    #pragma unroll
    for (int k = 0; k < 4; k++) {
        int d = tid + k * 128;
        float r = (v[k] - mean) * inv * w[d] + beta[d];
        o[(size_t)t * DMODEL + d] = r;
        if (out2) f16x2_store_scalar(out2 + (size_t)t * 2 * DMODEL, DMODEL, d, r);
    }
}

// ---------------- launch ----------------
static inline void splitA(const float* src, __half* dst, int M, int K) {
    k_split2<0><<<(int)(((size_t)M * K / 4) / 256), 256>>>(src, dst, K);
}
static inline void splitW(const float* src, __half* dst, int M, int K) {
    k_split2<1><<<(int)(((size_t)M * K / 4) / 256), 256>>>(src, dst, K);
}

extern "C" void kernel_launch(void* const* d_in, const int* in_sizes, int n_in,
                              void* d_out, int out_size) {
    const float* tgt        = (const float*)d_in[0];
    const float* in_proj_w  = (const float*)d_in[5];
    const float* conv_w     = (const float*)d_in[6];
    const float* conv_b     = (const float*)d_in[7];
    const float* dt_bias    = (const float*)d_in[8];
    const float* A_log      = (const float*)d_in[9];
    const float* D_head     = (const float*)d_in[10];
    const float* norm_w     = (const float*)d_in[11];
    const float* out_proj_w = (const float*)d_in[12];
    const float* n1w = (const float*)d_in[13];
    const float* n1b = (const float*)d_in[14];
    const float* w1  = (const float*)d_in[15];
    const float* b1  = (const float*)d_in[16];
    const float* w2  = (const float*)d_in[17];
    const float* b2  = (const float*)d_in[18];
    const float* n3w = (const float*)d_in[19];
    const float* n3b = (const float*)d_in[20];
    float* out = (float*)d_out;

    float *zx, *mo, *tb, *f2;
    __half *A2, *A2b, *W2;
    cudaGetSymbolAddress((void**)&zx,   g_zx);
    cudaGetSymbolAddress((void**)&mo,   g_mo);
    cudaGetSymbolAddress((void**)&tb,   g_t);
    cudaGetSymbolAddress((void**)&f2,   g_f2);
    cudaGetSymbolAddress((void**)&A2,   g_A2);
    cudaGetSymbolAddress((void**)&A2b,  g_A2b);
    cudaGetSymbolAddress((void**)&W2,   g_W2);

    const int smem_states = (16384 + 8192 + 128) * 4;
    const int smem_y = (128 * CPAD + 8192 + 8192 + 256) * 4;
    const int smem_g = 4 * 128 * GP * 2;
    cudaFuncSetAttribute(k_states, cudaFuncAttributeMaxDynamicSharedMemorySize, smem_states);
    cudaFuncSetAttribute(k_y,      cudaFuncAttributeMaxDynamicSharedMemorySize, smem_y);
    cudaFuncSetAttribute(k_G,      cudaFuncAttributeMaxDynamicSharedMemorySize, smem_g);

    // 1. in_proj: zx = tgt @ in_proj_w^T
    splitA(tgt, A2, TOK, DMODEL);
    splitW(in_proj_w, W2, DINPROJ, DMODEL);
    k_gemm_f16<0, 0><<<dim3((DINPROJ + 127) / 128, TOK / 128), 256>>>(A2, W2, nullptr, zx, DINPROJ, 2 * DMODEL);
    // 2. conv + silu
    k_conv<<<(TOK / 4 * CONVDIM) / 256, 256>>>(conv_w, conv_b);
    // 3. dt softplus + cumsum
    k_dtscan<<<NBLK, 128>>>(dt_bias, A_log);
    // 4. shared score matrices G = C @ B^T (per (b,c))
    k_G<<<NGC, 256, smem_g>>>();
    // 5. chunk end-states
    k_states<<<NBLK, 256, smem_states>>>();
    // 6. chunk scan -> prev
    k_scan<<<BATCH * NHEADS * 8, 256>>>();
    // 7. fused SSD output
    k_y<<<NBLK, 512, smem_y>>>(D_head);
    // 8. gate + rmsnorm -> fp16x2 directly
    k_gate<<<TOK, 256>>>(norm_w, A2);
    // 9. out_proj: mo = gate @ out_proj_w^T
    splitW(out_proj_w, W2, DMODEL, DINNER);
    k_gemm_f16<0, 0><<<dim3(DMODEL / 128, TOK / 128), 256>>>(A2, W2, nullptr, mo, DMODEL, 2 * DINNER);
    // 10. t = LN(tgt + mo), also emit fp16x2 for FFN GEMM
    k_addln<<<TOK, 128>>>(tgt, mo, n1w, n1b, tb, A2);
    // 11. f1 = gelu(t @ w1^T + b1) -> fp16x2 directly
    splitW(w1, W2, FF, DMODEL);
    k_gemm_f16<1, 1><<<dim3(FF / 128, TOK / 128), 256>>>(A2, W2, b1, A2b, FF, 2 * DMODEL);
    // 12. f2 = f1 @ w2^T + b2
    splitW(w2, W2, DMODEL, FF);
    k_gemm_f16<0, 0><<<dim3(DMODEL / 128, TOK / 128), 256>>>(A2b, W2, b2, f2, DMODEL, 2 * FF);
    // 13. out = LN(t + f2)
    k_addln<<<TOK, 128>>>(tb, f2, n3w, n3b, out, nullptr);
}

// round 14
// speedup vs baseline: 3.2442x; 1.1659x over previous
#include <cuda_runtime.h>
#include <cuda_bf16.h>
#include <cuda_fp16.h>
#include <math.h>
#include <cstdint>

// ---------------- problem constants ----------------
#define BATCH 8
#define SEQ 2048
#define TOK (BATCH*SEQ)          // 16384
#define DMODEL 512
#define DINNER 1024
#define DSTATE 128
#define NHEADS 16
#define HEADDIM 64
#define CONVDIM 1280
#define DINPROJ 2320
#define FF 2048
#define CHUNK 128
#define NCHUNK (SEQ/CHUNK)       // 16
#define NBLK (BATCH*NCHUNK*NHEADS) // 2048
#define NGC (BATCH*NCHUNK)       // 128
#define EPSF 1e-5f

#define MMA_F16(cc, aa, b0, b1) \
    asm volatile("mma.sync.aligned.m16n8k16.row.col.f32.f16.f16.f32 " \
        "{%0,%1,%2,%3},{%4,%5,%6,%7},{%8,%9},{%0,%1,%2,%3};" \
        : "+f"(cc[0]), "+f"(cc[1]), "+f"(cc[2]), "+f"(cc[3]) \
        : "r"(aa[0]), "r"(aa[1]), "r"(aa[2]), "r"(aa[3]), "r"(b0), "r"(b1))

#define MMA_BF16(cc, aa, b0, b1) \
    asm volatile("mma.sync.aligned.m16n8k16.row.col.f32.bf16.bf16.f32 " \
        "{%0,%1,%2,%3},{%4,%5,%6,%7},{%8,%9},{%0,%1,%2,%3};" \
        : "+f"(cc[0]), "+f"(cc[1]), "+f"(cc[2]), "+f"(cc[3]) \
        : "r"(aa[0]), "r"(aa[1]), "r"(aa[2]), "r"(aa[3]), "r"(b0), "r"(b1))

#define LDSM_X4(r, addr) \
    asm volatile("ldmatrix.sync.aligned.m8n8.x4.shared.b16 {%0,%1,%2,%3},[%4];" \
        : "=r"((r)[0]), "=r"((r)[1]), "=r"((r)[2]), "=r"((r)[3]) : "r"(addr))

#define LDSM_X4T(r, addr) \
    asm volatile("ldmatrix.sync.aligned.m8n8.x4.trans.shared.b16 {%0,%1,%2,%3},[%4];" \
        : "=r"((r)[0]), "=r"((r)[1]), "=r"((r)[2]), "=r"((r)[3]) : "r"(addr))

#define CP_ASYNC16(dst, src) \
    asm volatile("cp.async.cg.shared.global [%0], [%1], 16;" :: "r"(dst), "l"(src))
#define CP_COMMIT() asm volatile("cp.async.commit_group;" ::: "memory")
#define CP_WAIT2()  asm volatile("cp.async.wait_group 2;" ::: "memory")
#define CP_WAIT0()  asm volatile("cp.async.wait_group 0;" ::: "memory")

// ---------------- scratch ----------------
__device__ __align__(16) float g_zx[TOK*DINPROJ];
__device__ __align__(16) float g_xbc[TOK*CONVDIM];
__device__ __align__(16) float g_dt[NBLK*CHUNK];
__device__ __align__(16) float g_acs[NBLK*CHUNK];
__device__ __align__(16) float g_states[(size_t)NBLK*DSTATE*HEADDIM];
__device__ __align__(16) float g_prev[(size_t)NBLK*DSTATE*HEADDIM];
__device__ __align__(16) float g_y[(size_t)TOK*DINNER];
__device__ __align__(16) float g_mo[(size_t)TOK*DMODEL];
__device__ __align__(16) float g_t[(size_t)TOK*DMODEL];
__device__ __align__(16) float g_f2[(size_t)TOK*DMODEL];
__device__ __align__(16) float g_G[(size_t)NGC*CHUNK*CHUNK];
// fp16x2 expanded operands
__device__ __align__(16) __half g_A2[(size_t)TOK*2*DINNER];
__device__ __align__(16) __half g_A2b[(size_t)TOK*2*FF];
__device__ __align__(16) __half g_W2[DINPROJ*2*DMODEL];

// ---------------- helpers ----------------
__device__ __forceinline__ void blockReduce2(float& a, float& b, float* sh) {
    int lane = threadIdx.x & 31, w = threadIdx.x >> 5;
    #pragma unroll
    for (int o = 16; o; o >>= 1) {
        a += __shfl_xor_sync(0xffffffffu, a, o);
        b += __shfl_xor_sync(0xffffffffu, b, o);
    }
    if (lane == 0) { sh[w] = a; sh[32 + w] = b; }
    __syncthreads();
    int nw = blockDim.x >> 5;
    if (w == 0) {
        a = (lane < nw) ? sh[lane] : 0.f;
        b = (lane < nw) ? sh[32 + lane] : 0.f;
        #pragma unroll
        for (int o = 16; o; o >>= 1) {
            a += __shfl_xor_sync(0xffffffffu, a, o);
            b += __shfl_xor_sync(0xffffffffu, b, o);
        }
        if (lane == 0) { sh[0] = a; sh[32] = b; }
    }
    __syncthreads();
    a = sh[0]; b = sh[32];
}

__device__ __forceinline__ void f16x2_store_scalar(__half* row, int K, int d, float s) {
    __half hi = __float2half_rn(s);
    __half lo = __float2half_rn(s - __half2float(hi));
    row[d] = hi; row[K + d] = lo;
}

__device__ __forceinline__ void split4(float4 v, __half* hi, __half* lo, int o) {
    __half2 h0, h1, l0, l1;
    h0.x = __float2half_rn(v.x); h0.y = __float2half_rn(v.y);
    h1.x = __float2half_rn(v.z); h1.y = __float2half_rn(v.w);
    l0.x = __float2half_rn(v.x - __half2float(h0.x));
    l0.y = __float2half_rn(v.y - __half2float(h0.y));
    l1.x = __float2half_rn(v.z - __half2float(h1.x));
    l1.y = __float2half_rn(v.w - __half2float(h1.y));
    *(__half2*)&hi[o] = h0; *(__half2*)&hi[o + 2] = h1;
    *(__half2*)&lo[o] = l0; *(__half2*)&lo[o + 2] = l1;
}

// ---------------- fp16x2 split: src[M,K] fp32 -> dst[M,2K] f16 (hi | DUP?hi:lo) ----------------
template<int DUP>
__global__ void k_split2(const float* __restrict__ src, __half* __restrict__ dst, int K) {
    size_t i = (size_t)blockIdx.x * 256 + threadIdx.x;
    int K4 = K >> 2;
    size_t row = i / K4;
    int c4 = (int)(i % K4);
    float4 v = ((const float4*)src)[i];
    __half2 h0, h1, l0, l1;
    h0.x = __float2half_rn(v.x); h0.y = __float2half_rn(v.y);
    h1.x = __float2half_rn(v.z); h1.y = __float2half_rn(v.w);
    l0.x = __float2half_rn(v.x - __half2float(h0.x));
    l0.y = __float2half_rn(v.y - __half2float(h0.y));
    l1.x = __float2half_rn(v.z - __half2float(h1.x));
    l1.y = __float2half_rn(v.w - __half2float(h1.y));
    __half2* d = (__half2*)(dst + row * 2 * K);
    int c2 = c4 * 2;
    int K2 = K >> 1;
    d[c2] = h0; d[c2 + 1] = h1;
    d[K2 + c2]     = DUP ? h0 : l0;
    d[K2 + c2 + 1] = DUP ? h1 : l1;
}

// ---------------- fp16 tensor-core GEMM, 4-stage cp.async, single-sync mainloop ----------------
#define SPITCH 40
#define NSTG 4
template<int ACT, int OUT2>
__global__ void __launch_bounds__(256) k_gemm_f16(const __half* __restrict__ A,
                                                  const __half* __restrict__ W,
                                                  const float* __restrict__ bias,
                                                  void* __restrict__ Cout,
                                                  int N, int K2) {
    __shared__ __align__(16) __half As[NSTG][128][SPITCH];
    __shared__ __align__(16) __half Ws[NSTG][128][SPITCH];
    int tid = threadIdx.x;
    int bm = blockIdx.y * 128, bn = blockIdx.x * 128;
    int lr = tid >> 1, lc = (tid & 1) * 16;
    int lane = tid & 31, wid = tid >> 5;
    int wm = (wid & 3) * 32, wn = (wid >> 2) * 64;
    int g = lane >> 2, t4 = lane & 3;

    float c[2][8][4];
    #pragma unroll
    for (int mi = 0; mi < 2; mi++)
        #pragma unroll
        for (int ni = 0; ni < 8; ni++)
            #pragma unroll
            for (int q = 0; q < 4; q++) c[mi][ni][q] = 0.f;

    const __half* Aptr = A + (size_t)(bm + lr) * K2 + lc;
    int wr = bn + lr; if (wr >= N) wr = N - 1;
    const __half* Wptr = W + (size_t)wr * K2 + lc;

    uint32_t sbA = (uint32_t)__cvta_generic_to_shared(&As[0][0][0]);
    uint32_t sbW = (uint32_t)__cvta_generic_to_shared(&Ws[0][0][0]);
    const uint32_t bufStride = 128 * SPITCH * 2;
    uint32_t dOff = (uint32_t)((lr * SPITCH + lc) * 2);

    int l7 = lane & 7;
    int aRow = wm + ((lane >> 3) & 1) * 8 + l7;
    int aCol = (lane >> 4) * 8;
    int bRow = wn + (lane >> 4) * 8 + l7;
    int bCol = ((lane >> 3) & 1) * 8;

    int KT = K2 / 32;

    #pragma unroll
    for (int s = 0; s < NSTG - 1; s++) {
        if (s < KT) {
            const __half* ap = Aptr + s * 32;
            const __half* wp = Wptr + s * 32;
            uint32_t da = sbA + s * bufStride + dOff;
            uint32_t dw = sbW + s * bufStride + dOff;
            CP_ASYNC16(da, ap); CP_ASYNC16(da + 16, ap + 8);
            CP_ASYNC16(dw, wp); CP_ASYNC16(dw + 16, wp + 8);
        }
        CP_COMMIT();
    }

    for (int kt = 0; kt < KT; kt++) {
        CP_WAIT2();
        __syncthreads();

        int cur = kt & (NSTG - 1);
        uint32_t aBase = sbA + cur * bufStride;
        uint32_t wBase = sbW + cur * bufStride;
        #pragma unroll
        for (int kk = 0; kk < 32; kk += 16) {
            uint32_t af[2][4], bf[4][4];
            #pragma unroll
            for (int mi = 0; mi < 2; mi++) {
                uint32_t addr = aBase + (uint32_t)(((aRow + mi * 16) * SPITCH + aCol + kk) * 2);
                LDSM_X4(af[mi], addr);
            }
            #pragma unroll
            for (int q = 0; q < 4; q++) {
                uint32_t addr = wBase + (uint32_t)(((bRow + q * 16) * SPITCH + bCol + kk) * 2);
                LDSM_X4(bf[q], addr);
            }
            #pragma unroll
            for (int q = 0; q < 4; q++) {
                MMA_F16(c[0][2 * q],     af[0], bf[q][0], bf[q][1]);
                MMA_F16(c[1][2 * q],     af[1], bf[q][0], bf[q][1]);
                MMA_F16(c[0][2 * q + 1], af[0], bf[q][2], bf[q][3]);
                MMA_F16(c[1][2 * q + 1], af[1], bf[q][2], bf[q][3]);
            }
        }
        {
            int s = kt + NSTG - 1;
            if (s < KT) {
                const __half* ap = Aptr + s * 32;
                const __half* wp = Wptr + s * 32;
                uint32_t da = sbA + (s & (NSTG - 1)) * bufStride + dOff;
                uint32_t dw = sbW + (s & (NSTG - 1)) * bufStride + dOff;
                CP_ASYNC16(da, ap); CP_ASYNC16(da + 16, ap + 8);
                CP_ASYNC16(dw, wp); CP_ASYNC16(dw + 16, wp + 8);
            }
            CP_COMMIT();
        }
    }
    CP_WAIT0();

    #pragma unroll
    for (int mi = 0; mi < 2; mi++) {
        int r0 = bm + wm + mi * 16 + g;
        #pragma unroll
        for (int ni = 0; ni < 8; ni++) {
            int col = bn + wn + ni * 8 + 2 * t4;
            #pragma unroll
            for (int half = 0; half < 2; half++) {
                int r = r0 + half * 8;
                float v0 = c[mi][ni][half * 2 + 0];
                float v1 = c[mi][ni][half * 2 + 1];
                if (bias) { v0 += bias[col]; v1 += bias[col + 1]; }
                if (ACT == 1) {
                    v0 = 0.5f * v0 * (1.f + erff(v0 * 0.70710678118654752f));
                    v1 = 0.5f * v1 * (1.f + erff(v1 * 0.70710678118654752f));
                }
                if (OUT2) {
                    __half* O = (__half*)Cout;
                    __half2 hi, lo;
                    hi.x = __float2half_rn(v0); hi.y = __float2half_rn(v1);
                    lo.x = __float2half_rn(v0 - __half2float(hi.x));
                    lo.y = __float2half_rn(v1 - __half2float(hi.y));
                    size_t base = (size_t)r * 2 * N + col;
                    *(__half2*)&O[base]     = hi;
                    *(__half2*)&O[base + N] = lo;
                } else {
                    float* Cf = (float*)Cout;
                    if (col + 1 < N) {
                        float2 v; v.x = v0; v.y = v1;
                        *(float2*)&Cf[(size_t)r * N + col] = v;
                    } else if (col < N) {
                        Cf[(size_t)r * N + col] = v0;
                    }
                }
            }
        }
    }
}

// ---------------- k_G: per (b,c) score matrix G = C @ B^T via MMA (bf16 hi/lo 3-term) ----------------
#define GP 136
__global__ void __launch_bounds__(256) k_G() {
    extern __shared__ __align__(16) char sg[];
    __nv_bfloat16* Chi = (__nv_bfloat16*)sg;
    __nv_bfloat16* Clo = Chi + 128 * GP;
    __nv_bfloat16* Bhi = Clo + 128 * GP;
    __nv_bfloat16* Blo = Bhi + 128 * GP;
    int tid = threadIdx.x, lane = tid & 31, wid = tid >> 5;
    int blk = blockIdx.x;
    int base = blk * 128;
    int wm = (wid & 3) * 32, wn = (wid >> 2) * 64;
    int g = lane >> 2, t4 = lane & 3;

    for (int q = tid; q < 4096; q += 256) {
        int row = q >> 5, c4 = (q & 31) * 4;
        const float* rp = &g_xbc[(size_t)(base + row) * CONVDIM + DINNER];
        float4 vB = *(const float4*)(rp + c4);
        float4 vC = *(const float4*)(rp + DSTATE + c4);
        __nv_bfloat162 h, l;
        int o = row * GP + c4;
        h.x = __float2bfloat16_rn(vC.x); h.y = __float2bfloat16_rn(vC.y);
        l.x = __float2bfloat16_rn(vC.x - __bfloat162float(h.x));
        l.y = __float2bfloat16_rn(vC.y - __bfloat162float(h.y));
        *(__nv_bfloat162*)&Chi[o] = h; *(__nv_bfloat162*)&Clo[o] = l;
        h.x = __float2bfloat16_rn(vC.z); h.y = __float2bfloat16_rn(vC.w);
        l.x = __float2bfloat16_rn(vC.z - __bfloat162float(h.x));
        l.y = __float2bfloat16_rn(vC.w - __bfloat162float(h.y));
        *(__nv_bfloat162*)&Chi[o + 2] = h; *(__nv_bfloat162*)&Clo[o + 2] = l;
        h.x = __float2bfloat16_rn(vB.x); h.y = __float2bfloat16_rn(vB.y);
        l.x = __float2bfloat16_rn(vB.x - __bfloat162float(h.x));
        l.y = __float2bfloat16_rn(vB.y - __bfloat162float(h.y));
        *(__nv_bfloat162*)&Bhi[o] = h; *(__nv_bfloat162*)&Blo[o] = l;
        h.x = __float2bfloat16_rn(vB.z); h.y = __float2bfloat16_rn(vB.w);
        l.x = __float2bfloat16_rn(vB.z - __bfloat162float(h.x));
        l.y = __float2bfloat16_rn(vB.w - __bfloat162float(h.y));
        *(__nv_bfloat162*)&Bhi[o + 2] = h; *(__nv_bfloat162*)&Blo[o + 2] = l;
    }
    __syncthreads();

    uint32_t bChi = (uint32_t)__cvta_generic_to_shared(Chi);
    uint32_t bClo = (uint32_t)__cvta_generic_to_shared(Clo);
    uint32_t bBhi = (uint32_t)__cvta_generic_to_shared(Bhi);
    uint32_t bBlo = (uint32_t)__cvta_generic_to_shared(Blo);

    int l7 = lane & 7;
    int aRow = wm + ((lane >> 3) & 1) * 8 + l7;
    int aCol = (lane >> 4) * 8;
    int bRow = wn + (lane >> 4) * 8 + l7;
    int bCol = ((lane >> 3) & 1) * 8;

    float c[2][8][4];
    #pragma unroll
    for (int mi = 0; mi < 2; mi++)
        #pragma unroll
        for (int ni = 0; ni < 8; ni++)
            #pragma unroll
            for (int q = 0; q < 4; q++) c[mi][ni][q] = 0.f;

    #pragma unroll
    for (int term = 0; term < 3; term++) {
        uint32_t aB = (term == 2) ? bClo : bChi;
        uint32_t bB = (term == 1) ? bBlo : bBhi;
        #pragma unroll
        for (int kk = 0; kk < 128; kk += 16) {
            uint32_t af[2][4], bf[4][4];
            #pragma unroll
            for (int mi = 0; mi < 2; mi++) {
                uint32_t addr = aB + (uint32_t)(((aRow + mi * 16) * GP + aCol + kk) * 2);
                LDSM_X4(af[mi], addr);
            }
            #pragma unroll
            for (int q = 0; q < 4; q++) {
                uint32_t addr = bB + (uint32_t)(((bRow + q * 16) * GP + bCol + kk) * 2);
                LDSM_X4(bf[q], addr);
            }
            #pragma unroll
            for (int q = 0; q < 4; q++) {
                MMA_BF16(c[0][2 * q],     af[0], bf[q][0], bf[q][1]);
                MMA_BF16(c[1][2 * q],     af[1], bf[q][0], bf[q][1]);
                MMA_BF16(c[0][2 * q + 1], af[0], bf[q][2], bf[q][3]);
                MMA_BF16(c[1][2 * q + 1], af[1], bf[q][2], bf[q][3]);
            }
        }
    }

    float* Gout = &g_G[(size_t)blk * 16384];
    #pragma unroll
    for (int mi = 0; mi < 2; mi++) {
        int r0 = wm + mi * 16 + g;
        #pragma unroll
        for (int ni = 0; ni < 8; ni++) {
            int col = wn + ni * 8 + 2 * t4;
            #pragma unroll
            for (int half = 0; half < 2; half++) {
                int r = r0 + half * 8;
                float2 v; v.x = c[mi][ni][half * 2]; v.y = c[mi][ni][half * 2 + 1];
                *(float2*)&Gout[r * 128 + col] = v;
            }
        }
    }
}

// ---------------- shared MMA pass for SSD kernels ----------------
#define BP 136
#define XP 72
// TRANSA=0: A row-major [m][k] pitch BP (normal LDSM). TRANSA=1: A stored [k][m] pitch BP (trans LDSM).
// B always stored [k][p] pitch XP, consumed via trans LDSM. M=16 per warp (offset wm), N=64, K=128.
// 3-term fp16 compensation: (hiA,hiB), (loA,hiB), (hiA,loB).
template<int TRANSA>
__device__ __forceinline__ void ssd_pass(uint32_t aHi, uint32_t aLo, uint32_t xHi, uint32_t xLo,
                                         int wm, int lane, float cacc[8][4]) {
    int l7 = lane & 7;
    int aRow = wm + ((lane >> 3) & 1) * 8 + l7;       // normal A
    int aCol = (lane >> 4) * 8;
    int tL = (lane >> 4) * 8 + l7;                    // trans A
    int tN = ((lane >> 3) & 1) * 8;
    int bL = ((lane >> 3) & 1) * 8 + l7;              // trans B
    int bP = (lane >> 4) * 8;
    #pragma unroll
    for (int term = 0; term < 3; term++) {
        uint32_t aB = (term == 1) ? aLo : aHi;
        uint32_t bB = (term == 2) ? xLo : xHi;
        #pragma unroll
        for (int k0 = 0; k0 < 128; k0 += 16) {
            uint32_t af[4];
            if (TRANSA) {
                LDSM_X4T(af, aB + (uint32_t)(((k0 + tL) * BP + wm + tN) * 2));
            } else {
                LDSM_X4(af, aB + (uint32_t)((aRow * BP + k0 + aCol) * 2));
            }
            #pragma unroll
            for (int q = 0; q < 4; q++) {
                uint32_t bf[4];
                LDSM_X4T(bf, bB + (uint32_t)(((k0 + bL) * XP + q * 16 + bP) * 2));
                MMA_F16(cacc[2 * q],     af, bf[0], bf[1]);
                MMA_F16(cacc[2 * q + 1], af, bf[2], bf[3]);
            }
        }
    }
}

// ---------------- causal depthwise conv1d + silu (4 s-positions/thread) ----------------
__global__ void k_conv(const float* __restrict__ conv_w, const float* __restrict__ conv_b) {
    int idx = blockIdx.x * 256 + threadIdx.x;
    int ch = idx % CONVDIM;
    int r  = idx / CONVDIM;
    int s4 = r % (SEQ / 4);
    int b  = r / (SEQ / 4);
    int s0 = s4 * 4;
    float w0 = conv_w[ch * 4], w1 = conv_w[ch * 4 + 1], w2 = conv_w[ch * 4 + 2], w3 = conv_w[ch * 4 + 3];
    float bias = conv_b[ch];
    float in[7];
    #pragma unroll
    for (int k = 0; k < 7; k++) {
        int sp = s0 + k - 3;
        in[k] = (sp >= 0) ? g_zx[(size_t)(b * SEQ + sp) * DINPROJ + DINNER + ch] : 0.f;
    }
    #pragma unroll
    for (int s = 0; s < 4; s++) {
        float acc = bias + in[s] * w0 + in[s + 1] * w1 + in[s + 2] * w2 + in[s + 3] * w3;
        acc = acc / (1.f + expf(-acc));
        g_xbc[(size_t)(b * SEQ + s0 + s) * CONVDIM + ch] = acc;
    }
}

// ---------------- dt softplus + per-chunk cumulative log-decay ----------------
__global__ void k_dtscan(const float* __restrict__ dt_bias, const float* __restrict__ A_log) {
    __shared__ float s[128];
    int blk = blockIdx.x, l = threadIdx.x;
    int h = blk & 15, c = (blk >> 4) & 15, b = blk >> 8;
    int tok = b * SEQ + c * CHUNK + l;
    float raw = g_zx[(size_t)tok * DINPROJ + 2304 + h] + dt_bias[h];
    float dtv = (raw > 20.f) ? raw : log1pf(expf(raw));
    float A = -expf(A_log[h]);
    g_dt[blk * 128 + l] = dtv;
    s[l] = dtv * A;
    __syncthreads();
    #pragma unroll
    for (int off = 1; off < 128; off <<= 1) {
        float t = (l >= off) ? s[l - off] : 0.f;
        __syncthreads();
        s[l] += t;
        __syncthreads();
    }
    g_acs[blk * 128 + l] = s[l];
}

// ---------------- per-chunk end states via tensor cores ----------------
// states[n,p] = sum_l (B[l,n]*w[l]) * x[l,p]: A = Bw^T (trans), B = x (trans), fp16 3-term.
__global__ void __launch_bounds__(256) k_states() {
    extern __shared__ __align__(16) char sraw[];
    __half* Ahi = (__half*)sraw;            // Bw [l][n] 128*BP
    __half* Alo = Ahi + 128 * BP;
    __half* Xhi = Alo + 128 * BP;           // x [l][p] 128*XP
    __half* Xlo = Xhi + 128 * XP;
    float*  ws  = (float*)(Xlo + 128 * XP); // 128
    int tid = threadIdx.x, lane = tid & 31, wid = tid >> 5;
    int blk = blockIdx.x;
    int h = blk & 15, cc = (blk >> 4) & 15, b = blk >> 8;
    int base = b * SEQ + cc * CHUNK;

    if (tid < 128) {
        float acsL = g_acs[blk * 128 + 127];
        ws[tid] = expf(acsL - g_acs[blk * 128 + tid]) * g_dt[blk * 128 + tid];
    }
    __syncthreads();
    for (int q = tid; q < 4096; q += 256) {
        int l = q >> 5, n4 = (q & 31) * 4;
        float4 v = *(const float4*)&g_xbc[(size_t)(base + l) * CONVDIM + DINNER + n4];
        float w = ws[l];
        v.x *= w; v.y *= w; v.z *= w; v.w *= w;
        split4(v, Ahi, Alo, l * BP + n4);
    }
    for (int q = tid; q < 2048; q += 256) {
        int l = q >> 4, p4 = (q & 15) * 4;
        float4 v = *(const float4*)&g_xbc[(size_t)(base + l) * CONVDIM + h * 64 + p4];
        split4(v, Xhi, Xlo, l * XP + p4);
    }
    __syncthreads();

    uint32_t bAhi = (uint32_t)__cvta_generic_to_shared(Ahi);
    uint32_t bAlo = (uint32_t)__cvta_generic_to_shared(Alo);
    uint32_t bXhi = (uint32_t)__cvta_generic_to_shared(Xhi);
    uint32_t bXlo = (uint32_t)__cvta_generic_to_shared(Xlo);
    int wm = wid * 16;
    float cacc[8][4];
    #pragma unroll
    for (int ni = 0; ni < 8; ni++)
        #pragma unroll
        for (int q = 0; q < 4; q++) cacc[ni][q] = 0.f;

    ssd_pass<1>(bAhi, bAlo, bXhi, bXlo, wm, lane, cacc);

    int g = lane >> 2, t4 = lane & 3;
    float* d0 = &g_states[(size_t)blk * 8192 + (wm + g) * 64];
    float* d1 = d0 + 8 * 64;
    #pragma unroll
    for (int ni = 0; ni < 8; ni++) {
        int col = ni * 8 + 2 * t4;
        float2 v0; v0.x = cacc[ni][0]; v0.y = cacc[ni][1];
        float2 v1; v1.x = cacc[ni][2]; v1.y = cacc[ni][3];
        *(float2*)&d0[col] = v0;
        *(float2*)&d1[col] = v1;
    }
}

// ---------------- sequential chunk scan (parallelized over e-chunks) ----------------
__global__ void k_scan() {
    int bx = blockIdx.x;
    int e8 = bx & 7;
    int bh = bx >> 3;
    int b = bh >> 4, h = bh & 15;
    int e = e8 * 1024 + threadIdx.x;
    for (int k = 0; k < 4; k++, e += 256) {
        float acc = 0.f;
        #pragma unroll
        for (int c = 0; c < NCHUNK; c++) {
            int blk = ((b * NCHUNK + c) << 4) + h;
            g_prev[(size_t)blk * 8192 + e] = acc;
            float cd = expf(g_acs[blk * 128 + 127]);
            acc = cd * acc + g_states[(size_t)blk * 8192 + e];
        }
    }
}

// ---------------- fused SSD output via tensor cores ----------------
// Y = M@x + C~@prev + D*x, M[i,j] = causal exp(a_i-a_j) dt_j G[i,j], C~[i,n] = e^{a_i} C[i,n].
__global__ void __launch_bounds__(256) k_y(const float* __restrict__ D_head) {
    extern __shared__ __align__(16) char sraw[];
    __half* Ahi = (__half*)sraw;            // M then C~: 128*BP
    __half* Alo = Ahi + 128 * BP;
    __half* Xhi = Alo + 128 * BP;           // x then prev: 128*XP
    __half* Xlo = Xhi + 128 * XP;
    float* acs_s = (float*)(Xlo + 128 * XP);
    float* dt_s  = acs_s + 128;
    int tid = threadIdx.x, lane = tid & 31, wid = tid >> 5;
    int blk = blockIdx.x;
    int h = blk & 15, cc = (blk >> 4) & 15, b = blk >> 8;
    int base = b * SEQ + cc * CHUNK;
    size_t gbase = (size_t)(blk >> 4) * 16384;

    if (tid < 128) {
        acs_s[tid] = g_acs[blk * 128 + tid];
        dt_s[tid]  = g_dt[blk * 128 + tid];
    }
    __syncthreads();

    // build M and x
    for (int q = tid; q < 4096; q += 256) {
        int i = q >> 5, j4 = (q & 31) * 4;
        float4 gv = *(const float4*)&g_G[gbase + i * 128 + j4];
        float ai = acs_s[i];
        float4 m;
        m.x = (j4     <= i) ? expf(ai - acs_s[j4])     * dt_s[j4]     * gv.x : 0.f;
        m.y = (j4 + 1 <= i) ? expf(ai - acs_s[j4 + 1]) * dt_s[j4 + 1] * gv.y : 0.f;
        m.z = (j4 + 2 <= i) ? expf(ai - acs_s[j4 + 2]) * dt_s[j4 + 2] * gv.z : 0.f;
        m.w = (j4 + 3 <= i) ? expf(ai - acs_s[j4 + 3]) * dt_s[j4 + 3] * gv.w : 0.f;
        split4(m, Ahi, Alo, i * BP + j4);
    }
    for (int q = tid; q < 2048; q += 256) {
        int l = q >> 4, p4 = (q & 15) * 4;
        float4 v = *(const float4*)&g_xbc[(size_t)(base + l) * CONVDIM + h * 64 + p4];
        split4(v, Xhi, Xlo, l * XP + p4);
    }
    __syncthreads();

    uint32_t bAhi = (uint32_t)__cvta_generic_to_shared(Ahi);
    uint32_t bAlo = (uint32_t)__cvta_generic_to_shared(Alo);
    uint32_t bXhi = (uint32_t)__cvta_generic_to_shared(Xhi);
    uint32_t bXlo = (uint32_t)__cvta_generic_to_shared(Xlo);
    int wm = wid * 16;
    float cacc[8][4];
    #pragma unroll
    for (int ni = 0; ni < 8; ni++)
        #pragma unroll
        for (int q = 0; q < 4; q++) cacc[ni][q] = 0.f;

    // pass 1: Y_diag
    ssd_pass<0>(bAhi, bAlo, bXhi, bXlo, wm, lane, cacc);

    // D*x term from the still-resident x halves (error 2^-22)
    int g = lane >> 2, t4 = lane & 3;
    {
        float dh = D_head[h];
        int i0 = wm + g, i1 = i0 + 8;
        #pragma unroll
        for (int ni = 0; ni < 8; ni++) {
            int col = ni * 8 + 2 * t4;
            cacc[ni][0] += dh * (__half2float(Xhi[i0 * XP + col])     + __half2float(Xlo[i0 * XP + col]));
            cacc[ni][1] += dh * (__half2float(Xhi[i0 * XP + col + 1]) + __half2float(Xlo[i0 * XP + col + 1]));
            cacc[ni][2] += dh * (__half2float(Xhi[i1 * XP + col])     + __half2float(Xlo[i1 * XP + col]));
            cacc[ni][3] += dh * (__half2float(Xhi[i1 * XP + col + 1]) + __half2float(Xlo[i1 * XP + col + 1]));
        }
    }
    __syncthreads();   // all reads of M/x complete before overwrite

    // rebuild: A = C~, X = prev
    for (int q = tid; q < 4096; q += 256) {
        int i = q >> 5, n4 = (q & 31) * 4;
        float4 v = *(const float4*)&g_xbc[(size_t)(base + i) * CONVDIM + DINNER + DSTATE + n4];
        float e = expf(acs_s[i]);
        v.x *= e; v.y *= e; v.z *= e; v.w *= e;
        split4(v, Ahi, Alo, i * BP + n4);
    }
    for (int q = tid; q < 2048; q += 256) {
        int n = q >> 4, p4 = (q & 15) * 4;
        float4 v = *(const float4*)&g_prev[(size_t)blk * 8192 + n * 64 + p4];
        split4(v, Xhi, Xlo, n * XP + p4);
    }
    __syncthreads();

    // pass 2: Y_off
    ssd_pass<0>(bAhi, bAlo, bXhi, bXlo, wm, lane, cacc);

    // epilogue
    {
        int i0 = wm + g;
        float* d0 = &g_y[(size_t)(base + i0) * DINNER + h * 64];
        float* d1 = &g_y[(size_t)(base + i0 + 8) * DINNER + h * 64];
        #pragma unroll
        for (int ni = 0; ni < 8; ni++) {
            int col = ni * 8 + 2 * t4;
            float2 v0; v0.x = cacc[ni][0]; v0.y = cacc[ni][1];
            float2 v1; v1.x = cacc[ni][2]; v1.y = cacc[ni][3];
            *(float2*)&d0[col] = v0;
            *(float2*)&d1[col] = v1;
        }
    }
}

// ---------------- gate with silu(z) + RMSNorm * norm_w -> fp16x2 A operand ----------------
__global__ void k_gate(const float* __restrict__ norm_w, __half* __restrict__ out2) {
    __shared__ float red[64];
    int t = blockIdx.x, tid = threadIdx.x;
    float v[4]; float ss = 0.f, dummy = 0.f;
    #pragma unroll
    for (int k = 0; k < 4; k++) {
        int d = tid + k * 256;
        float yv = g_y[(size_t)t * DINNER + d];
        float zv = g_zx[(size_t)t * DINPROJ + d];
        float sv = yv * (zv / (1.f + expf(-zv)));
        v[k] = sv; ss += sv * sv;
    }
    blockReduce2(ss, dummy, red);
    float sc = rsqrtf(ss * (1.f / 1024.f) + EPSF);
    __half* row = out2 + (size_t)t * 2 * DINNER;
    #pragma unroll
    for (int k = 0; k < 4; k++) {
        int d = tid + k * 256;
        f16x2_store_scalar(row, DINNER, d, v[k] * sc * norm_w[d]);
    }
}

// ---------------- out = LayerNorm(a + b) * w + beta (D=512), optional fp16x2 copy ----------------
__global__ void k_addln(const float* __restrict__ a, const float* __restrict__ bsrc,
                        const float* __restrict__ w, const float* __restrict__ beta,
                        float* __restrict__ o, __half* __restrict__ out2) {
    __shared__ float red[64];
    int t = blockIdx.x, tid = threadIdx.x;
    float v[4]; float s = 0.f, ssq = 0.f;
    #pragma unroll
    for (int k = 0; k < 4; k++) {
        int d = tid + k * 128;
        float x = a[(size_t)t * DMODEL + d] + bsrc[(size_t)t * DMODEL + d];
        v[k] = x; s += x; ssq += x * x;
    }
    blockReduce2(s, ssq, red);
    float mean = s * (1.f / 512.f);
    float var = ssq * (1.f / 512.f) - mean * mean;
    float inv = rsqrtf(var + EPSF);
    #pragma unroll
    for (int k = 0; k < 4; k++) {
        int d = tid + k * 128;
        float r = (v[k] - mean) * inv * w[d] + beta[d];
        o[(size_t)t * DMODEL + d] = r;
        if (out2) f16x2_store_scalar(out2 + (size_t)t * 2 * DMODEL, DMODEL, d, r);
    }
}

// ---------------- launch ----------------
static inline void splitA(const float* src, __half* dst, int M, int K) {
    k_split2<0><<<(int)(((size_t)M * K / 4) / 256), 256>>>(src, dst, K);
}
static inline void splitW(const float* src, __half* dst, int M, int K) {
    k_split2<1><<<(int)(((size_t)M * K / 4) / 256), 256>>>(src, dst, K);
}

extern "C" void kernel_launch(void* const* d_in, const int* in_sizes, int n_in,
                              void* d_out, int out_size) {
    const float* tgt        = (const float*)d_in[0];
    const float* in_proj_w  = (const float*)d_in[5];
    const float* conv_w     = (const float*)d_in[6];
    const float* conv_b     = (const float*)d_in[7];
    const float* dt_bias    = (const float*)d_in[8];
    const float* A_log      = (const float*)d_in[9];
    const float* D_head     = (const float*)d_in[10];
    const float* norm_w     = (const float*)d_in[11];
    const float* out_proj_w = (const float*)d_in[12];
    const float* n1w = (const float*)d_in[13];
    const float* n1b = (const float*)d_in[14];
    const float* w1  = (const float*)d_in[15];
    const float* b1  = (const float*)d_in[16];
    const float* w2  = (const float*)d_in[17];
    const float* b2  = (const float*)d_in[18];
    const float* n3w = (const float*)d_in[19];
    const float* n3b = (const float*)d_in[20];
    float* out = (float*)d_out;

    float *zx, *mo, *tb, *f2;
    __half *A2, *A2b, *W2;
    cudaGetSymbolAddress((void**)&zx,   g_zx);
    cudaGetSymbolAddress((void**)&mo,   g_mo);
    cudaGetSymbolAddress((void**)&tb,   g_t);
    cudaGetSymbolAddress((void**)&f2,   g_f2);
    cudaGetSymbolAddress((void**)&A2,   g_A2);
    cudaGetSymbolAddress((void**)&A2b,  g_A2b);
    cudaGetSymbolAddress((void**)&W2,   g_W2);

    const int smem_st = 2 * 128 * BP * 2 + 2 * 128 * XP * 2 + 512;    // 107008
    const int smem_y  = 2 * 128 * BP * 2 + 2 * 128 * XP * 2 + 1024;   // 107520
    const int smem_g  = 4 * 128 * GP * 2;                             // 139264
    cudaFuncSetAttribute(k_states, cudaFuncAttributeMaxDynamicSharedMemorySize, smem_st);
    cudaFuncSetAttribute(k_y,      cudaFuncAttributeMaxDynamicSharedMemorySize, smem_y);
    cudaFuncSetAttribute(k_G,      cudaFuncAttributeMaxDynamicSharedMemorySize, smem_g);

    // 1. in_proj: zx = tgt @ in_proj_w^T
    splitA(tgt, A2, TOK, DMODEL);
    splitW(in_proj_w, W2, DINPROJ, DMODEL);
    k_gemm_f16<0, 0><<<dim3((DINPROJ + 127) / 128, TOK / 128), 256>>>(A2, W2, nullptr, zx, DINPROJ, 2 * DMODEL);
    // 2. conv + silu
    k_conv<<<(TOK / 4 * CONVDIM) / 256, 256>>>(conv_w, conv_b);
    // 3. dt softplus + cumsum
    k_dtscan<<<NBLK, 128>>>(dt_bias, A_log);
    // 4. shared score matrices G = C @ B^T
    k_G<<<NGC, 256, smem_g>>>();
    // 5. chunk end-states (tensor core)
    k_states<<<NBLK, 256, smem_st>>>();
    // 6. chunk scan -> prev
    k_scan<<<BATCH * NHEADS * 8, 256>>>();
    // 7. fused SSD output (tensor core)
    k_y<<<NBLK, 256, smem_y>>>(D_head);
    // 8. gate + rmsnorm -> fp16x2 directly
    k_gate<<<TOK, 256>>>(norm_w, A2);
    // 9. out_proj: mo = gate @ out_proj_w^T
    splitW(out_proj_w, W2, DMODEL, DINNER);
    k_gemm_f16<0, 0><<<dim3(DMODEL / 128, TOK / 128), 256>>>(A2, W2, nullptr, mo, DMODEL, 2 * DINNER);
    // 10. t = LN(tgt + mo), also emit fp16x2 for FFN GEMM
    k_addln<<<TOK, 128>>>(tgt, mo, n1w, n1b, tb, A2);
    // 11. f1 = gelu(t @ w1^T + b1) -> fp16x2 directly
    splitW(w1, W2, FF, DMODEL);
    k_gemm_f16<1, 1><<<dim3(FF / 128, TOK / 128), 256>>>(A2, W2, b1, A2b, FF, 2 * DMODEL);
    // 12. f2 = f1 @ w2^T + b2
    splitW(w2, W2, DMODEL, FF);
    k_gemm_f16<0, 0><<<dim3(DMODEL / 128, TOK / 128), 256>>>(A2b, W2, b2, f2, DMODEL, 2 * FF);
    // 13. out = LN(t + f2)
    k_addln<<<TOK, 128>>>(tb, f2, n3w, n3b, out, nullptr);
}

// round 15
// speedup vs baseline: 3.3114x; 1.0207x over previous
#include <cuda_runtime.h>
#include <cuda_bf16.h>
#include <cuda_fp16.h>
#include <math.h>
#include <cstdint>

// ---------------- problem constants ----------------
#define BATCH 8
#define SEQ 2048
#define TOK (BATCH*SEQ)          // 16384
#define DMODEL 512
#define DINNER 1024
#define DSTATE 128
#define NHEADS 16
#define HEADDIM 64
#define CONVDIM 1280
#define DINPROJ 2320
#define FF 2048
#define CHUNK 128
#define NCHUNK (SEQ/CHUNK)       // 16
#define NBLK (BATCH*NCHUNK*NHEADS) // 2048
#define NGC (BATCH*NCHUNK)       // 128
#define EPSF 1e-5f

#define MMA_F16(cc, aa, b0, b1) \
    asm volatile("mma.sync.aligned.m16n8k16.row.col.f32.f16.f16.f32 " \
        "{%0,%1,%2,%3},{%4,%5,%6,%7},{%8,%9},{%0,%1,%2,%3};" \
        : "+f"(cc[0]), "+f"(cc[1]), "+f"(cc[2]), "+f"(cc[3]) \
        : "r"(aa[0]), "r"(aa[1]), "r"(aa[2]), "r"(aa[3]), "r"(b0), "r"(b1))

#define MMA_BF16(cc, aa, b0, b1) \
    asm volatile("mma.sync.aligned.m16n8k16.row.col.f32.bf16.bf16.f32 " \
        "{%0,%1,%2,%3},{%4,%5,%6,%7},{%8,%9},{%0,%1,%2,%3};" \
        : "+f"(cc[0]), "+f"(cc[1]), "+f"(cc[2]), "+f"(cc[3]) \
        : "r"(aa[0]), "r"(aa[1]), "r"(aa[2]), "r"(aa[3]), "r"(b0), "r"(b1))

#define LDSM_X4(r, addr) \
    asm volatile("ldmatrix.sync.aligned.m8n8.x4.shared.b16 {%0,%1,%2,%3},[%4];" \
        : "=r"((r)[0]), "=r"((r)[1]), "=r"((r)[2]), "=r"((r)[3]) : "r"(addr))

#define LDSM_X4T(r, addr) \
    asm volatile("ldmatrix.sync.aligned.m8n8.x4.trans.shared.b16 {%0,%1,%2,%3},[%4];" \
        : "=r"((r)[0]), "=r"((r)[1]), "=r"((r)[2]), "=r"((r)[3]) : "r"(addr))

#define CP_ASYNC16(dst, src) \
    asm volatile("cp.async.cg.shared.global [%0], [%1], 16;" :: "r"(dst), "l"(src))
#define CP_COMMIT() asm volatile("cp.async.commit_group;" ::: "memory")
#define CP_WAIT2()  asm volatile("cp.async.wait_group 2;" ::: "memory")
#define CP_WAIT0()  asm volatile("cp.async.wait_group 0;" ::: "memory")

// ---------------- scratch ----------------
__device__ __align__(16) float g_zx[TOK*DINPROJ];
__device__ __align__(16) float g_xbc[TOK*CONVDIM];
__device__ __align__(16) float g_dt[NBLK*CHUNK];
__device__ __align__(16) float g_acs[NBLK*CHUNK];
__device__ __align__(16) float g_states[(size_t)NBLK*DSTATE*HEADDIM];
__device__ __align__(16) float g_prev[(size_t)NBLK*DSTATE*HEADDIM];
__device__ __align__(16) float g_y[(size_t)TOK*DINNER];
__device__ __align__(16) float g_mo[(size_t)TOK*DMODEL];
__device__ __align__(16) float g_t[(size_t)TOK*DMODEL];
__device__ __align__(16) float g_f2[(size_t)TOK*DMODEL];
__device__ __align__(16) float g_G[(size_t)NGC*CHUNK*CHUNK];
// fp16 operands: A side [hi|lo] pitch 2K, W side [hi] pitch K
__device__ __align__(16) __half g_A2[(size_t)TOK*2*DINNER];
__device__ __align__(16) __half g_A2b[(size_t)TOK*2*FF];
__device__ __align__(16) __half g_W2[DINPROJ*DMODEL];

// ---------------- helpers ----------------
__device__ __forceinline__ void blockReduce2(float& a, float& b, float* sh) {
    int lane = threadIdx.x & 31, w = threadIdx.x >> 5;
    #pragma unroll
    for (int o = 16; o; o >>= 1) {
        a += __shfl_xor_sync(0xffffffffu, a, o);
        b += __shfl_xor_sync(0xffffffffu, b, o);
    }
    if (lane == 0) { sh[w] = a; sh[32 + w] = b; }
    __syncthreads();
    int nw = blockDim.x >> 5;
    if (w == 0) {
        a = (lane < nw) ? sh[lane] : 0.f;
        b = (lane < nw) ? sh[32 + lane] : 0.f;
        #pragma unroll
        for (int o = 16; o; o >>= 1) {
            a += __shfl_xor_sync(0xffffffffu, a, o);
            b += __shfl_xor_sync(0xffffffffu, b, o);
        }
        if (lane == 0) { sh[0] = a; sh[32] = b; }
    }
    __syncthreads();
    a = sh[0]; b = sh[32];
}

__device__ __forceinline__ void f16x2_store_scalar(__half* row, int K, int d, float s) {
    __half hi = __float2half_rn(s);
    __half lo = __float2half_rn(s - __half2float(hi));
    row[d] = hi; row[K + d] = lo;
}

__device__ __forceinline__ void split4(float4 v, __half* hi, __half* lo, int o) {
    __half2 h0, h1, l0, l1;
    h0.x = __float2half_rn(v.x); h0.y = __float2half_rn(v.y);
    h1.x = __float2half_rn(v.z); h1.y = __float2half_rn(v.w);
    l0.x = __float2half_rn(v.x - __half2float(h0.x));
    l0.y = __float2half_rn(v.y - __half2float(h0.y));
    l1.x = __float2half_rn(v.z - __half2float(h1.x));
    l1.y = __float2half_rn(v.w - __half2float(h1.y));
    *(__half2*)&hi[o] = h0; *(__half2*)&hi[o + 2] = h1;
    *(__half2*)&lo[o] = l0; *(__half2*)&lo[o + 2] = l1;
}

__device__ __forceinline__ void hi4(float4 v, __half* hi, int o) {
    __half2 h0, h1;
    h0.x = __float2half_rn(v.x); h0.y = __float2half_rn(v.y);
    h1.x = __float2half_rn(v.z); h1.y = __float2half_rn(v.w);
    *(__half2*)&hi[o] = h0; *(__half2*)&hi[o + 2] = h1;
}

// ---------------- A-split: src[M,K] fp32 -> dst[M,2K] f16 (hi | lo) ----------------
__global__ void k_splitA(const float* __restrict__ src, __half* __restrict__ dst, int K) {
    size_t i = (size_t)blockIdx.x * 256 + threadIdx.x;
    int K4 = K >> 2;
    size_t row = i / K4;
    int c4 = (int)(i % K4);
    float4 v = ((const float4*)src)[i];
    __half2 h0, h1, l0, l1;
    h0.x = __float2half_rn(v.x); h0.y = __float2half_rn(v.y);
    h1.x = __float2half_rn(v.z); h1.y = __float2half_rn(v.w);
    l0.x = __float2half_rn(v.x - __half2float(h0.x));
    l0.y = __float2half_rn(v.y - __half2float(h0.y));
    l1.x = __float2half_rn(v.z - __half2float(h1.x));
    l1.y = __float2half_rn(v.w - __half2float(h1.y));
    __half2* d = (__half2*)(dst + row * 2 * K);
    int c2 = c4 * 2;
    int K2 = K >> 1;
    d[c2] = h0; d[c2 + 1] = h1;
    d[K2 + c2] = l0; d[K2 + c2 + 1] = l1;
}

// ---------------- W-split: src fp32 -> dst f16 hi only (flat) ----------------
__global__ void k_splitW(const float* __restrict__ src, __half* __restrict__ dst) {
    size_t i = (size_t)blockIdx.x * 256 + threadIdx.x;
    float4 v = ((const float4*)src)[i];
    __half2 h0, h1;
    h0.x = __float2half_rn(v.x); h0.y = __float2half_rn(v.y);
    h1.x = __float2half_rn(v.z); h1.y = __float2half_rn(v.w);
    __half2* d = (__half2*)dst;
    d[2 * i] = h0; d[2 * i + 1] = h1;
}

// ---------------- fp16 tensor-core GEMM, 4-stage cp.async ----------------
// A = [hi|lo] pitch 2K; W = [hi] pitch K (second K half of A reuses same W tiles).
#define SPITCH 40
#define NSTG 4
template<int ACT, int OUT2>
__global__ void __launch_bounds__(256) k_gemm_f16(const __half* __restrict__ A,
                                                  const __half* __restrict__ W,
                                                  const float* __restrict__ bias,
                                                  void* __restrict__ Cout,
                                                  int N, int K) {
    __shared__ __align__(16) __half As[NSTG][128][SPITCH];
    __shared__ __align__(16) __half Ws[NSTG][128][SPITCH];
    int tid = threadIdx.x;
    int bm = blockIdx.y * 128, bn = blockIdx.x * 128;
    int lr = tid >> 1, lc = (tid & 1) * 16;
    int lane = tid & 31, wid = tid >> 5;
    int wm = (wid & 3) * 32, wn = (wid >> 2) * 64;
    int g = lane >> 2, t4 = lane & 3;
    int K2 = 2 * K;

    float c[2][8][4];
    #pragma unroll
    for (int mi = 0; mi < 2; mi++)
        #pragma unroll
        for (int ni = 0; ni < 8; ni++)
            #pragma unroll
            for (int q = 0; q < 4; q++) c[mi][ni][q] = 0.f;

    const __half* Aptr = A + (size_t)(bm + lr) * K2 + lc;
    int wr = bn + lr; if (wr >= N) wr = N - 1;
    const __half* Wrow = W + (size_t)wr * K + lc;

    uint32_t sbA = (uint32_t)__cvta_generic_to_shared(&As[0][0][0]);
    uint32_t sbW = (uint32_t)__cvta_generic_to_shared(&Ws[0][0][0]);
    const uint32_t bufStride = 128 * SPITCH * 2;
    uint32_t dOff = (uint32_t)((lr * SPITCH + lc) * 2);

    int l7 = lane & 7;
    int aRow = wm + ((lane >> 3) & 1) * 8 + l7;
    int aCol = (lane >> 4) * 8;
    int bRow = wn + (lane >> 4) * 8 + l7;
    int bCol = ((lane >> 3) & 1) * 8;

    int KT = K2 / 32;

    #pragma unroll
    for (int s = 0; s < NSTG - 1; s++) {
        if (s < KT) {
            int ao = s * 32;
            int wo = (ao >= K) ? ao - K : ao;
            const __half* ap = Aptr + ao;
            const __half* wp = Wrow + wo;
            uint32_t da = sbA + s * bufStride + dOff;
            uint32_t dw = sbW + s * bufStride + dOff;
            CP_ASYNC16(da, ap); CP_ASYNC16(da + 16, ap + 8);
            CP_ASYNC16(dw, wp); CP_ASYNC16(dw + 16, wp + 8);
        }
        CP_COMMIT();
    }

    for (int kt = 0; kt < KT; kt++) {
        CP_WAIT2();
        __syncthreads();

        int cur = kt & (NSTG - 1);
        uint32_t aBase = sbA + cur * bufStride;
        uint32_t wBase = sbW + cur * bufStride;
        #pragma unroll
        for (int kk = 0; kk < 32; kk += 16) {
            uint32_t af[2][4], bf[4][4];
            #pragma unroll
            for (int mi = 0; mi < 2; mi++) {
                uint32_t addr = aBase + (uint32_t)(((aRow + mi * 16) * SPITCH + aCol + kk) * 2);
                LDSM_X4(af[mi], addr);
            }
            #pragma unroll
            for (int q = 0; q < 4; q++) {
                uint32_t addr = wBase + (uint32_t)(((bRow + q * 16) * SPITCH + bCol + kk) * 2);
                LDSM_X4(bf[q], addr);
            }
            #pragma unroll
            for (int q = 0; q < 4; q++) {
                MMA_F16(c[0][2 * q],     af[0], bf[q][0], bf[q][1]);
                MMA_F16(c[1][2 * q],     af[1], bf[q][0], bf[q][1]);
                MMA_F16(c[0][2 * q + 1], af[0], bf[q][2], bf[q][3]);
                MMA_F16(c[1][2 * q + 1], af[1], bf[q][2], bf[q][3]);
            }
        }
        {
            int s = kt + NSTG - 1;
            if (s < KT) {
                int ao = s * 32;
                int wo = (ao >= K) ? ao - K : ao;
                const __half* ap = Aptr + ao;
                const __half* wp = Wrow + wo;
                uint32_t da = sbA + (s & (NSTG - 1)) * bufStride + dOff;
                uint32_t dw = sbW + (s & (NSTG - 1)) * bufStride + dOff;
                CP_ASYNC16(da, ap); CP_ASYNC16(da + 16, ap + 8);
                CP_ASYNC16(dw, wp); CP_ASYNC16(dw + 16, wp + 8);
            }
            CP_COMMIT();
        }
    }
    CP_WAIT0();

    #pragma unroll
    for (int mi = 0; mi < 2; mi++) {
        int r0 = bm + wm + mi * 16 + g;
        #pragma unroll
        for (int ni = 0; ni < 8; ni++) {
            int col = bn + wn + ni * 8 + 2 * t4;
            #pragma unroll
            for (int half = 0; half < 2; half++) {
                int r = r0 + half * 8;
                float v0 = c[mi][ni][half * 2 + 0];
                float v1 = c[mi][ni][half * 2 + 1];
                if (bias) { v0 += bias[col]; v1 += bias[col + 1]; }
                if (ACT == 1) {
                    v0 = 0.5f * v0 * (1.f + erff(v0 * 0.70710678118654752f));
                    v1 = 0.5f * v1 * (1.f + erff(v1 * 0.70710678118654752f));
                }
                if (OUT2) {
                    __half* O = (__half*)Cout;
                    __half2 hi, lo;
                    hi.x = __float2half_rn(v0); hi.y = __float2half_rn(v1);
                    lo.x = __float2half_rn(v0 - __half2float(hi.x));
                    lo.y = __float2half_rn(v1 - __half2float(hi.y));
                    size_t base = (size_t)r * 2 * N + col;
                    *(__half2*)&O[base]     = hi;
                    *(__half2*)&O[base + N] = lo;
                } else {
                    float* Cf = (float*)Cout;
                    if (col + 1 < N) {
                        float2 v; v.x = v0; v.y = v1;
                        *(float2*)&Cf[(size_t)r * N + col] = v;
                    } else if (col < N) {
                        Cf[(size_t)r * N + col] = v0;
                    }
                }
            }
        }
    }
}

// ---------------- k_G: per (b,c) score matrix G = C @ B^T via MMA (bf16 hi/lo 3-term) ----------------
#define GP 136
__global__ void __launch_bounds__(256) k_G() {
    extern __shared__ __align__(16) char sg[];
    __nv_bfloat16* Chi = (__nv_bfloat16*)sg;
    __nv_bfloat16* Clo = Chi + 128 * GP;
    __nv_bfloat16* Bhi = Clo + 128 * GP;
    __nv_bfloat16* Blo = Bhi + 128 * GP;
    int tid = threadIdx.x, lane = tid & 31, wid = tid >> 5;
    int blk = blockIdx.x;
    int base = blk * 128;
    int wm = (wid & 3) * 32, wn = (wid >> 2) * 64;
    int g = lane >> 2, t4 = lane & 3;

    for (int q = tid; q < 4096; q += 256) {
        int row = q >> 5, c4 = (q & 31) * 4;
        const float* rp = &g_xbc[(size_t)(base + row) * CONVDIM + DINNER];
        float4 vB = *(const float4*)(rp + c4);
        float4 vC = *(const float4*)(rp + DSTATE + c4);
        __nv_bfloat162 h, l;
        int o = row * GP + c4;
        h.x = __float2bfloat16_rn(vC.x); h.y = __float2bfloat16_rn(vC.y);
        l.x = __float2bfloat16_rn(vC.x - __bfloat162float(h.x));
        l.y = __float2bfloat16_rn(vC.y - __bfloat162float(h.y));
        *(__nv_bfloat162*)&Chi[o] = h; *(__nv_bfloat162*)&Clo[o] = l;
        h.x = __float2bfloat16_rn(vC.z); h.y = __float2bfloat16_rn(vC.w);
        l.x = __float2bfloat16_rn(vC.z - __bfloat162float(h.x));
        l.y = __float2bfloat16_rn(vC.w - __bfloat162float(h.y));
        *(__nv_bfloat162*)&Chi[o + 2] = h; *(__nv_bfloat162*)&Clo[o + 2] = l;
        h.x = __float2bfloat16_rn(vB.x); h.y = __float2bfloat16_rn(vB.y);
        l.x = __float2bfloat16_rn(vB.x - __bfloat162float(h.x));
        l.y = __float2bfloat16_rn(vB.y - __bfloat162float(h.y));
        *(__nv_bfloat162*)&Bhi[o] = h; *(__nv_bfloat162*)&Blo[o] = l;
        h.x = __float2bfloat16_rn(vB.z); h.y = __float2bfloat16_rn(vB.w);
        l.x = __float2bfloat16_rn(vB.z - __bfloat162float(h.x));
        l.y = __float2bfloat16_rn(vB.w - __bfloat162float(h.y));
        *(__nv_bfloat162*)&Bhi[o + 2] = h; *(__nv_bfloat162*)&Blo[o + 2] = l;
    }
    __syncthreads();

    uint32_t bChi = (uint32_t)__cvta_generic_to_shared(Chi);
    uint32_t bClo = (uint32_t)__cvta_generic_to_shared(Clo);
    uint32_t bBhi = (uint32_t)__cvta_generic_to_shared(Bhi);
    uint32_t bBlo = (uint32_t)__cvta_generic_to_shared(Blo);

    int l7 = lane & 7;
    int aRow = wm + ((lane >> 3) & 1) * 8 + l7;
    int aCol = (lane >> 4) * 8;
    int bRow = wn + (lane >> 4) * 8 + l7;
    int bCol = ((lane >> 3) & 1) * 8;

    float c[2][8][4];
    #pragma unroll
    for (int mi = 0; mi < 2; mi++)
        #pragma unroll
        for (int ni = 0; ni < 8; ni++)
            #pragma unroll
            for (int q = 0; q < 4; q++) c[mi][ni][q] = 0.f;

    #pragma unroll
    for (int term = 0; term < 3; term++) {
        uint32_t aB = (term == 2) ? bClo : bChi;
        uint32_t bB = (term == 1) ? bBlo : bBhi;
        #pragma unroll
        for (int kk = 0; kk < 128; kk += 16) {
            uint32_t af[2][4], bf[4][4];
            #pragma unroll
            for (int mi = 0; mi < 2; mi++) {
                uint32_t addr = aB + (uint32_t)(((aRow + mi * 16) * GP + aCol + kk) * 2);
                LDSM_X4(af[mi], addr);
            }
            #pragma unroll
            for (int q = 0; q < 4; q++) {
                uint32_t addr = bB + (uint32_t)(((bRow + q * 16) * GP + bCol + kk) * 2);
                LDSM_X4(bf[q], addr);
            }
            #pragma unroll
            for (int q = 0; q < 4; q++) {
                MMA_BF16(c[0][2 * q],     af[0], bf[q][0], bf[q][1]);
                MMA_BF16(c[1][2 * q],     af[1], bf[q][0], bf[q][1]);
                MMA_BF16(c[0][2 * q + 1], af[0], bf[q][2], bf[q][3]);
                MMA_BF16(c[1][2 * q + 1], af[1], bf[q][2], bf[q][3]);
            }
        }
    }

    float* Gout = &g_G[(size_t)blk * 16384];
    #pragma unroll
    for (int mi = 0; mi < 2; mi++) {
        int r0 = wm + mi * 16 + g;
        #pragma unroll
        for (int ni = 0; ni < 8; ni++) {
            int col = wn + ni * 8 + 2 * t4;
            #pragma unroll
            for (int half = 0; half < 2; half++) {
                int r = r0 + half * 8;
                float2 v; v.x = c[mi][ni][half * 2]; v.y = c[mi][ni][half * 2 + 1];
                *(float2*)&Gout[r * 128 + col] = v;
            }
        }
    }
}

// ---------------- shared MMA pass for SSD kernels (2-term: hiA,loA vs hiX) ----------------
#define BP 136
#define XP 72
template<int TRANSA>
__device__ __forceinline__ void ssd_pass(uint32_t aHi, uint32_t aLo, uint32_t xHi,
                                         int wm, int lane, float cacc[8][4]) {
    int l7 = lane & 7;
    int aRow = wm + ((lane >> 3) & 1) * 8 + l7;
    int aCol = (lane >> 4) * 8;
    int tL = (lane >> 4) * 8 + l7;
    int tN = ((lane >> 3) & 1) * 8;
    int bL = ((lane >> 3) & 1) * 8 + l7;
    int bP = (lane >> 4) * 8;
    #pragma unroll
    for (int term = 0; term < 2; term++) {
        uint32_t aB = (term == 1) ? aLo : aHi;
        #pragma unroll
        for (int k0 = 0; k0 < 128; k0 += 16) {
            uint32_t af[4];
            if (TRANSA) {
                LDSM_X4T(af, aB + (uint32_t)(((k0 + tL) * BP + wm + tN) * 2));
            } else {
                LDSM_X4(af, aB + (uint32_t)((aRow * BP + k0 + aCol) * 2));
            }
            #pragma unroll
            for (int q = 0; q < 4; q++) {
                uint32_t bf[4];
                LDSM_X4T(bf, xHi + (uint32_t)(((k0 + bL) * XP + q * 16 + bP) * 2));
                MMA_F16(cacc[2 * q],     af, bf[0], bf[1]);
                MMA_F16(cacc[2 * q + 1], af, bf[2], bf[3]);
            }
        }
    }
}

// ---------------- causal depthwise conv1d + silu (4 s-positions/thread) ----------------
__global__ void k_conv(const float* __restrict__ conv_w, const float* __restrict__ conv_b) {
    int idx = blockIdx.x * 256 + threadIdx.x;
    int ch = idx % CONVDIM;
    int r  = idx / CONVDIM;
    int s4 = r % (SEQ / 4);
    int b  = r / (SEQ / 4);
    int s0 = s4 * 4;
    float w0 = conv_w[ch * 4], w1 = conv_w[ch * 4 + 1], w2 = conv_w[ch * 4 + 2], w3 = conv_w[ch * 4 + 3];
    float bias = conv_b[ch];
    float in[7];
    #pragma unroll
    for (int k = 0; k < 7; k++) {
        int sp = s0 + k - 3;
        in[k] = (sp >= 0) ? g_zx[(size_t)(b * SEQ + sp) * DINPROJ + DINNER + ch] : 0.f;
    }
    #pragma unroll
    for (int s = 0; s < 4; s++) {
        float acc = bias + in[s] * w0 + in[s + 1] * w1 + in[s + 2] * w2 + in[s + 3] * w3;
        acc = acc / (1.f + expf(-acc));
        g_xbc[(size_t)(b * SEQ + s0 + s) * CONVDIM + ch] = acc;
    }
}

// ---------------- dt softplus + per-chunk cumulative log-decay ----------------
__global__ void k_dtscan(const float* __restrict__ dt_bias, const float* __restrict__ A_log) {
    __shared__ float s[128];
    int blk = blockIdx.x, l = threadIdx.x;
    int h = blk & 15, c = (blk >> 4) & 15, b = blk >> 8;
    int tok = b * SEQ + c * CHUNK + l;
    float raw = g_zx[(size_t)tok * DINPROJ + 2304 + h] + dt_bias[h];
    float dtv = (raw > 20.f) ? raw : log1pf(expf(raw));
    float A = -expf(A_log[h]);
    g_dt[blk * 128 + l] = dtv;
    s[l] = dtv * A;
    __syncthreads();
    #pragma unroll
    for (int off = 1; off < 128; off <<= 1) {
        float t = (l >= off) ? s[l - off] : 0.f;
        __syncthreads();
        s[l] += t;
        __syncthreads();
    }
    g_acs[blk * 128 + l] = s[l];
}

// ---------------- per-chunk end states via tensor cores (2-term) ----------------
__global__ void __launch_bounds__(256) k_states() {
    extern __shared__ __align__(16) char sraw[];
    __half* Ahi = (__half*)sraw;            // Bw [l][n] 128*BP
    __half* Alo = Ahi + 128 * BP;
    __half* Xhi = Alo + 128 * BP;           // x [l][p] 128*XP
    float*  ws  = (float*)(Xhi + 128 * XP);
    int tid = threadIdx.x, lane = tid & 31, wid = tid >> 5;
    int blk = blockIdx.x;
    int h = blk & 15, cc = (blk >> 4) & 15, b = blk >> 8;
    int base = b * SEQ + cc * CHUNK;

    if (tid < 128) {
        float acsL = g_acs[blk * 128 + 127];
        ws[tid] = expf(acsL - g_acs[blk * 128 + tid]) * g_dt[blk * 128 + tid];
    }
    __syncthreads();
    for (int q = tid; q < 4096; q += 256) {
        int l = q >> 5, n4 = (q & 31) * 4;
        float4 v = *(const float4*)&g_xbc[(size_t)(base + l) * CONVDIM + DINNER + n4];
        float w = ws[l];
        v.x *= w; v.y *= w; v.z *= w; v.w *= w;
        split4(v, Ahi, Alo, l * BP + n4);
    }
    for (int q = tid; q < 2048; q += 256) {
        int l = q >> 4, p4 = (q & 15) * 4;
        float4 v = *(const float4*)&g_xbc[(size_t)(base + l) * CONVDIM + h * 64 + p4];
        hi4(v, Xhi, l * XP + p4);
    }
    __syncthreads();

    uint32_t bAhi = (uint32_t)__cvta_generic_to_shared(Ahi);
    uint32_t bAlo = (uint32_t)__cvta_generic_to_shared(Alo);
    uint32_t bXhi = (uint32_t)__cvta_generic_to_shared(Xhi);
    int wm = wid * 16;
    float cacc[8][4];
    #pragma unroll
    for (int ni = 0; ni < 8; ni++)
        #pragma unroll
        for (int q = 0; q < 4; q++) cacc[ni][q] = 0.f;

    ssd_pass<1>(bAhi, bAlo, bXhi, wm, lane, cacc);

    int g = lane >> 2, t4 = lane & 3;
    float* d0 = &g_states[(size_t)blk * 8192 + (wm + g) * 64];
    float* d1 = d0 + 8 * 64;
    #pragma unroll
    for (int ni = 0; ni < 8; ni++) {
        int col = ni * 8 + 2 * t4;
        float2 v0; v0.x = cacc[ni][0]; v0.y = cacc[ni][1];
        float2 v1; v1.x = cacc[ni][2]; v1.y = cacc[ni][3];
        *(float2*)&d0[col] = v0;
        *(float2*)&d1[col] = v1;
    }
}

// ---------------- sequential chunk scan ----------------
__global__ void k_scan() {
    int bx = blockIdx.x;
    int e8 = bx & 7;
    int bh = bx >> 3;
    int b = bh >> 4, h = bh & 15;
    int e = e8 * 1024 + threadIdx.x;
    for (int k = 0; k < 4; k++, e += 256) {
        float acc = 0.f;
        #pragma unroll
        for (int c = 0; c < NCHUNK; c++) {
            int blk = ((b * NCHUNK + c) << 4) + h;
            g_prev[(size_t)blk * 8192 + e] = acc;
            float cd = expf(g_acs[blk * 128 + 127]);
            acc = cd * acc + g_states[(size_t)blk * 8192 + e];
        }
    }
}

// ---------------- fused SSD output via tensor cores (2-term passes) ----------------
__global__ void __launch_bounds__(256) k_y(const float* __restrict__ D_head) {
    extern __shared__ __align__(16) char sraw[];
    __half* Ahi = (__half*)sraw;            // M then C~: 128*BP
    __half* Alo = Ahi + 128 * BP;
    __half* Xhi = Alo + 128 * BP;           // x then prev: 128*XP
    float* acs_s = (float*)(Xhi + 128 * XP);
    float* dt_s  = acs_s + 128;
    int tid = threadIdx.x, lane = tid & 31, wid = tid >> 5;
    int blk = blockIdx.x;
    int h = blk & 15, cc = (blk >> 4) & 15, b = blk >> 8;
    int base = b * SEQ + cc * CHUNK;
    size_t gbase = (size_t)(blk >> 4) * 16384;

    if (tid < 128) {
        acs_s[tid] = g_acs[blk * 128 + tid];
        dt_s[tid]  = g_dt[blk * 128 + tid];
    }
    __syncthreads();

    // build M and x
    for (int q = tid; q < 4096; q += 256) {
        int i = q >> 5, j4 = (q & 31) * 4;
        float4 gv = *(const float4*)&g_G[gbase + i * 128 + j4];
        float ai = acs_s[i];
        float4 m;
        m.x = (j4     <= i) ? expf(ai - acs_s[j4])     * dt_s[j4]     * gv.x : 0.f;
        m.y = (j4 + 1 <= i) ? expf(ai - acs_s[j4 + 1]) * dt_s[j4 + 1] * gv.y : 0.f;
        m.z = (j4 + 2 <= i) ? expf(ai - acs_s[j4 + 2]) * dt_s[j4 + 2] * gv.z : 0.f;
        m.w = (j4 + 3 <= i) ? expf(ai - acs_s[j4 + 3]) * dt_s[j4 + 3] * gv.w : 0.f;
        split4(m, Ahi, Alo, i * BP + j4);
    }
    for (int q = tid; q < 2048; q += 256) {
        int l = q >> 4, p4 = (q & 15) * 4;
        float4 v = *(const float4*)&g_xbc[(size_t)(base + l) * CONVDIM + h * 64 + p4];
        hi4(v, Xhi, l * XP + p4);
    }
    __syncthreads();

    uint32_t bAhi = (uint32_t)__cvta_generic_to_shared(Ahi);
    uint32_t bAlo = (uint32_t)__cvta_generic_to_shared(Alo);
    uint32_t bXhi = (uint32_t)__cvta_generic_to_shared(Xhi);
    int wm = wid * 16;
    float cacc[8][4];
    #pragma unroll
    for (int ni = 0; ni < 8; ni++)
        #pragma unroll
        for (int q = 0; q < 4; q++) cacc[ni][q] = 0.f;

    // pass 1: Y_diag
    ssd_pass<0>(bAhi, bAlo, bXhi, wm, lane, cacc);

    // D*x term from resident x hi
    int g = lane >> 2, t4 = lane & 3;
    {
        float dh = D_head[h];
        int i0 = wm + g, i1 = i0 + 8;
        #pragma unroll
        for (int ni = 0; ni < 8; ni++) {
            int col = ni * 8 + 2 * t4;
            cacc[ni][0] += dh * __half2float(Xhi[i0 * XP + col]);
            cacc[ni][1] += dh * __half2float(Xhi[i0 * XP + col + 1]);
            cacc[ni][2] += dh * __half2float(Xhi[i1 * XP + col]);
            cacc[ni][3] += dh * __half2float(Xhi[i1 * XP + col + 1]);
        }
    }
    __syncthreads();

    // rebuild: A = C~, X = prev
    for (int q = tid; q < 4096; q += 256) {
        int i = q >> 5, n4 = (q & 31) * 4;
        float4 v = *(const float4*)&g_xbc[(size_t)(base + i) * CONVDIM + DINNER + DSTATE + n4];
        float e = expf(acs_s[i]);
        v.x *= e; v.y *= e; v.z *= e; v.w *= e;
        split4(v, Ahi, Alo, i * BP + n4);
    }
    for (int q = tid; q < 2048; q += 256) {
        int n = q >> 4, p4 = (q & 15) * 4;
        float4 v = *(const float4*)&g_prev[(size_t)blk * 8192 + n * 64 + p4];
        hi4(v, Xhi, n * XP + p4);
    }
    __syncthreads();

    // pass 2: Y_off
    ssd_pass<0>(bAhi, bAlo, bXhi, wm, lane, cacc);

    // epilogue
    {
        int i0 = wm + g;
        float* d0 = &g_y[(size_t)(base + i0) * DINNER + h * 64];
        float* d1 = &g_y[(size_t)(base + i0 + 8) * DINNER + h * 64];
        #pragma unroll
        for (int ni = 0; ni < 8; ni++) {
            int col = ni * 8 + 2 * t4;
            float2 v0; v0.x = cacc[ni][0]; v0.y = cacc[ni][1];
            float2 v1; v1.x = cacc[ni][2]; v1.y = cacc[ni][3];
            *(float2*)&d0[col] = v0;
            *(float2*)&d1[col] = v1;
        }
    }
}

// ---------------- gate with silu(z) + RMSNorm * norm_w -> fp16 [hi|lo] ----------------
__global__ void k_gate(const float* __restrict__ norm_w, __half* __restrict__ out2) {
    __shared__ float red[64];
    int t = blockIdx.x, tid = threadIdx.x;
    float v[4]; float ss = 0.f, dummy = 0.f;
    #pragma unroll
    for (int k = 0; k < 4; k++) {
        int d = tid + k * 256;
        float yv = g_y[(size_t)t * DINNER + d];
        float zv = g_zx[(size_t)t * DINPROJ + d];
        float sv = yv * (zv / (1.f + expf(-zv)));
        v[k] = sv; ss += sv * sv;
    }
    blockReduce2(ss, dummy, red);
    float sc = rsqrtf(ss * (1.f / 1024.f) + EPSF);
    __half* row = out2 + (size_t)t * 2 * DINNER;
    #pragma unroll
    for (int k = 0; k < 4; k++) {
        int d = tid + k * 256;
        f16x2_store_scalar(row, DINNER, d, v[k] * sc * norm_w[d]);
    }
}

// ---------------- out = LayerNorm(a + b) * w + beta (D=512), optional fp16 [hi|lo] copy ----------------
__global__ void k_addln(const float* __restrict__ a, const float* __restrict__ bsrc,
                        const float* __restrict__ w, const float* __restrict__ beta,
                        float* __restrict__ o, __half* __restrict__ out2) {
    __shared__ float red[64];
    int t = blockIdx.x, tid = threadIdx.x;
    float v[4]; float s = 0.f, ssq = 0.f;
    #pragma unroll
    for (int k = 0; k < 4; k++) {
        int d = tid + k * 128;
        float x = a[(size_t)t * DMODEL + d] + bsrc[(size_t)t * DMODEL + d];
        v[k] = x; s += x; ssq += x * x;
    }
    blockReduce2(s, ssq, red);
    float mean = s * (1.f / 512.f);
    float var = ssq * (1.f / 512.f) - mean * mean;
    float inv = rsqrtf(var + EPSF);
    #pragma unroll
    for (int k = 0; k < 4; k++) {
        int d = tid + k * 128;
        float r = (v[k] - mean) * inv * w[d] + beta[d];
        o[(size_t)t * DMODEL + d] = r;
        if (out2) f16x2_store_scalar(out2 + (size_t)t * 2 * DMODEL, DMODEL, d, r);
    }
}

// ---------------- launch ----------------
extern "C" void kernel_launch(void* const* d_in, const int* in_sizes, int n_in,
                              void* d_out, int out_size) {
    const float* tgt        = (const float*)d_in[0];
    const float* in_proj_w  = (const float*)d_in[5];
    const float* conv_w     = (const float*)d_in[6];
    const float* conv_b     = (const float*)d_in[7];
    const float* dt_bias    = (const float*)d_in[8];
    const float* A_log      = (const float*)d_in[9];
    const float* D_head     = (const float*)d_in[10];
    const float* norm_w     = (const float*)d_in[11];
    const float* out_proj_w = (const float*)d_in[12];
    const float* n1w = (const float*)d_in[13];
    const float* n1b = (const float*)d_in[14];
    const float* w1  = (const float*)d_in[15];
    const float* b1  = (const float*)d_in[16];
    const float* w2  = (const float*)d_in[17];
    const float* b2  = (const float*)d_in[18];
    const float* n3w = (const float*)d_in[19];
    const float* n3b = (const float*)d_in[20];
    float* out = (float*)d_out;

    float *zx, *mo, *tb, *f2;
    __half *A2, *A2b, *W2;
    cudaGetSymbolAddress((void**)&zx,   g_zx);
    cudaGetSymbolAddress((void**)&mo,   g_mo);
    cudaGetSymbolAddress((void**)&tb,   g_t);
    cudaGetSymbolAddress((void**)&f2,   g_f2);
    cudaGetSymbolAddress((void**)&A2,   g_A2);
    cudaGetSymbolAddress((void**)&A2b,  g_A2b);
    cudaGetSymbolAddress((void**)&W2,   g_W2);

    const int smem_st = (2 * 128 * BP + 128 * XP) * 2 + 512;    // 88576
    const int smem_y  = (2 * 128 * BP + 128 * XP) * 2 + 1024;   // 89088
    const int smem_g  = 4 * 128 * GP * 2;                       // 139264
    cudaFuncSetAttribute(k_states, cudaFuncAttributeMaxDynamicSharedMemorySize, smem_st);
    cudaFuncSetAttribute(k_y,      cudaFuncAttributeMaxDynamicSharedMemorySize, smem_y);
    cudaFuncSetAttribute(k_G,      cudaFuncAttributeMaxDynamicSharedMemorySize, smem_g);

    // 1. in_proj: zx = tgt @ in_proj_w^T
    k_splitA<<<(int)(((size_t)TOK * DMODEL / 4) / 256), 256>>>(tgt, A2, DMODEL);
    k_splitW<<<(DINPROJ * DMODEL / 4) / 256, 256>>>(in_proj_w, W2);
    k_gemm_f16<0, 0><<<dim3((DINPROJ + 127) / 128, TOK / 128), 256>>>(A2, W2, nullptr, zx, DINPROJ, DMODEL);
    // 2. conv + silu
    k_conv<<<(TOK / 4 * CONVDIM) / 256, 256>>>(conv_w, conv_b);
    // 3. dt softplus + cumsum
    k_dtscan<<<NBLK, 128>>>(dt_bias, A_log);
    // 4. shared score matrices G = C @ B^T
    k_G<<<NGC, 256, smem_g>>>();
    // 5. chunk end-states (tensor core)
    k_states<<<NBLK, 256, smem_st>>>();
    // 6. chunk scan -> prev
    k_scan<<<BATCH * NHEADS * 8, 256>>>();
    // 7. fused SSD output (tensor core)
    k_y<<<NBLK, 256, smem_y>>>(D_head);
    // 8. gate + rmsnorm -> fp16 [hi|lo]
    k_gate<<<TOK, 256>>>(norm_w, A2);
    // 9. out_proj: mo = gate @ out_proj_w^T
    k_splitW<<<(DMODEL * DINNER / 4) / 256, 256>>>(out_proj_w, W2);
    k_gemm_f16<0, 0><<<dim3(DMODEL / 128, TOK / 128), 256>>>(A2, W2, nullptr, mo, DMODEL, DINNER);
    // 10. t = LN(tgt + mo), also emit fp16 [hi|lo]
    k_addln<<<TOK, 128>>>(tgt, mo, n1w, n1b, tb, A2);
    // 11. f1 = gelu(t @ w1^T + b1) -> fp16 [hi|lo] directly
    k_splitW<<<(FF * DMODEL / 4) / 256, 256>>>(w1, W2);
    k_gemm_f16<1, 1><<<dim3(FF / 128, TOK / 128), 256>>>(A2, W2, b1, A2b, FF, DMODEL);
    // 12. f2 = f1 @ w2^T + b2
    k_splitW<<<(DMODEL * FF / 4) / 256, 256>>>(w2, W2);
    k_gemm_f16<0, 0><<<dim3(DMODEL / 128, TOK / 128), 256>>>(A2b, W2, b2, f2, DMODEL, FF);
    // 13. out = LN(t + f2)
    k_addln<<<TOK, 128>>>(tb, f2, n3w, n3b, out, nullptr);
}